// round 7
// baseline (speedup 1.0000x reference)
#include <cuda_runtime.h>
#include <cuda_bf16.h>
#include <cstdint>
#include <cstddef>

// Problem constants
#define BB  4
#define SS  2048
#define DD  1024
#define HH  16
#define HDD 64
#define MTOK (BB*SS)          // 8192 token rows

// q prescale: HD^-0.5 * log2(e)  (softmax done in exp2 domain)
#define QSC 0.18033688011112042f

// Scratch (device globals; no allocations allowed)
__device__ __align__(128) __nv_bfloat16 g_xh[(size_t)MTOK * DD];
__device__ __align__(128) __nv_bfloat16 g_xl[(size_t)MTOK * DD];
__device__ __align__(128) __nv_bfloat16 g_yh[(size_t)MTOK * DD];
__device__ __align__(128) __nv_bfloat16 g_yl[(size_t)MTOK * DD];
__device__ __align__(128) __nv_bfloat16 g_wt_hi [(size_t)3 * DD * DD];
__device__ __align__(128) __nv_bfloat16 g_wt_lo [(size_t)3 * DD * DD];
__device__ __align__(128) __nv_bfloat16 g_wpt_hi[(size_t)DD * DD];
__device__ __align__(128) __nv_bfloat16 g_wpt_lo[(size_t)DD * DD];
#define BHSZ ((size_t)BB * HH * SS * HDD)
__device__ __align__(128) __nv_bfloat16 g_qh[BHSZ], g_ql[BHSZ];
__device__ __align__(128) __nv_bfloat16 g_kh[BHSZ], g_kl[BHSZ];
__device__ __align__(128) __nv_bfloat16 g_vh[BHSZ], g_vl[BHSZ];

// ---------------------------------------------------------------------------
// Warp-MMA + async-copy helpers
// ---------------------------------------------------------------------------
__device__ __forceinline__ uint32_t smem_u32(const void* p) {
    uint32_t a;
    asm("{ .reg .u64 t; cvta.to.shared.u64 t, %1; cvt.u32.u64 %0, t; }"
        : "=r"(a) : "l"(p));
    return a;
}
__device__ __forceinline__ void ldsm_x4(uint32_t* r, uint32_t addr) {
    asm volatile("ldmatrix.sync.aligned.m8n8.x4.shared.b16 {%0,%1,%2,%3}, [%4];"
                 : "=r"(r[0]), "=r"(r[1]), "=r"(r[2]), "=r"(r[3]) : "r"(addr));
}
__device__ __forceinline__ void ldsm_x4_t(uint32_t* r, uint32_t addr) {
    asm volatile("ldmatrix.sync.aligned.m8n8.x4.trans.shared.b16 {%0,%1,%2,%3}, [%4];"
                 : "=r"(r[0]), "=r"(r[1]), "=r"(r[2]), "=r"(r[3]) : "r"(addr));
}
__device__ __forceinline__ void mma16816(float* d, const uint32_t* a,
                                         const uint32_t b0, const uint32_t b1) {
    asm volatile(
        "mma.sync.aligned.m16n8k16.row.col.f32.bf16.bf16.f32 "
        "{%0,%1,%2,%3}, {%4,%5,%6,%7}, {%8,%9}, {%0,%1,%2,%3};"
        : "+f"(d[0]), "+f"(d[1]), "+f"(d[2]), "+f"(d[3])
        : "r"(a[0]), "r"(a[1]), "r"(a[2]), "r"(a[3]), "r"(b0), "r"(b1));
}
__device__ __forceinline__ void cp_async16(uint32_t saddr, const void* g) {
    asm volatile("cp.async.cg.shared.global [%0], [%1], 16;"
                 :: "r"(saddr), "l"(g) : "memory");
}
#define CP_COMMIT() asm volatile("cp.async.commit_group;" ::: "memory")
#define CP_WAIT(n)  asm volatile("cp.async.wait_group %0;" :: "n"(n) : "memory")

__device__ __forceinline__ uint32_t pack_bf2(__nv_bfloat16 a, __nv_bfloat16 b) {
    __nv_bfloat162 t; t.x = a; t.y = b;
    return *reinterpret_cast<uint32_t*>(&t);
}
__device__ __forceinline__ float ex2f(float x) {
    float r;
    asm("ex2.approx.f32 %0, %1;" : "=f"(r) : "f"(x));
    return r;
}

#define TSTR 72   // GEMM BK=64 tile row stride (elems): 144B rows, conflict-free
#define KSTR 72   // attention tile row stride

// ---------------------------------------------------------------------------
// Elementwise fp32 -> bf16 hi/lo split (for x)
// ---------------------------------------------------------------------------
__global__ __launch_bounds__(256)
void split_kernel(const float* __restrict__ in,
                  __nv_bfloat16* __restrict__ hi,
                  __nv_bfloat16* __restrict__ lo)
{
    size_t i = ((size_t)blockIdx.x * 256 + threadIdx.x) * 4;
    float4 v = *reinterpret_cast<const float4*>(in + i);
    __nv_bfloat16 h0 = __float2bfloat16_rn(v.x);
    __nv_bfloat16 h1 = __float2bfloat16_rn(v.y);
    __nv_bfloat16 h2 = __float2bfloat16_rn(v.z);
    __nv_bfloat16 h3 = __float2bfloat16_rn(v.w);
    uint2 hv, lv;
    hv.x = pack_bf2(h0, h1); hv.y = pack_bf2(h2, h3);
    lv.x = pack_bf2(__float2bfloat16_rn(v.x - __bfloat162float(h0)),
                    __float2bfloat16_rn(v.y - __bfloat162float(h1)));
    lv.y = pack_bf2(__float2bfloat16_rn(v.z - __bfloat162float(h2)),
                    __float2bfloat16_rn(v.w - __bfloat162float(h3)));
    *reinterpret_cast<uint2*>(hi + i) = hv;
    *reinterpret_cast<uint2*>(lo + i) = lv;
}

// ---------------------------------------------------------------------------
// Transpose + bf16 hi/lo split of weights:  W[K,N] fp32 -> Th/Tl[N,K] bf16
// ---------------------------------------------------------------------------
__global__ __launch_bounds__(256)
void transpose_split_kernel(const float* __restrict__ W,
                            __nv_bfloat16* __restrict__ Th,
                            __nv_bfloat16* __restrict__ Tl,
                            int K, int N)
{
    __shared__ float tile[32][33];
    const int n0 = blockIdx.x * 32;
    const int k0 = blockIdx.y * 32;
    const int tx = threadIdx.x & 31;
    const int ty4 = (threadIdx.x >> 5) * 4;

    #pragma unroll
    for (int j = 0; j < 4; j++)
        tile[ty4 + j][tx] = W[(size_t)(k0 + ty4 + j) * N + n0 + tx];
    __syncthreads();
    #pragma unroll
    for (int j = 0; j < 4; j++) {
        float v = tile[tx][ty4 + j];
        __nv_bfloat16 hi = __float2bfloat16_rn(v);
        __nv_bfloat16 lo = __float2bfloat16_rn(v - __bfloat162float(hi));
        size_t o = (size_t)(n0 + ty4 + j) * K + k0 + tx;
        Th[o] = hi;
        Tl[o] = lo;
    }
}

// ---------------------------------------------------------------------------
// cp.async 2-stage tensor-core GEMM (bf16 hi/lo, fp32 accum)
// BM=256, BN=128, BK=64, 512 threads (16 warps, 64x32 warp tiles), 1 CTA/SM.
// Single barrier per 64-K chunk (~1536 tensor-cycles between barriers).
// MODE 0: fp32 C.  MODE 1 (QKV): split bf16 q/k/v per-head buffers.
// ---------------------------------------------------------------------------
#define G_AH 0
#define G_AL (256 * TSTR * 2)            // 36864
#define G_BH (2 * 256 * TSTR * 2)        // 73728
#define G_BL (G_BH + 128 * TSTR * 2)     // 92160
#define G_STG (G_BL + 128 * TSTR * 2)    // 110592
#define GEMM_SMEM (2 * G_STG)            // 221184

template <int MODE>
__global__ __launch_bounds__(512, 1)
void tc_gemm_kernel(const __nv_bfloat16* __restrict__ Agh,
                    const __nv_bfloat16* __restrict__ Agl,
                    const __nv_bfloat16* __restrict__ Bgh,
                    const __nv_bfloat16* __restrict__ Bgl,
                    const float* __restrict__ bias,
                    float* __restrict__ C,
                    __nv_bfloat16* __restrict__ oqh, __nv_bfloat16* __restrict__ oql,
                    __nv_bfloat16* __restrict__ okh, __nv_bfloat16* __restrict__ okl,
                    __nv_bfloat16* __restrict__ ovh, __nv_bfloat16* __restrict__ ovl,
                    int M, int N, int K)
{
    extern __shared__ __align__(16) char gsm[];
    const uint32_t sb = smem_u32(gsm);

    const int tid  = threadIdx.x;
    const int lane = tid & 31;
    const int wid  = tid >> 5;              // 0..15
    const int brow = blockIdx.y * 256;
    const int bcol = blockIdx.x * 128;

    const int m_base = (wid >> 2) * 64;     // 0..192
    const int n_base = (wid & 3) * 32;      // 0..96

    const int a_r  = lane & 15;
    const int a_k  = (lane >> 4) * 8;
    const uint32_t ah_rel = G_AH + ((m_base + a_r) * TSTR + a_k) * 2;
    const uint32_t al_rel = G_AL + ((m_base + a_r) * TSTR + a_k) * 2;
    const int b_n  = (lane >> 4) * 8 + (lane & 7);
    const int b_k  = ((lane >> 3) & 1) * 8;
    const uint32_t bh_rel = G_BH + ((n_base + b_n) * TSTR + b_k) * 2;
    const uint32_t bl_rel = G_BL + ((n_base + b_n) * TSTR + b_k) * 2;

    float acc[4][4][4];
    #pragma unroll
    for (int i = 0; i < 4; i++)
        #pragma unroll
        for (int j = 0; j < 4; j++)
            #pragma unroll
            for (int r = 0; r < 4; r++) acc[i][j][r] = 0.f;

    const int nchunks = K / 64;

    // prefetch lambda: one 64-K chunk into stage (c&1)
    auto prefetch = [&](int c) {
        const uint32_t so = sb + (c & 1) * G_STG;
        const size_t k0 = (size_t)c * 64;
        #pragma unroll
        for (int i = 0; i < 4; i++) {            // Ah: 2048 chunks
            int idx = i * 512 + tid;
            int r = idx >> 3, k8 = (idx & 7) << 3;
            cp_async16(so + G_AH + (uint32_t)(r * TSTR + k8) * 2,
                       &Agh[(size_t)(brow + r) * K + k0 + k8]);
        }
        #pragma unroll
        for (int i = 0; i < 4; i++) {            // Al
            int idx = i * 512 + tid;
            int r = idx >> 3, k8 = (idx & 7) << 3;
            cp_async16(so + G_AL + (uint32_t)(r * TSTR + k8) * 2,
                       &Agl[(size_t)(brow + r) * K + k0 + k8]);
        }
        #pragma unroll
        for (int i = 0; i < 2; i++) {            // Bh: 1024 chunks
            int idx = i * 512 + tid;
            int r = idx >> 3, k8 = (idx & 7) << 3;
            cp_async16(so + G_BH + (uint32_t)(r * TSTR + k8) * 2,
                       &Bgh[(size_t)(bcol + r) * K + k0 + k8]);
        }
        #pragma unroll
        for (int i = 0; i < 2; i++) {            // Bl
            int idx = i * 512 + tid;
            int r = idx >> 3, k8 = (idx & 7) << 3;
            cp_async16(so + G_BL + (uint32_t)(r * TSTR + k8) * 2,
                       &Bgl[(size_t)(bcol + r) * K + k0 + k8]);
        }
        CP_COMMIT();
    };

    prefetch(0);

    for (int c = 0; c < nchunks; c++) {
        CP_WAIT(0);
        __syncthreads();          // stage c ready; stage (c+1)&1 free

        if (c + 1 < nchunks) prefetch(c + 1);

        const uint32_t so = sb + (c & 1) * G_STG;
        #pragma unroll
        for (int ks = 0; ks < 64; ks += 16) {
            // pass 1: Ahi x Bhi
            uint32_t ah[4][4], bh[2][4];
            #pragma unroll
            for (int mt = 0; mt < 4; mt++)
                ldsm_x4(ah[mt], so + ah_rel + (mt * 16 * TSTR + ks) * 2);
            #pragma unroll
            for (int p = 0; p < 2; p++)
                ldsm_x4(bh[p], so + bh_rel + (p * 16 * TSTR + ks) * 2);
            #pragma unroll
            for (int mt = 0; mt < 4; mt++)
                #pragma unroll
                for (int nt = 0; nt < 4; nt++) {
                    const int p = nt >> 1, hx = (nt & 1) * 2;
                    mma16816(acc[mt][nt], ah[mt], bh[p][hx], bh[p][hx + 1]);
                }
            // pass 2: Ahi x Blo
            uint32_t bl[2][4];
            #pragma unroll
            for (int p = 0; p < 2; p++)
                ldsm_x4(bl[p], so + bl_rel + (p * 16 * TSTR + ks) * 2);
            #pragma unroll
            for (int mt = 0; mt < 4; mt++)
                #pragma unroll
                for (int nt = 0; nt < 4; nt++) {
                    const int p = nt >> 1, hx = (nt & 1) * 2;
                    mma16816(acc[mt][nt], ah[mt], bl[p][hx], bl[p][hx + 1]);
                }
            // pass 3: Alo x Bhi
            uint32_t al[4][4];
            #pragma unroll
            for (int mt = 0; mt < 4; mt++)
                ldsm_x4(al[mt], so + al_rel + (mt * 16 * TSTR + ks) * 2);
            #pragma unroll
            for (int mt = 0; mt < 4; mt++)
                #pragma unroll
                for (int nt = 0; nt < 4; nt++) {
                    const int p = nt >> 1, hx = (nt & 1) * 2;
                    mma16816(acc[mt][nt], al[mt], bh[p][hx], bh[p][hx + 1]);
                }
        }
    }

    // --- epilogue ---
    #pragma unroll
    for (int nt = 0; nt < 4; nt++) {
        const int ncol = bcol + n_base + nt * 8 + (lane & 3) * 2;
        float2 bv = *reinterpret_cast<const float2*>(&bias[ncol]);
        if (MODE == 0) {
            #pragma unroll
            for (int mt = 0; mt < 4; mt++) {
                int row0 = brow + m_base + mt * 16 + (lane >> 2);
                float2 v0, v1;
                v0.x = acc[mt][nt][0] + bv.x;  v0.y = acc[mt][nt][1] + bv.y;
                v1.x = acc[mt][nt][2] + bv.x;  v1.y = acc[mt][nt][3] + bv.y;
                *reinterpret_cast<float2*>(&C[(size_t)row0 * N + ncol]) = v0;
                *reinterpret_cast<float2*>(&C[(size_t)(row0 + 8) * N + ncol]) = v1;
            }
        } else {
            const int region = ncol >> 10;
            const int hh = (ncol >> 6) & (HH - 1);
            const int dd = ncol & (HDD - 1);
            __nv_bfloat16* oh = (region == 0) ? oqh : (region == 1) ? okh : ovh;
            __nv_bfloat16* ol = (region == 0) ? oql : (region == 1) ? okl : ovl;
            const float sc = (region == 0) ? QSC : 1.f;
            const size_t colbase = (size_t)hh * (SS * HDD) + dd;
            #pragma unroll
            for (int mt = 0; mt < 4; mt++) {
                int row0 = brow + m_base + mt * 16 + (lane >> 2);
                #pragma unroll
                for (int rr = 0; rr < 2; rr++) {
                    int row = row0 + rr * 8;
                    float v0 = (acc[mt][nt][rr * 2 + 0] + bv.x) * sc;
                    float v1 = (acc[mt][nt][rr * 2 + 1] + bv.y) * sc;
                    __nv_bfloat16 h0 = __float2bfloat16_rn(v0);
                    __nv_bfloat16 h1 = __float2bfloat16_rn(v1);
                    __nv_bfloat16 l0 = __float2bfloat16_rn(v0 - __bfloat162float(h0));
                    __nv_bfloat16 l1 = __float2bfloat16_rn(v1 - __bfloat162float(h1));
                    int bb = row >> 11, ss = row & (SS - 1);
                    size_t off = (size_t)bb * HH * SS * HDD + colbase + (size_t)ss * HDD;
                    *reinterpret_cast<uint32_t*>(&oh[off]) = pack_bf2(h0, h1);
                    *reinterpret_cast<uint32_t*>(&ol[off]) = pack_bf2(l0, l1);
                }
            }
        }
    }
}

// ---------------------------------------------------------------------------
// Tensor-core causal flash attention: BM=128 (8 warps, 256 threads),
// cp.async 2-stage K/V ring (64 keys/tile), Q-lo in dedicated smem.
// ---------------------------------------------------------------------------
#define FS_KH   0
#define FS_KL   9216
#define FS_VH   18432
#define FS_VL   27648
#define FS_STG  36864                  // one ring stage (4 arrays x 64 x KSTR x 2B)
#define FS_QL   (2 * FS_STG)           // 73728: Q-lo, 128 x KSTR x 2 = 18432
#define FS_TOTAL (FS_QL + 18432)       // 92160

__global__ __launch_bounds__(256, 2)
void flash_attn_tc(const __nv_bfloat16* __restrict__ Qh, const __nv_bfloat16* __restrict__ Ql,
                   const __nv_bfloat16* __restrict__ Kh, const __nv_bfloat16* __restrict__ Kl,
                   const __nv_bfloat16* __restrict__ Vh, const __nv_bfloat16* __restrict__ Vl,
                   __nv_bfloat16* __restrict__ yh, __nv_bfloat16* __restrict__ yl)
{
    extern __shared__ __align__(16) char sm[];
    const uint32_t sbase = smem_u32(sm);

    const int tid  = threadIdx.x;
    const int lane = tid & 31;
    const int w    = tid >> 5;                        // 0..7
    const int qtile = (gridDim.x - 1) - blockIdx.x;   // long tiles first
    const int h = blockIdx.y;
    const int b = blockIdx.z;
    const size_t base = ((size_t)(b * HH + h)) * SS * HDD;

    // ---- load Q: Qh staged in ring stage 0, Ql into permanent slot ----
    {
        const int s0 = qtile * 128;
        #pragma unroll
        for (int i = 0; i < 4; i++) {
            int idx = i * 256 + tid;                  // 0..1023
            int r  = idx >> 3;
            int c8 = (idx & 7) * 8;
            uint32_t so = (uint32_t)(r * KSTR + c8) * 2;
            size_t g = base + (size_t)(s0 + r) * HDD + c8;
            *reinterpret_cast<uint4*>(sm + so) =
                *reinterpret_cast<const uint4*>(&Qh[g]);
            *reinterpret_cast<uint4*>(sm + FS_QL + so) =
                *reinterpret_cast<const uint4*>(&Ql[g]);
        }
    }
    __syncthreads();

    // Q-hi fragments resident in registers; Q-lo re-loaded per tile from smem
    uint32_t qfh[4][4];
    const uint32_t q_rel = ((w * 16 + (lane & 15)) * KSTR + (lane >> 4) * 8) * 2;
    {
        const uint32_t qa = sbase + q_rel;
        #pragma unroll
        for (int kc = 0; kc < 4; kc++) ldsm_x4(qfh[kc], qa + kc * 32);
    }
    __syncthreads();   // Q-hi staging dead; ring stage 0 reusable
    const uint32_t qla = sbase + FS_QL + q_rel;

    const uint32_t ka_rel = (((lane >> 4) * 8 + (lane & 7)) * KSTR +
                             ((lane >> 3) & 1) * 8) * 2;
    const uint32_t va_rel = ((((lane >> 3) & 1) * 8 + (lane & 7)) * KSTR +
                             ((lane >> 4) & 1) * 8) * 2;

    float o[8][4];
    #pragma unroll
    for (int j = 0; j < 8; j++)
        #pragma unroll
        for (int r = 0; r < 4; r++) o[j][r] = 0.f;
    float m0 = -1e30f, m1 = -1e30f, l0 = 0.f, l1 = 0.f;

    const int row_a0 = qtile * 128 + w * 16 + (lane >> 2);
    const int num_kv = 2 * qtile + 2;

    // KV tile loader into stage (t&1)
    auto kv_load = [&](int t) {
        const uint32_t sa = sbase + (uint32_t)(t & 1) * FS_STG;
        const size_t gb = base + (size_t)t * 64 * HDD;
        #pragma unroll
        for (int ii = 0; ii < 2; ii++) {
            int j  = ii * 256 + tid;                  // 0..511
            int r  = j >> 3;
            int c8 = (j & 7) * 8;
            size_t g = gb + (size_t)r * HDD + c8;
            uint32_t s_ = (uint32_t)(r * KSTR + c8) * 2;
            cp_async16(sa + FS_KH + s_, Kh + g);
            cp_async16(sa + FS_KL + s_, Kl + g);
            cp_async16(sa + FS_VH + s_, Vh + g);
            cp_async16(sa + FS_VL + s_, Vl + g);
        }
        CP_COMMIT();
    };

    kv_load(0);

    for (int t = 0; t < num_kv; t++) {
        CP_WAIT(0);
        __syncthreads();

        if (t + 1 < num_kv) kv_load(t + 1);

        const uint32_t sa = sbase + (uint32_t)(t & 1) * FS_STG;
        const uint32_t ka_h = sa + FS_KH + ka_rel;
        const uint32_t ka_l = sa + FS_KL + ka_rel;
        const uint32_t va_h = sa + FS_VH + va_rel;
        const uint32_t va_l = sa + FS_VL + va_rel;

        // ---- S = Q K^T ----
        float s[8][4];
        #pragma unroll
        for (int j = 0; j < 8; j++)
            #pragma unroll
            for (int r = 0; r < 4; r++) s[j][r] = 0.f;

        #pragma unroll
        for (int kc = 0; kc < 4; kc++) {
            uint32_t qfl4[4];
            ldsm_x4(qfl4, qla + kc * 32);
            #pragma unroll
            for (int np = 0; np < 4; np++) {
                uint32_t kh4[4], kl4[4];
                ldsm_x4(kh4, ka_h + np * (16 * KSTR * 2) + kc * 32);
                ldsm_x4(kl4, ka_l + np * (16 * KSTR * 2) + kc * 32);
                mma16816(s[2*np],   qfh[kc], kh4[0], kh4[1]);
                mma16816(s[2*np+1], qfh[kc], kh4[2], kh4[3]);
                mma16816(s[2*np],   qfl4,    kh4[0], kh4[1]);
                mma16816(s[2*np+1], qfl4,    kh4[2], kh4[3]);
                mma16816(s[2*np],   qfh[kc], kl4[0], kl4[1]);
                mma16816(s[2*np+1], qfh[kc], kl4[2], kl4[3]);
            }
        }

        // ---- causal mask (only the last two tiles can cross the diagonal) ----
        if (t >= 2 * qtile) {
            #pragma unroll
            for (int j = 0; j < 8; j++) {
                int col = t * 64 + j * 8 + (lane & 3) * 2;
                #pragma unroll
                for (int r = 0; r < 4; r++) {
                    int cc = col + (r & 1);
                    int rw = row_a0 + ((r >= 2) ? 8 : 0);
                    if (cc > rw) s[j][r] = -1e30f;
                }
            }
        }

        // ---- online softmax ----
        float mx0 = -1e30f, mx1 = -1e30f;
        #pragma unroll
        for (int j = 0; j < 8; j++) {
            mx0 = fmaxf(mx0, fmaxf(s[j][0], s[j][1]));
            mx1 = fmaxf(mx1, fmaxf(s[j][2], s[j][3]));
        }
        mx0 = fmaxf(mx0, __shfl_xor_sync(0xffffffffu, mx0, 1));
        mx0 = fmaxf(mx0, __shfl_xor_sync(0xffffffffu, mx0, 2));
        mx1 = fmaxf(mx1, __shfl_xor_sync(0xffffffffu, mx1, 1));
        mx1 = fmaxf(mx1, __shfl_xor_sync(0xffffffffu, mx1, 2));
        float mn0 = fmaxf(m0, mx0), mn1 = fmaxf(m1, mx1);
        float sc0 = ex2f(m0 - mn0), sc1 = ex2f(m1 - mn1);
        m0 = mn0; m1 = mn1;
        l0 *= sc0; l1 *= sc1;
        #pragma unroll
        for (int j = 0; j < 8; j++) {
            o[j][0] *= sc0; o[j][1] *= sc0;
            o[j][2] *= sc1; o[j][3] *= sc1;
        }
        #pragma unroll
        for (int j = 0; j < 8; j++) {
            float p0 = ex2f(s[j][0] - mn0);
            float p1 = ex2f(s[j][1] - mn0);
            float p2 = ex2f(s[j][2] - mn1);
            float p3 = ex2f(s[j][3] - mn1);
            s[j][0] = p0; s[j][1] = p1; s[j][2] = p2; s[j][3] = p3;
            l0 += p0 + p1;
            l1 += p2 + p3;
        }

        // ---- O += P V ----
        #pragma unroll
        for (int kc = 0; kc < 4; kc++) {
            uint32_t aph[4], apl[4];
            #pragma unroll
            for (int t2 = 0; t2 < 2; t2++) {
                int j = 2 * kc + t2;
                __nv_bfloat16 h0 = __float2bfloat16_rn(s[j][0]);
                __nv_bfloat16 h1 = __float2bfloat16_rn(s[j][1]);
                __nv_bfloat16 h2 = __float2bfloat16_rn(s[j][2]);
                __nv_bfloat16 h3 = __float2bfloat16_rn(s[j][3]);
                aph[t2*2 + 0] = pack_bf2(h0, h1);
                aph[t2*2 + 1] = pack_bf2(h2, h3);
                apl[t2*2 + 0] = pack_bf2(
                    __float2bfloat16_rn(s[j][0] - __bfloat162float(h0)),
                    __float2bfloat16_rn(s[j][1] - __bfloat162float(h1)));
                apl[t2*2 + 1] = pack_bf2(
                    __float2bfloat16_rn(s[j][2] - __bfloat162float(h2)),
                    __float2bfloat16_rn(s[j][3] - __bfloat162float(h3)));
            }
            #pragma unroll
            for (int nb = 0; nb < 4; nb++) {
                uint32_t vh4[4], vl4[4];
                ldsm_x4_t(vh4, va_h + kc * (16 * KSTR * 2) + nb * 32);
                ldsm_x4_t(vl4, va_l + kc * (16 * KSTR * 2) + nb * 32);
                mma16816(o[2*nb],   aph, vh4[0], vh4[1]);
                mma16816(o[2*nb+1], aph, vh4[2], vh4[3]);
                mma16816(o[2*nb],   apl, vh4[0], vh4[1]);
                mma16816(o[2*nb+1], apl, vh4[2], vh4[3]);
                mma16816(o[2*nb],   aph, vl4[0], vl4[1]);
                mma16816(o[2*nb+1], aph, vl4[2], vl4[3]);
            }
        }
    }

    l0 += __shfl_xor_sync(0xffffffffu, l0, 1);
    l0 += __shfl_xor_sync(0xffffffffu, l0, 2);
    l1 += __shfl_xor_sync(0xffffffffu, l1, 1);
    l1 += __shfl_xor_sync(0xffffffffu, l1, 2);
    float inv0 = 1.f / l0, inv1 = 1.f / l1;

    // epilogue: write split bf16 y (row-major [8192, 1024])
    size_t tok0 = (size_t)b * SS + row_a0;
    size_t o0 = tok0 * DD + h * HDD + (lane & 3) * 2;
    size_t o1 = o0 + (size_t)8 * DD;
    #pragma unroll
    for (int j = 0; j < 8; j++) {
        float v00 = o[j][0] * inv0, v01 = o[j][1] * inv0;
        float v10 = o[j][2] * inv1, v11 = o[j][3] * inv1;
        __nv_bfloat16 h00 = __float2bfloat16_rn(v00);
        __nv_bfloat16 h01 = __float2bfloat16_rn(v01);
        __nv_bfloat16 h10 = __float2bfloat16_rn(v10);
        __nv_bfloat16 h11 = __float2bfloat16_rn(v11);
        *reinterpret_cast<uint32_t*>(&yh[o0 + j * 8]) = pack_bf2(h00, h01);
        *reinterpret_cast<uint32_t*>(&yl[o0 + j * 8]) = pack_bf2(
            __float2bfloat16_rn(v00 - __bfloat162float(h00)),
            __float2bfloat16_rn(v01 - __bfloat162float(h01)));
        *reinterpret_cast<uint32_t*>(&yh[o1 + j * 8]) = pack_bf2(h10, h11);
        *reinterpret_cast<uint32_t*>(&yl[o1 + j * 8]) = pack_bf2(
            __float2bfloat16_rn(v10 - __bfloat162float(h10)),
            __float2bfloat16_rn(v11 - __bfloat162float(h11)));
    }
}

// ---------------------------------------------------------------------------
// Launch
// ---------------------------------------------------------------------------
extern "C" void kernel_launch(void* const* d_in, const int* in_sizes, int n_in,
                              void* d_out, int out_size)
{
    const float* x      = (const float*)d_in[0];
    const float* W_attn = (const float*)d_in[1];
    const float* b_attn = (const float*)d_in[2];
    const float* W_proj = (const float*)d_in[3];
    const float* b_proj = (const float*)d_in[4];
    float* out = (float*)d_out;

    static __nv_bfloat16 *xh = nullptr, *xl, *yh, *yl;
    static __nv_bfloat16 *wt_hi, *wt_lo, *wpt_hi, *wpt_lo;
    static __nv_bfloat16 *qh, *ql, *kh, *kl, *vh, *vl;
    if (!xh) {   // first (non-captured) correctness call
        cudaGetSymbolAddress((void**)&xh, g_xh);
        cudaGetSymbolAddress((void**)&xl, g_xl);
        cudaGetSymbolAddress((void**)&yh, g_yh);
        cudaGetSymbolAddress((void**)&yl, g_yl);
        cudaGetSymbolAddress((void**)&wt_hi,  g_wt_hi);
        cudaGetSymbolAddress((void**)&wt_lo,  g_wt_lo);
        cudaGetSymbolAddress((void**)&wpt_hi, g_wpt_hi);
        cudaGetSymbolAddress((void**)&wpt_lo, g_wpt_lo);
        cudaGetSymbolAddress((void**)&qh, g_qh);
        cudaGetSymbolAddress((void**)&ql, g_ql);
        cudaGetSymbolAddress((void**)&kh, g_kh);
        cudaGetSymbolAddress((void**)&kl, g_kl);
        cudaGetSymbolAddress((void**)&vh, g_vh);
        cudaGetSymbolAddress((void**)&vl, g_vl);
        cudaFuncSetAttribute(flash_attn_tc,
                             cudaFuncAttributeMaxDynamicSharedMemorySize,
                             FS_TOTAL);
        cudaFuncSetAttribute(tc_gemm_kernel<0>,
                             cudaFuncAttributeMaxDynamicSharedMemorySize,
                             GEMM_SMEM);
        cudaFuncSetAttribute(tc_gemm_kernel<1>,
                             cudaFuncAttributeMaxDynamicSharedMemorySize,
                             GEMM_SMEM);
    }

    // 0a) split x -> bf16 hi/lo
    split_kernel<<<(MTOK * DD) / (256 * 4), 256>>>(x, xh, xl);
    // 0b) transpose + split weights
    {
        dim3 g1(3 * DD / 32, DD / 32);
        transpose_split_kernel<<<g1, 256>>>(W_attn, wt_hi, wt_lo, DD, 3 * DD);
        dim3 g2(DD / 32, DD / 32);
        transpose_split_kernel<<<g2, 256>>>(W_proj, wpt_hi, wpt_lo, DD, DD);
    }

    // 1) QKV GEMM + fused split epilogue
    {
        dim3 grid(3 * DD / 128, MTOK / 256);
        tc_gemm_kernel<1><<<grid, 512, GEMM_SMEM>>>(
            xh, xl, wt_hi, wt_lo, b_attn, nullptr,
            qh, ql, kh, kl, vh, vl, MTOK, 3 * DD, DD);
    }

    // 2) tensor-core causal flash attention -> split bf16 y
    {
        dim3 grid(SS / 128, HH, BB);
        flash_attn_tc<<<grid, 256, FS_TOTAL>>>(qh, ql, kh, kl, vh, vl, yh, yl);
    }

    // 3) output projection -> out
    {
        dim3 grid(DD / 128, MTOK / 256);
        tc_gemm_kernel<0><<<grid, 512, GEMM_SMEM>>>(
            yh, yl, wpt_hi, wpt_lo, b_proj, out,
            nullptr, nullptr, nullptr, nullptr, nullptr, nullptr,
            MTOK, DD, DD);
    }
}

// round 8
// speedup vs baseline: 1.0263x; 1.0263x over previous
#include <cuda_runtime.h>
#include <cuda_bf16.h>
#include <cstdint>
#include <cstddef>

// Problem constants
#define BB  4
#define SS  2048
#define DD  1024
#define HH  16
#define HDD 64
#define MTOK (BB*SS)          // 8192 token rows

// q prescale: HD^-0.5 * log2(e)  (softmax done in exp2 domain)
#define QSC 0.18033688011112042f

// Scratch (device globals; no allocations allowed)
__device__ __align__(128) __nv_bfloat16 g_xh[(size_t)MTOK * DD];
__device__ __align__(128) __nv_bfloat16 g_xl[(size_t)MTOK * DD];
__device__ __align__(128) __nv_bfloat16 g_yh[(size_t)MTOK * DD];
__device__ __align__(128) __nv_bfloat16 g_yl[(size_t)MTOK * DD];
__device__ __align__(128) __nv_bfloat16 g_wt_hi [(size_t)3 * DD * DD];
__device__ __align__(128) __nv_bfloat16 g_wt_lo [(size_t)3 * DD * DD];
__device__ __align__(128) __nv_bfloat16 g_wpt_hi[(size_t)DD * DD];
__device__ __align__(128) __nv_bfloat16 g_wpt_lo[(size_t)DD * DD];
#define BHSZ ((size_t)BB * HH * SS * HDD)
__device__ __align__(128) __nv_bfloat16 g_qh[BHSZ], g_ql[BHSZ];
__device__ __align__(128) __nv_bfloat16 g_kh[BHSZ], g_kl[BHSZ];
__device__ __align__(128) __nv_bfloat16 g_vh[BHSZ], g_vl[BHSZ];

// ---------------------------------------------------------------------------
// Warp-MMA + async-copy helpers
// ---------------------------------------------------------------------------
__device__ __forceinline__ uint32_t smem_u32(const void* p) {
    uint32_t a;
    asm("{ .reg .u64 t; cvta.to.shared.u64 t, %1; cvt.u32.u64 %0, t; }"
        : "=r"(a) : "l"(p));
    return a;
}
__device__ __forceinline__ void ldsm_x4(uint32_t* r, uint32_t addr) {
    asm volatile("ldmatrix.sync.aligned.m8n8.x4.shared.b16 {%0,%1,%2,%3}, [%4];"
                 : "=r"(r[0]), "=r"(r[1]), "=r"(r[2]), "=r"(r[3]) : "r"(addr));
}
__device__ __forceinline__ void ldsm_x4_t(uint32_t* r, uint32_t addr) {
    asm volatile("ldmatrix.sync.aligned.m8n8.x4.trans.shared.b16 {%0,%1,%2,%3}, [%4];"
                 : "=r"(r[0]), "=r"(r[1]), "=r"(r[2]), "=r"(r[3]) : "r"(addr));
}
__device__ __forceinline__ void mma16816(float* d, const uint32_t* a,
                                         const uint32_t b0, const uint32_t b1) {
    asm volatile(
        "mma.sync.aligned.m16n8k16.row.col.f32.bf16.bf16.f32 "
        "{%0,%1,%2,%3}, {%4,%5,%6,%7}, {%8,%9}, {%0,%1,%2,%3};"
        : "+f"(d[0]), "+f"(d[1]), "+f"(d[2]), "+f"(d[3])
        : "r"(a[0]), "r"(a[1]), "r"(a[2]), "r"(a[3]), "r"(b0), "r"(b1));
}
__device__ __forceinline__ void cp_async16(uint32_t saddr, const void* g) {
    asm volatile("cp.async.cg.shared.global [%0], [%1], 16;"
                 :: "r"(saddr), "l"(g) : "memory");
}
#define CP_COMMIT() asm volatile("cp.async.commit_group;" ::: "memory")
#define CP_WAIT(n)  asm volatile("cp.async.wait_group %0;" :: "n"(n) : "memory")

__device__ __forceinline__ uint32_t pack_bf2(__nv_bfloat16 a, __nv_bfloat16 b) {
    __nv_bfloat162 t; t.x = a; t.y = b;
    return *reinterpret_cast<uint32_t*>(&t);
}
__device__ __forceinline__ float ex2f(float x) {
    float r;
    asm("ex2.approx.f32 %0, %1;" : "=f"(r) : "f"(x));
    return r;
}

#define TSTR 40   // GEMM tile row stride (elems): 80B rows, conflict-free ldsm
#define KSTR 72   // attention tile row stride (144B rows, conflict-free)

// ---------------------------------------------------------------------------
// Elementwise fp32 -> bf16 hi/lo split (for x)
// ---------------------------------------------------------------------------
__global__ __launch_bounds__(256)
void split_kernel(const float* __restrict__ in,
                  __nv_bfloat16* __restrict__ hi,
                  __nv_bfloat16* __restrict__ lo)
{
    size_t i = ((size_t)blockIdx.x * 256 + threadIdx.x) * 4;
    float4 v = *reinterpret_cast<const float4*>(in + i);
    __nv_bfloat16 h0 = __float2bfloat16_rn(v.x);
    __nv_bfloat16 h1 = __float2bfloat16_rn(v.y);
    __nv_bfloat16 h2 = __float2bfloat16_rn(v.z);
    __nv_bfloat16 h3 = __float2bfloat16_rn(v.w);
    uint2 hv, lv;
    hv.x = pack_bf2(h0, h1); hv.y = pack_bf2(h2, h3);
    lv.x = pack_bf2(__float2bfloat16_rn(v.x - __bfloat162float(h0)),
                    __float2bfloat16_rn(v.y - __bfloat162float(h1)));
    lv.y = pack_bf2(__float2bfloat16_rn(v.z - __bfloat162float(h2)),
                    __float2bfloat16_rn(v.w - __bfloat162float(h3)));
    *reinterpret_cast<uint2*>(hi + i) = hv;
    *reinterpret_cast<uint2*>(lo + i) = lv;
}

// ---------------------------------------------------------------------------
// Transpose + bf16 hi/lo split of weights:  W[K,N] fp32 -> Th/Tl[N,K] bf16
// ---------------------------------------------------------------------------
__global__ __launch_bounds__(256)
void transpose_split_kernel(const float* __restrict__ W,
                            __nv_bfloat16* __restrict__ Th,
                            __nv_bfloat16* __restrict__ Tl,
                            int K, int N)
{
    __shared__ float tile[32][33];
    const int n0 = blockIdx.x * 32;
    const int k0 = blockIdx.y * 32;
    const int tx = threadIdx.x & 31;
    const int ty4 = (threadIdx.x >> 5) * 4;

    #pragma unroll
    for (int j = 0; j < 4; j++)
        tile[ty4 + j][tx] = W[(size_t)(k0 + ty4 + j) * N + n0 + tx];
    __syncthreads();
    #pragma unroll
    for (int j = 0; j < 4; j++) {
        float v = tile[tx][ty4 + j];
        __nv_bfloat16 hi = __float2bfloat16_rn(v);
        __nv_bfloat16 lo = __float2bfloat16_rn(v - __bfloat162float(hi));
        size_t o = (size_t)(n0 + ty4 + j) * K + k0 + tx;
        Th[o] = hi;
        Tl[o] = lo;
    }
}

// ---------------------------------------------------------------------------
// cp.async 2-stage tensor-core GEMM (bf16 hi/lo, fp32 accum)
// BM=128, BN=128, BK=32, 128 threads (4 warps, 64x64 warp tiles), 2 CTA/SM.
// Per k16-step per warp: 16 LDSM + 96 HMMA -> issue load ~29%, tensor-bound.
// MODE 0: fp32 C.  MODE 1 (QKV): split bf16 q/k/v per-head buffers.
// ---------------------------------------------------------------------------
#define ARR_BYTES (128 * TSTR * 2)        // 10240 per array
#define G_AH 0
#define G_AL (1 * ARR_BYTES)
#define G_BH (2 * ARR_BYTES)
#define G_BL (3 * ARR_BYTES)
#define G_STG (4 * ARR_BYTES)             // 40960 per stage
#define GEMM_SMEM (2 * G_STG)             // 81920

template <int MODE>
__global__ __launch_bounds__(128, 2)
void tc_gemm_kernel(const __nv_bfloat16* __restrict__ Agh,
                    const __nv_bfloat16* __restrict__ Agl,
                    const __nv_bfloat16* __restrict__ Bgh,
                    const __nv_bfloat16* __restrict__ Bgl,
                    const float* __restrict__ bias,
                    float* __restrict__ C,
                    __nv_bfloat16* __restrict__ oqh, __nv_bfloat16* __restrict__ oql,
                    __nv_bfloat16* __restrict__ okh, __nv_bfloat16* __restrict__ okl,
                    __nv_bfloat16* __restrict__ ovh, __nv_bfloat16* __restrict__ ovl,
                    int M, int N, int K)
{
    extern __shared__ __align__(16) char gsm[];
    const uint32_t sb = smem_u32(gsm);

    const int tid  = threadIdx.x;
    const int lane = tid & 31;
    const int wid  = tid >> 5;              // 0..3
    const int brow = blockIdx.y * 128;
    const int bcol = blockIdx.x * 128;

    const int m_base = (wid >> 1) * 64;     // 0 / 64
    const int n_base = (wid & 1) * 64;      // 0 / 64

    // per-thread cp.async src/dst: 16 chunks of 16B per stage
    // idx = i*128+tid; arr = idx>>9; j = idx&511; r = j>>2; k8 = (j&3)*8
    const __nv_bfloat16* gsrc[16];
    uint32_t sdst[16];
    #pragma unroll
    for (int i = 0; i < 16; i++) {
        int idx = i * 128 + tid;
        int arr = idx >> 9;
        int j   = idx & 511;
        int r   = j >> 2;
        int k8  = (j & 3) << 3;
        const __nv_bfloat16* g =
            (arr == 0) ? &Agh[(size_t)(brow + r) * K + k8] :
            (arr == 1) ? &Agl[(size_t)(brow + r) * K + k8] :
            (arr == 2) ? &Bgh[(size_t)(bcol + r) * K + k8] :
                         &Bgl[(size_t)(bcol + r) * K + k8];
        gsrc[i] = g;
        sdst[i] = sb + arr * ARR_BYTES + (uint32_t)(r * TSTR + k8) * 2;
    }

    const int a_r  = lane & 15;
    const int a_k  = (lane >> 4) * 8;
    const uint32_t ah_rel = G_AH + ((m_base + a_r) * TSTR + a_k) * 2;
    const uint32_t al_rel = G_AL + ((m_base + a_r) * TSTR + a_k) * 2;
    const int b_n  = (lane >> 4) * 8 + (lane & 7);
    const int b_k  = ((lane >> 3) & 1) * 8;
    const uint32_t bh_rel = G_BH + ((n_base + b_n) * TSTR + b_k) * 2;
    const uint32_t bl_rel = G_BL + ((n_base + b_n) * TSTR + b_k) * 2;

    float acc[4][8][4];
    #pragma unroll
    for (int i = 0; i < 4; i++)
        #pragma unroll
        for (int j = 0; j < 8; j++)
            #pragma unroll
            for (int r = 0; r < 4; r++) acc[i][j][r] = 0.f;

    const int nchunks = K / 32;

    // prologue: stage 0
    #pragma unroll
    for (int i = 0; i < 16; i++) cp_async16(sdst[i], gsrc[i]);
    CP_COMMIT();

    for (int c = 0; c < nchunks; c++) {
        CP_WAIT(0);
        __syncthreads();          // stage c ready; stage (c+1)&1 free

        if (c + 1 < nchunks) {
            const uint32_t so = ((c + 1) & 1) * G_STG;
            const size_t go = (size_t)(c + 1) * 32;
            #pragma unroll
            for (int i = 0; i < 16; i++) cp_async16(sdst[i] + so, gsrc[i] + go);
            CP_COMMIT();
        }

        const uint32_t so = sb + (c & 1) * G_STG;
        #pragma unroll
        for (int ks = 0; ks < 32; ks += 16) {
            uint32_t ah[4][4], al[4][4], bh[4][4], bl[4][4];
            #pragma unroll
            for (int mt = 0; mt < 4; mt++)
                ldsm_x4(ah[mt], so + ah_rel + (mt * 16 * TSTR + ks) * 2);
            #pragma unroll
            for (int p = 0; p < 4; p++)
                ldsm_x4(bh[p], so + bh_rel + (p * 16 * TSTR + ks) * 2);
            // pass 1: Ahi x Bhi (32 MMAs, RAW distance 32)
            #pragma unroll
            for (int mt = 0; mt < 4; mt++)
                #pragma unroll
                for (int nt = 0; nt < 8; nt++) {
                    const int p = nt >> 1, hx = (nt & 1) * 2;
                    mma16816(acc[mt][nt], ah[mt], bh[p][hx], bh[p][hx + 1]);
                }
            // pass 2: Ahi x Blo
            #pragma unroll
            for (int p = 0; p < 4; p++)
                ldsm_x4(bl[p], so + bl_rel + (p * 16 * TSTR + ks) * 2);
            #pragma unroll
            for (int mt = 0; mt < 4; mt++)
                #pragma unroll
                for (int nt = 0; nt < 8; nt++) {
                    const int p = nt >> 1, hx = (nt & 1) * 2;
                    mma16816(acc[mt][nt], ah[mt], bl[p][hx], bl[p][hx + 1]);
                }
            // pass 3: Alo x Bhi
            #pragma unroll
            for (int mt = 0; mt < 4; mt++)
                ldsm_x4(al[mt], so + al_rel + (mt * 16 * TSTR + ks) * 2);
            #pragma unroll
            for (int mt = 0; mt < 4; mt++)
                #pragma unroll
                for (int nt = 0; nt < 8; nt++) {
                    const int p = nt >> 1, hx = (nt & 1) * 2;
                    mma16816(acc[mt][nt], al[mt], bh[p][hx], bh[p][hx + 1]);
                }
        }
    }

    // --- epilogue ---
    #pragma unroll
    for (int nt = 0; nt < 8; nt++) {
        const int ncol = bcol + n_base + nt * 8 + (lane & 3) * 2;
        float2 bv = *reinterpret_cast<const float2*>(&bias[ncol]);
        if (MODE == 0) {
            #pragma unroll
            for (int mt = 0; mt < 4; mt++) {
                int row0 = brow + m_base + mt * 16 + (lane >> 2);
                float2 v0, v1;
                v0.x = acc[mt][nt][0] + bv.x;  v0.y = acc[mt][nt][1] + bv.y;
                v1.x = acc[mt][nt][2] + bv.x;  v1.y = acc[mt][nt][3] + bv.y;
                *reinterpret_cast<float2*>(&C[(size_t)row0 * N + ncol]) = v0;
                *reinterpret_cast<float2*>(&C[(size_t)(row0 + 8) * N + ncol]) = v1;
            }
        } else {
            const int region = ncol >> 10;
            const int hh = (ncol >> 6) & (HH - 1);
            const int dd = ncol & (HDD - 1);
            __nv_bfloat16* oh = (region == 0) ? oqh : (region == 1) ? okh : ovh;
            __nv_bfloat16* ol = (region == 0) ? oql : (region == 1) ? okl : ovl;
            const float sc = (region == 0) ? QSC : 1.f;
            const size_t colbase = (size_t)hh * (SS * HDD) + dd;
            #pragma unroll
            for (int mt = 0; mt < 4; mt++) {
                int row0 = brow + m_base + mt * 16 + (lane >> 2);
                #pragma unroll
                for (int rr = 0; rr < 2; rr++) {
                    int row = row0 + rr * 8;
                    float v0 = (acc[mt][nt][rr * 2 + 0] + bv.x) * sc;
                    float v1 = (acc[mt][nt][rr * 2 + 1] + bv.y) * sc;
                    __nv_bfloat16 h0 = __float2bfloat16_rn(v0);
                    __nv_bfloat16 h1 = __float2bfloat16_rn(v1);
                    __nv_bfloat16 l0 = __float2bfloat16_rn(v0 - __bfloat162float(h0));
                    __nv_bfloat16 l1 = __float2bfloat16_rn(v1 - __bfloat162float(h1));
                    int bb = row >> 11, ss = row & (SS - 1);
                    size_t off = (size_t)bb * HH * SS * HDD + colbase + (size_t)ss * HDD;
                    *reinterpret_cast<uint32_t*>(&oh[off]) = pack_bf2(h0, h1);
                    *reinterpret_cast<uint32_t*>(&ol[off]) = pack_bf2(l0, l1);
                }
            }
        }
    }
}

// ---------------------------------------------------------------------------
// Tensor-core causal flash attention: BM=128 (8 warps, 256 threads),
// cp.async 2-stage K/V ring (64 keys/tile), Q-lo in dedicated smem. (as R7)
// ---------------------------------------------------------------------------
#define FS_KH   0
#define FS_KL   9216
#define FS_VH   18432
#define FS_VL   27648
#define FS_STG  36864
#define FS_QL   (2 * FS_STG)           // 73728
#define FS_TOTAL (FS_QL + 18432)       // 92160

__global__ __launch_bounds__(256, 2)
void flash_attn_tc(const __nv_bfloat16* __restrict__ Qh, const __nv_bfloat16* __restrict__ Ql,
                   const __nv_bfloat16* __restrict__ Kh, const __nv_bfloat16* __restrict__ Kl,
                   const __nv_bfloat16* __restrict__ Vh, const __nv_bfloat16* __restrict__ Vl,
                   __nv_bfloat16* __restrict__ yh, __nv_bfloat16* __restrict__ yl)
{
    extern __shared__ __align__(16) char sm[];
    const uint32_t sbase = smem_u32(sm);

    const int tid  = threadIdx.x;
    const int lane = tid & 31;
    const int w    = tid >> 5;                        // 0..7
    const int qtile = (gridDim.x - 1) - blockIdx.x;   // long tiles first
    const int h = blockIdx.y;
    const int b = blockIdx.z;
    const size_t base = ((size_t)(b * HH + h)) * SS * HDD;

    // ---- load Q: Qh staged in ring stage 0, Ql into permanent slot ----
    {
        const int s0 = qtile * 128;
        #pragma unroll
        for (int i = 0; i < 4; i++) {
            int idx = i * 256 + tid;
            int r  = idx >> 3;
            int c8 = (idx & 7) * 8;
            uint32_t so = (uint32_t)(r * KSTR + c8) * 2;
            size_t g = base + (size_t)(s0 + r) * HDD + c8;
            *reinterpret_cast<uint4*>(sm + so) =
                *reinterpret_cast<const uint4*>(&Qh[g]);
            *reinterpret_cast<uint4*>(sm + FS_QL + so) =
                *reinterpret_cast<const uint4*>(&Ql[g]);
        }
    }
    __syncthreads();

    uint32_t qfh[4][4];
    const uint32_t q_rel = ((w * 16 + (lane & 15)) * KSTR + (lane >> 4) * 8) * 2;
    {
        const uint32_t qa = sbase + q_rel;
        #pragma unroll
        for (int kc = 0; kc < 4; kc++) ldsm_x4(qfh[kc], qa + kc * 32);
    }
    __syncthreads();
    const uint32_t qla = sbase + FS_QL + q_rel;

    const uint32_t ka_rel = (((lane >> 4) * 8 + (lane & 7)) * KSTR +
                             ((lane >> 3) & 1) * 8) * 2;
    const uint32_t va_rel = ((((lane >> 3) & 1) * 8 + (lane & 7)) * KSTR +
                             ((lane >> 4) & 1) * 8) * 2;

    float o[8][4];
    #pragma unroll
    for (int j = 0; j < 8; j++)
        #pragma unroll
        for (int r = 0; r < 4; r++) o[j][r] = 0.f;
    float m0 = -1e30f, m1 = -1e30f, l0 = 0.f, l1 = 0.f;

    const int row_a0 = qtile * 128 + w * 16 + (lane >> 2);
    const int num_kv = 2 * qtile + 2;

    auto kv_load = [&](int t) {
        const uint32_t sa = sbase + (uint32_t)(t & 1) * FS_STG;
        const size_t gb = base + (size_t)t * 64 * HDD;
        #pragma unroll
        for (int ii = 0; ii < 2; ii++) {
            int j  = ii * 256 + tid;
            int r  = j >> 3;
            int c8 = (j & 7) * 8;
            size_t g = gb + (size_t)r * HDD + c8;
            uint32_t s_ = (uint32_t)(r * KSTR + c8) * 2;
            cp_async16(sa + FS_KH + s_, Kh + g);
            cp_async16(sa + FS_KL + s_, Kl + g);
            cp_async16(sa + FS_VH + s_, Vh + g);
            cp_async16(sa + FS_VL + s_, Vl + g);
        }
        CP_COMMIT();
    };

    kv_load(0);

    for (int t = 0; t < num_kv; t++) {
        CP_WAIT(0);
        __syncthreads();

        if (t + 1 < num_kv) kv_load(t + 1);

        const uint32_t sa = sbase + (uint32_t)(t & 1) * FS_STG;
        const uint32_t ka_h = sa + FS_KH + ka_rel;
        const uint32_t ka_l = sa + FS_KL + ka_rel;
        const uint32_t va_h = sa + FS_VH + va_rel;
        const uint32_t va_l = sa + FS_VL + va_rel;

        // ---- S = Q K^T ----
        float s[8][4];
        #pragma unroll
        for (int j = 0; j < 8; j++)
            #pragma unroll
            for (int r = 0; r < 4; r++) s[j][r] = 0.f;

        #pragma unroll
        for (int kc = 0; kc < 4; kc++) {
            uint32_t qfl4[4];
            ldsm_x4(qfl4, qla + kc * 32);
            #pragma unroll
            for (int np = 0; np < 4; np++) {
                uint32_t kh4[4], kl4[4];
                ldsm_x4(kh4, ka_h + np * (16 * KSTR * 2) + kc * 32);
                ldsm_x4(kl4, ka_l + np * (16 * KSTR * 2) + kc * 32);
                mma16816(s[2*np],   qfh[kc], kh4[0], kh4[1]);
                mma16816(s[2*np+1], qfh[kc], kh4[2], kh4[3]);
                mma16816(s[2*np],   qfl4,    kh4[0], kh4[1]);
                mma16816(s[2*np+1], qfl4,    kh4[2], kh4[3]);
                mma16816(s[2*np],   qfh[kc], kl4[0], kl4[1]);
                mma16816(s[2*np+1], qfh[kc], kl4[2], kl4[3]);
            }
        }

        // ---- causal mask ----
        if (t >= 2 * qtile) {
            #pragma unroll
            for (int j = 0; j < 8; j++) {
                int col = t * 64 + j * 8 + (lane & 3) * 2;
                #pragma unroll
                for (int r = 0; r < 4; r++) {
                    int cc = col + (r & 1);
                    int rw = row_a0 + ((r >= 2) ? 8 : 0);
                    if (cc > rw) s[j][r] = -1e30f;
                }
            }
        }

        // ---- online softmax ----
        float mx0 = -1e30f, mx1 = -1e30f;
        #pragma unroll
        for (int j = 0; j < 8; j++) {
            mx0 = fmaxf(mx0, fmaxf(s[j][0], s[j][1]));
            mx1 = fmaxf(mx1, fmaxf(s[j][2], s[j][3]));
        }
        mx0 = fmaxf(mx0, __shfl_xor_sync(0xffffffffu, mx0, 1));
        mx0 = fmaxf(mx0, __shfl_xor_sync(0xffffffffu, mx0, 2));
        mx1 = fmaxf(mx1, __shfl_xor_sync(0xffffffffu, mx1, 1));
        mx1 = fmaxf(mx1, __shfl_xor_sync(0xffffffffu, mx1, 2));
        float mn0 = fmaxf(m0, mx0), mn1 = fmaxf(m1, mx1);
        float sc0 = ex2f(m0 - mn0), sc1 = ex2f(m1 - mn1);
        m0 = mn0; m1 = mn1;
        l0 *= sc0; l1 *= sc1;
        #pragma unroll
        for (int j = 0; j < 8; j++) {
            o[j][0] *= sc0; o[j][1] *= sc0;
            o[j][2] *= sc1; o[j][3] *= sc1;
        }
        #pragma unroll
        for (int j = 0; j < 8; j++) {
            float p0 = ex2f(s[j][0] - mn0);
            float p1 = ex2f(s[j][1] - mn0);
            float p2 = ex2f(s[j][2] - mn1);
            float p3 = ex2f(s[j][3] - mn1);
            s[j][0] = p0; s[j][1] = p1; s[j][2] = p2; s[j][3] = p3;
            l0 += p0 + p1;
            l1 += p2 + p3;
        }

        // ---- O += P V ----
        #pragma unroll
        for (int kc = 0; kc < 4; kc++) {
            uint32_t aph[4], apl[4];
            #pragma unroll
            for (int t2 = 0; t2 < 2; t2++) {
                int j = 2 * kc + t2;
                __nv_bfloat16 h0 = __float2bfloat16_rn(s[j][0]);
                __nv_bfloat16 h1 = __float2bfloat16_rn(s[j][1]);
                __nv_bfloat16 h2 = __float2bfloat16_rn(s[j][2]);
                __nv_bfloat16 h3 = __float2bfloat16_rn(s[j][3]);
                aph[t2*2 + 0] = pack_bf2(h0, h1);
                aph[t2*2 + 1] = pack_bf2(h2, h3);
                apl[t2*2 + 0] = pack_bf2(
                    __float2bfloat16_rn(s[j][0] - __bfloat162float(h0)),
                    __float2bfloat16_rn(s[j][1] - __bfloat162float(h1)));
                apl[t2*2 + 1] = pack_bf2(
                    __float2bfloat16_rn(s[j][2] - __bfloat162float(h2)),
                    __float2bfloat16_rn(s[j][3] - __bfloat162float(h3)));
            }
            #pragma unroll
            for (int nb = 0; nb < 4; nb++) {
                uint32_t vh4[4], vl4[4];
                ldsm_x4_t(vh4, va_h + kc * (16 * KSTR * 2) + nb * 32);
                ldsm_x4_t(vl4, va_l + kc * (16 * KSTR * 2) + nb * 32);
                mma16816(o[2*nb],   aph, vh4[0], vh4[1]);
                mma16816(o[2*nb+1], aph, vh4[2], vh4[3]);
                mma16816(o[2*nb],   apl, vh4[0], vh4[1]);
                mma16816(o[2*nb+1], apl, vh4[2], vh4[3]);
                mma16816(o[2*nb],   aph, vl4[0], vl4[1]);
                mma16816(o[2*nb+1], aph, vl4[2], vl4[3]);
            }
        }
    }

    l0 += __shfl_xor_sync(0xffffffffu, l0, 1);
    l0 += __shfl_xor_sync(0xffffffffu, l0, 2);
    l1 += __shfl_xor_sync(0xffffffffu, l1, 1);
    l1 += __shfl_xor_sync(0xffffffffu, l1, 2);
    float inv0 = 1.f / l0, inv1 = 1.f / l1;

    size_t tok0 = (size_t)b * SS + row_a0;
    size_t o0 = tok0 * DD + h * HDD + (lane & 3) * 2;
    size_t o1 = o0 + (size_t)8 * DD;
    #pragma unroll
    for (int j = 0; j < 8; j++) {
        float v00 = o[j][0] * inv0, v01 = o[j][1] * inv0;
        float v10 = o[j][2] * inv1, v11 = o[j][3] * inv1;
        __nv_bfloat16 h00 = __float2bfloat16_rn(v00);
        __nv_bfloat16 h01 = __float2bfloat16_rn(v01);
        __nv_bfloat16 h10 = __float2bfloat16_rn(v10);
        __nv_bfloat16 h11 = __float2bfloat16_rn(v11);
        *reinterpret_cast<uint32_t*>(&yh[o0 + j * 8]) = pack_bf2(h00, h01);
        *reinterpret_cast<uint32_t*>(&yl[o0 + j * 8]) = pack_bf2(
            __float2bfloat16_rn(v00 - __bfloat162float(h00)),
            __float2bfloat16_rn(v01 - __bfloat162float(h01)));
        *reinterpret_cast<uint32_t*>(&yh[o1 + j * 8]) = pack_bf2(h10, h11);
        *reinterpret_cast<uint32_t*>(&yl[o1 + j * 8]) = pack_bf2(
            __float2bfloat16_rn(v10 - __bfloat162float(h10)),
            __float2bfloat16_rn(v11 - __bfloat162float(h11)));
    }
}

// ---------------------------------------------------------------------------
// Launch
// ---------------------------------------------------------------------------
extern "C" void kernel_launch(void* const* d_in, const int* in_sizes, int n_in,
                              void* d_out, int out_size)
{
    const float* x      = (const float*)d_in[0];
    const float* W_attn = (const float*)d_in[1];
    const float* b_attn = (const float*)d_in[2];
    const float* W_proj = (const float*)d_in[3];
    const float* b_proj = (const float*)d_in[4];
    float* out = (float*)d_out;

    static __nv_bfloat16 *xh = nullptr, *xl, *yh, *yl;
    static __nv_bfloat16 *wt_hi, *wt_lo, *wpt_hi, *wpt_lo;
    static __nv_bfloat16 *qh, *ql, *kh, *kl, *vh, *vl;
    if (!xh) {   // first (non-captured) correctness call
        cudaGetSymbolAddress((void**)&xh, g_xh);
        cudaGetSymbolAddress((void**)&xl, g_xl);
        cudaGetSymbolAddress((void**)&yh, g_yh);
        cudaGetSymbolAddress((void**)&yl, g_yl);
        cudaGetSymbolAddress((void**)&wt_hi,  g_wt_hi);
        cudaGetSymbolAddress((void**)&wt_lo,  g_wt_lo);
        cudaGetSymbolAddress((void**)&wpt_hi, g_wpt_hi);
        cudaGetSymbolAddress((void**)&wpt_lo, g_wpt_lo);
        cudaGetSymbolAddress((void**)&qh, g_qh);
        cudaGetSymbolAddress((void**)&ql, g_ql);
        cudaGetSymbolAddress((void**)&kh, g_kh);
        cudaGetSymbolAddress((void**)&kl, g_kl);
        cudaGetSymbolAddress((void**)&vh, g_vh);
        cudaGetSymbolAddress((void**)&vl, g_vl);
        cudaFuncSetAttribute(flash_attn_tc,
                             cudaFuncAttributeMaxDynamicSharedMemorySize,
                             FS_TOTAL);
        cudaFuncSetAttribute(tc_gemm_kernel<0>,
                             cudaFuncAttributeMaxDynamicSharedMemorySize,
                             GEMM_SMEM);
        cudaFuncSetAttribute(tc_gemm_kernel<1>,
                             cudaFuncAttributeMaxDynamicSharedMemorySize,
                             GEMM_SMEM);
    }

    // 0a) split x -> bf16 hi/lo
    split_kernel<<<(MTOK * DD) / (256 * 4), 256>>>(x, xh, xl);
    // 0b) transpose + split weights
    {
        dim3 g1(3 * DD / 32, DD / 32);
        transpose_split_kernel<<<g1, 256>>>(W_attn, wt_hi, wt_lo, DD, 3 * DD);
        dim3 g2(DD / 32, DD / 32);
        transpose_split_kernel<<<g2, 256>>>(W_proj, wpt_hi, wpt_lo, DD, DD);
    }

    // 1) QKV GEMM + fused split epilogue
    {
        dim3 grid(3 * DD / 128, MTOK / 128);
        tc_gemm_kernel<1><<<grid, 128, GEMM_SMEM>>>(
            xh, xl, wt_hi, wt_lo, b_attn, nullptr,
            qh, ql, kh, kl, vh, vl, MTOK, 3 * DD, DD);
    }

    // 2) tensor-core causal flash attention -> split bf16 y
    {
        dim3 grid(SS / 128, HH, BB);
        flash_attn_tc<<<grid, 256, FS_TOTAL>>>(qh, ql, kh, kl, vh, vl, yh, yl);
    }

    // 3) output projection -> out
    {
        dim3 grid(DD / 128, MTOK / 128);
        tc_gemm_kernel<0><<<grid, 128, GEMM_SMEM>>>(
            yh, yl, wpt_hi, wpt_lo, b_proj, out,
            nullptr, nullptr, nullptr, nullptr, nullptr, nullptr,
            MTOK, DD, DD);
    }
}

// round 9
// speedup vs baseline: 1.0971x; 1.0690x over previous
#include <cuda_runtime.h>
#include <cuda_bf16.h>
#include <cstdint>
#include <cstddef>

// Problem constants
#define BB  4
#define SS  2048
#define DD  1024
#define HH  16
#define HDD 64
#define MTOK (BB*SS)          // 8192 token rows

// q prescale: HD^-0.5 * log2(e)  (softmax done in exp2 domain)
#define QSC 0.18033688011112042f

// Scratch (device globals; no allocations allowed)
__device__ __align__(128) __nv_bfloat16 g_xh[(size_t)MTOK * DD];
__device__ __align__(128) __nv_bfloat16 g_xl[(size_t)MTOK * DD];
__device__ __align__(128) __nv_bfloat16 g_yh[(size_t)MTOK * DD];
__device__ __align__(128) __nv_bfloat16 g_yl[(size_t)MTOK * DD];
__device__ __align__(128) __nv_bfloat16 g_wt_hi [(size_t)3 * DD * DD];
__device__ __align__(128) __nv_bfloat16 g_wt_lo [(size_t)3 * DD * DD];
__device__ __align__(128) __nv_bfloat16 g_wpt_hi[(size_t)DD * DD];
__device__ __align__(128) __nv_bfloat16 g_wpt_lo[(size_t)DD * DD];
#define BHSZ ((size_t)BB * HH * SS * HDD)
__device__ __align__(128) __nv_bfloat16 g_qh[BHSZ], g_ql[BHSZ];
__device__ __align__(128) __nv_bfloat16 g_kh[BHSZ], g_kl[BHSZ];
__device__ __align__(128) __nv_bfloat16 g_vh[BHSZ], g_vl[BHSZ];

// ---------------------------------------------------------------------------
// Warp-MMA + async-copy helpers
// ---------------------------------------------------------------------------
__device__ __forceinline__ uint32_t smem_u32(const void* p) {
    uint32_t a;
    asm("{ .reg .u64 t; cvta.to.shared.u64 t, %1; cvt.u32.u64 %0, t; }"
        : "=r"(a) : "l"(p));
    return a;
}
__device__ __forceinline__ void ldsm_x4(uint32_t* r, uint32_t addr) {
    asm volatile("ldmatrix.sync.aligned.m8n8.x4.shared.b16 {%0,%1,%2,%3}, [%4];"
                 : "=r"(r[0]), "=r"(r[1]), "=r"(r[2]), "=r"(r[3]) : "r"(addr));
}
__device__ __forceinline__ void ldsm_x4_t(uint32_t* r, uint32_t addr) {
    asm volatile("ldmatrix.sync.aligned.m8n8.x4.trans.shared.b16 {%0,%1,%2,%3}, [%4];"
                 : "=r"(r[0]), "=r"(r[1]), "=r"(r[2]), "=r"(r[3]) : "r"(addr));
}
__device__ __forceinline__ void mma16816(float* d, const uint32_t* a,
                                         const uint32_t b0, const uint32_t b1) {
    asm volatile(
        "mma.sync.aligned.m16n8k16.row.col.f32.bf16.bf16.f32 "
        "{%0,%1,%2,%3}, {%4,%5,%6,%7}, {%8,%9}, {%0,%1,%2,%3};"
        : "+f"(d[0]), "+f"(d[1]), "+f"(d[2]), "+f"(d[3])
        : "r"(a[0]), "r"(a[1]), "r"(a[2]), "r"(a[3]), "r"(b0), "r"(b1));
}
__device__ __forceinline__ void cp_async16(uint32_t saddr, const void* g) {
    asm volatile("cp.async.cg.shared.global [%0], [%1], 16;"
                 :: "r"(saddr), "l"(g) : "memory");
}
#define CP_COMMIT() asm volatile("cp.async.commit_group;" ::: "memory")
#define CP_WAIT(n)  asm volatile("cp.async.wait_group %0;" :: "n"(n) : "memory")

__device__ __forceinline__ uint32_t pack_bf2(__nv_bfloat16 a, __nv_bfloat16 b) {
    __nv_bfloat162 t; t.x = a; t.y = b;
    return *reinterpret_cast<uint32_t*>(&t);
}
__device__ __forceinline__ float ex2f(float x) {
    float r;
    asm("ex2.approx.f32 %0, %1;" : "=f"(r) : "f"(x));
    return r;
}

#define TS16 24   // GEMM BK=16 row stride (elems): 48B rows, conflict-free ldsm
#define KSTR 72   // attention tile row stride (144B rows, conflict-free)

// ---------------------------------------------------------------------------
// Elementwise fp32 -> bf16 hi/lo split (for x)
// ---------------------------------------------------------------------------
__global__ __launch_bounds__(256)
void split_kernel(const float* __restrict__ in,
                  __nv_bfloat16* __restrict__ hi,
                  __nv_bfloat16* __restrict__ lo)
{
    size_t i = ((size_t)blockIdx.x * 256 + threadIdx.x) * 4;
    float4 v = *reinterpret_cast<const float4*>(in + i);
    __nv_bfloat16 h0 = __float2bfloat16_rn(v.x);
    __nv_bfloat16 h1 = __float2bfloat16_rn(v.y);
    __nv_bfloat16 h2 = __float2bfloat16_rn(v.z);
    __nv_bfloat16 h3 = __float2bfloat16_rn(v.w);
    uint2 hv, lv;
    hv.x = pack_bf2(h0, h1); hv.y = pack_bf2(h2, h3);
    lv.x = pack_bf2(__float2bfloat16_rn(v.x - __bfloat162float(h0)),
                    __float2bfloat16_rn(v.y - __bfloat162float(h1)));
    lv.y = pack_bf2(__float2bfloat16_rn(v.z - __bfloat162float(h2)),
                    __float2bfloat16_rn(v.w - __bfloat162float(h3)));
    *reinterpret_cast<uint2*>(hi + i) = hv;
    *reinterpret_cast<uint2*>(lo + i) = lv;
}

// ---------------------------------------------------------------------------
// Transpose + bf16 hi/lo split of weights:  W[K,N] fp32 -> Th/Tl[N,K] bf16
// ---------------------------------------------------------------------------
__global__ __launch_bounds__(256)
void transpose_split_kernel(const float* __restrict__ W,
                            __nv_bfloat16* __restrict__ Th,
                            __nv_bfloat16* __restrict__ Tl,
                            int K, int N)
{
    __shared__ float tile[32][33];
    const int n0 = blockIdx.x * 32;
    const int k0 = blockIdx.y * 32;
    const int tx = threadIdx.x & 31;
    const int ty4 = (threadIdx.x >> 5) * 4;

    #pragma unroll
    for (int j = 0; j < 4; j++)
        tile[ty4 + j][tx] = W[(size_t)(k0 + ty4 + j) * N + n0 + tx];
    __syncthreads();
    #pragma unroll
    for (int j = 0; j < 4; j++) {
        float v = tile[tx][ty4 + j];
        __nv_bfloat16 hi = __float2bfloat16_rn(v);
        __nv_bfloat16 lo = __float2bfloat16_rn(v - __bfloat162float(hi));
        size_t o = (size_t)(n0 + ty4 + j) * K + k0 + tx;
        Th[o] = hi;
        Tl[o] = lo;
    }
}

// ---------------------------------------------------------------------------
// Persistent tensor-core GEMM (bf16 hi/lo, fp32 accum):
// BM=128, BN=128, BK=16, 256 threads (8 warps, 64x32 warp tiles), 2 CTA/SM.
// Continuous 4-stage cp.async pipeline across tiles (CP_WAIT(2), one commit
// per chunk), copy issues interleaved between MMA passes.
// MODE 0: fp32 C.  MODE 1 (QKV): split bf16 q/k/v per-head buffers.
// ---------------------------------------------------------------------------
#define A16_BYTES (128 * TS16 * 2)       // 6144 per array
#define S16_AH 0
#define S16_AL (1 * A16_BYTES)
#define S16_BH (2 * A16_BYTES)
#define S16_BL (3 * A16_BYTES)
#define S16_STG (4 * A16_BYTES)          // 24576 per stage
#define GEMM_SMEM (4 * S16_STG)          // 98304 (4 stages)

template <int MODE>
__global__ __launch_bounds__(256, 2)
void tc_gemm_kernel(const __nv_bfloat16* __restrict__ Agh,
                    const __nv_bfloat16* __restrict__ Agl,
                    const __nv_bfloat16* __restrict__ Bgh,
                    const __nv_bfloat16* __restrict__ Bgl,
                    const float* __restrict__ bias,
                    float* __restrict__ C,
                    __nv_bfloat16* __restrict__ oqh, __nv_bfloat16* __restrict__ oql,
                    __nv_bfloat16* __restrict__ okh, __nv_bfloat16* __restrict__ okl,
                    __nv_bfloat16* __restrict__ ovh, __nv_bfloat16* __restrict__ ovl,
                    int M, int N, int K)
{
    extern __shared__ __align__(16) char gsm[];
    const uint32_t sb = smem_u32(gsm);

    const int tid  = threadIdx.x;
    const int lane = tid & 31;
    const int wid  = tid >> 5;              // 0..7
    const int bid  = blockIdx.x;
    const int G    = gridDim.x;

    const int NX      = N >> 7;             // tiles along N
    const int ntiles  = (M >> 7) * NX;
    const int nchunks = K >> 4;             // BK=16
    const int njobs   = (bid < ntiles) ? ((ntiles - bid + G - 1) / G) : 0;

    const int m_base = (wid >> 2) * 64;
    const int n_base = (wid & 3) * 32;

    // ldsm per-thread relative offsets (within a stage)
    const int a_r  = lane & 15;
    const int a_k  = (lane >> 4) * 8;
    const uint32_t ah_rel = S16_AH + ((m_base + a_r) * TS16 + a_k) * 2;
    const uint32_t al_rel = S16_AL + ((m_base + a_r) * TS16 + a_k) * 2;
    const int b_n  = (lane >> 4) * 8 + (lane & 7);
    const int b_k  = ((lane >> 3) & 1) * 8;
    const uint32_t bh_rel = S16_BH + ((n_base + b_n) * TS16 + b_k) * 2;
    const uint32_t bl_rel = S16_BL + ((n_base + b_n) * TS16 + b_k) * 2;

    // cp.async per-thread mapping: 1 chunk of 16B per array per BK-16 chunk
    const int cp_r  = tid >> 1;             // 0..127
    const int cp_k8 = (tid & 1) << 3;       // 0 / 8
    const uint32_t cp_sdo = (uint32_t)(cp_r * TS16 + cp_k8) * 2;

    // --- load-pointer state (tile jl, chunk lc, stage ls, tile coords) ---
    int lj = 0, lc = 0, ls = 0;
    int lby = 0, lbx = 0;
    if (njobs > 0) { int t = bid; lby = t / NX; lbx = t - lby * NX; }

    auto advance_load = [&]() {
        ls = (ls + 1) & 3;
        if (++lc == nchunks) {
            lc = 0; lj++;
            if (lj < njobs) {
                int t = bid + lj * G;
                lby = t / NX; lbx = t - lby * NX;
            }
        }
    };

    // prologue: issue chunks 0,1,2 (one commit each; empty if no work)
    #pragma unroll
    for (int i = 0; i < 3; i++) {
        if (lj < njobs) {
            const uint32_t so = sb + (uint32_t)ls * S16_STG;
            const size_t k0 = (size_t)(lc << 4);
            const size_t ga = (size_t)(lby * 128 + cp_r) * K + k0 + cp_k8;
            const size_t gb = (size_t)(lbx * 128 + cp_r) * K + k0 + cp_k8;
            cp_async16(so + S16_AH + cp_sdo, Agh + ga);
            cp_async16(so + S16_AL + cp_sdo, Agl + ga);
            cp_async16(so + S16_BH + cp_sdo, Bgh + gb);
            cp_async16(so + S16_BL + cp_sdo, Bgl + gb);
        }
        CP_COMMIT();
        advance_load();
    }

    int cs = 0;   // compute stage
    for (int j = 0; j < njobs; j++) {
        const int tile_id = bid + j * G;
        const int by = tile_id / NX;
        const int bx = tile_id - by * NX;
        const int brow = by * 128;
        const int bcol = bx * 128;

        float acc[4][4][4];
        #pragma unroll
        for (int i = 0; i < 4; i++)
            #pragma unroll
            for (int jj = 0; jj < 4; jj++)
                #pragma unroll
                for (int r = 0; r < 4; r++) acc[i][jj][r] = 0.f;

        for (int c = 0; c < nchunks; c++) {
            CP_WAIT(2);
            __syncthreads();      // stage cs holds chunk (j,c); loads visible

            // load-pointer coords for chunk +3 (issued interleaved below)
            const bool lvalid = (lj < njobs);
            const uint32_t so_l = sb + (uint32_t)ls * S16_STG;
            const size_t lk0 = (size_t)(lc << 4);
            const size_t lga = (size_t)(lby * 128 + cp_r) * K + lk0 + cp_k8;
            const size_t lgb = (size_t)(lbx * 128 + cp_r) * K + lk0 + cp_k8;

            const uint32_t so = sb + (uint32_t)cs * S16_STG;
            uint32_t ah[4][4], al[4][4], bh[2][4], bl[2][4];

            // pass 1: Ahi x Bhi
            #pragma unroll
            for (int mt = 0; mt < 4; mt++)
                ldsm_x4(ah[mt], so + ah_rel + mt * (16 * TS16 * 2));
            #pragma unroll
            for (int p = 0; p < 2; p++)
                ldsm_x4(bh[p], so + bh_rel + p * (16 * TS16 * 2));
            #pragma unroll
            for (int mt = 0; mt < 4; mt++)
                #pragma unroll
                for (int nt = 0; nt < 4; nt++) {
                    const int p = nt >> 1, hx = (nt & 1) * 2;
                    mma16816(acc[mt][nt], ah[mt], bh[p][hx], bh[p][hx + 1]);
                }
            // interleaved copy issue (A arrays)
            if (lvalid) {
                cp_async16(so_l + S16_AH + cp_sdo, Agh + lga);
                cp_async16(so_l + S16_AL + cp_sdo, Agl + lga);
            }

            // pass 2: Ahi x Blo
            #pragma unroll
            for (int p = 0; p < 2; p++)
                ldsm_x4(bl[p], so + bl_rel + p * (16 * TS16 * 2));
            #pragma unroll
            for (int mt = 0; mt < 4; mt++)
                #pragma unroll
                for (int nt = 0; nt < 4; nt++) {
                    const int p = nt >> 1, hx = (nt & 1) * 2;
                    mma16816(acc[mt][nt], ah[mt], bl[p][hx], bl[p][hx + 1]);
                }
            // interleaved copy issue (B arrays)
            if (lvalid) {
                cp_async16(so_l + S16_BH + cp_sdo, Bgh + lgb);
                cp_async16(so_l + S16_BL + cp_sdo, Bgl + lgb);
            }

            // pass 3: Alo x Bhi
            #pragma unroll
            for (int mt = 0; mt < 4; mt++)
                ldsm_x4(al[mt], so + al_rel + mt * (16 * TS16 * 2));
            #pragma unroll
            for (int mt = 0; mt < 4; mt++)
                #pragma unroll
                for (int nt = 0; nt < 4; nt++) {
                    const int p = nt >> 1, hx = (nt & 1) * 2;
                    mma16816(acc[mt][nt], al[mt], bh[p][hx], bh[p][hx + 1]);
                }

            CP_COMMIT();          // exactly one group per chunk (may be empty)
            advance_load();
            cs = (cs + 1) & 3;
        }

        // --- epilogue for this tile (registers + global only; no smem) ---
        #pragma unroll
        for (int nt = 0; nt < 4; nt++) {
            const int ncol = bcol + n_base + nt * 8 + (lane & 3) * 2;
            float2 bv = *reinterpret_cast<const float2*>(&bias[ncol]);
            if (MODE == 0) {
                #pragma unroll
                for (int mt = 0; mt < 4; mt++) {
                    int row0 = brow + m_base + mt * 16 + (lane >> 2);
                    float2 v0, v1;
                    v0.x = acc[mt][nt][0] + bv.x;  v0.y = acc[mt][nt][1] + bv.y;
                    v1.x = acc[mt][nt][2] + bv.x;  v1.y = acc[mt][nt][3] + bv.y;
                    *reinterpret_cast<float2*>(&C[(size_t)row0 * N + ncol]) = v0;
                    *reinterpret_cast<float2*>(&C[(size_t)(row0 + 8) * N + ncol]) = v1;
                }
            } else {
                const int region = ncol >> 10;
                const int hh = (ncol >> 6) & (HH - 1);
                const int dd = ncol & (HDD - 1);
                __nv_bfloat16* oh = (region == 0) ? oqh : (region == 1) ? okh : ovh;
                __nv_bfloat16* ol = (region == 0) ? oql : (region == 1) ? okl : ovl;
                const float sc = (region == 0) ? QSC : 1.f;
                const size_t colbase = (size_t)hh * (SS * HDD) + dd;
                #pragma unroll
                for (int mt = 0; mt < 4; mt++) {
                    int row0 = brow + m_base + mt * 16 + (lane >> 2);
                    #pragma unroll
                    for (int rr = 0; rr < 2; rr++) {
                        int row = row0 + rr * 8;
                        float v0 = (acc[mt][nt][rr * 2 + 0] + bv.x) * sc;
                        float v1 = (acc[mt][nt][rr * 2 + 1] + bv.y) * sc;
                        __nv_bfloat16 h0 = __float2bfloat16_rn(v0);
                        __nv_bfloat16 h1 = __float2bfloat16_rn(v1);
                        __nv_bfloat16 l0 = __float2bfloat16_rn(v0 - __bfloat162float(h0));
                        __nv_bfloat16 l1 = __float2bfloat16_rn(v1 - __bfloat162float(h1));
                        int bb = row >> 11, ss = row & (SS - 1);
                        size_t off = (size_t)bb * HH * SS * HDD + colbase + (size_t)ss * HDD;
                        *reinterpret_cast<uint32_t*>(&oh[off]) = pack_bf2(h0, h1);
                        *reinterpret_cast<uint32_t*>(&ol[off]) = pack_bf2(l0, l1);
                    }
                }
            }
        }
    }
}

// ---------------------------------------------------------------------------
// Tensor-core causal flash attention: BM=128 (8 warps, 256 threads),
// cp.async 2-stage K/V ring (64 keys/tile), Q-lo in dedicated smem. (as R8)
// ---------------------------------------------------------------------------
#define FS_KH   0
#define FS_KL   9216
#define FS_VH   18432
#define FS_VL   27648
#define FS_STG  36864
#define FS_QL   (2 * FS_STG)           // 73728
#define FS_TOTAL (FS_QL + 18432)       // 92160

__global__ __launch_bounds__(256, 2)
void flash_attn_tc(const __nv_bfloat16* __restrict__ Qh, const __nv_bfloat16* __restrict__ Ql,
                   const __nv_bfloat16* __restrict__ Kh, const __nv_bfloat16* __restrict__ Kl,
                   const __nv_bfloat16* __restrict__ Vh, const __nv_bfloat16* __restrict__ Vl,
                   __nv_bfloat16* __restrict__ yh, __nv_bfloat16* __restrict__ yl)
{
    extern __shared__ __align__(16) char sm[];
    const uint32_t sbase = smem_u32(sm);

    const int tid  = threadIdx.x;
    const int lane = tid & 31;
    const int w    = tid >> 5;
    const int qtile = (gridDim.x - 1) - blockIdx.x;
    const int h = blockIdx.y;
    const int b = blockIdx.z;
    const size_t base = ((size_t)(b * HH + h)) * SS * HDD;

    {
        const int s0 = qtile * 128;
        #pragma unroll
        for (int i = 0; i < 4; i++) {
            int idx = i * 256 + tid;
            int r  = idx >> 3;
            int c8 = (idx & 7) * 8;
            uint32_t so = (uint32_t)(r * KSTR + c8) * 2;
            size_t g = base + (size_t)(s0 + r) * HDD + c8;
            *reinterpret_cast<uint4*>(sm + so) =
                *reinterpret_cast<const uint4*>(&Qh[g]);
            *reinterpret_cast<uint4*>(sm + FS_QL + so) =
                *reinterpret_cast<const uint4*>(&Ql[g]);
        }
    }
    __syncthreads();

    uint32_t qfh[4][4];
    const uint32_t q_rel = ((w * 16 + (lane & 15)) * KSTR + (lane >> 4) * 8) * 2;
    {
        const uint32_t qa = sbase + q_rel;
        #pragma unroll
        for (int kc = 0; kc < 4; kc++) ldsm_x4(qfh[kc], qa + kc * 32);
    }
    __syncthreads();
    const uint32_t qla = sbase + FS_QL + q_rel;

    const uint32_t ka_rel = (((lane >> 4) * 8 + (lane & 7)) * KSTR +
                             ((lane >> 3) & 1) * 8) * 2;
    const uint32_t va_rel = ((((lane >> 3) & 1) * 8 + (lane & 7)) * KSTR +
                             ((lane >> 4) & 1) * 8) * 2;

    float o[8][4];
    #pragma unroll
    for (int j = 0; j < 8; j++)
        #pragma unroll
        for (int r = 0; r < 4; r++) o[j][r] = 0.f;
    float m0 = -1e30f, m1 = -1e30f, l0 = 0.f, l1 = 0.f;

    const int row_a0 = qtile * 128 + w * 16 + (lane >> 2);
    const int num_kv = 2 * qtile + 2;

    auto kv_load = [&](int t) {
        const uint32_t sa = sbase + (uint32_t)(t & 1) * FS_STG;
        const size_t gb = base + (size_t)t * 64 * HDD;
        #pragma unroll
        for (int ii = 0; ii < 2; ii++) {
            int j  = ii * 256 + tid;
            int r  = j >> 3;
            int c8 = (j & 7) * 8;
            size_t g = gb + (size_t)r * HDD + c8;
            uint32_t s_ = (uint32_t)(r * KSTR + c8) * 2;
            cp_async16(sa + FS_KH + s_, Kh + g);
            cp_async16(sa + FS_KL + s_, Kl + g);
            cp_async16(sa + FS_VH + s_, Vh + g);
            cp_async16(sa + FS_VL + s_, Vl + g);
        }
        CP_COMMIT();
    };

    kv_load(0);

    for (int t = 0; t < num_kv; t++) {
        CP_WAIT(0);
        __syncthreads();

        if (t + 1 < num_kv) kv_load(t + 1);

        const uint32_t sa = sbase + (uint32_t)(t & 1) * FS_STG;
        const uint32_t ka_h = sa + FS_KH + ka_rel;
        const uint32_t ka_l = sa + FS_KL + ka_rel;
        const uint32_t va_h = sa + FS_VH + va_rel;
        const uint32_t va_l = sa + FS_VL + va_rel;

        float s[8][4];
        #pragma unroll
        for (int j = 0; j < 8; j++)
            #pragma unroll
            for (int r = 0; r < 4; r++) s[j][r] = 0.f;

        #pragma unroll
        for (int kc = 0; kc < 4; kc++) {
            uint32_t qfl4[4];
            ldsm_x4(qfl4, qla + kc * 32);
            #pragma unroll
            for (int np = 0; np < 4; np++) {
                uint32_t kh4[4], kl4[4];
                ldsm_x4(kh4, ka_h + np * (16 * KSTR * 2) + kc * 32);
                ldsm_x4(kl4, ka_l + np * (16 * KSTR * 2) + kc * 32);
                mma16816(s[2*np],   qfh[kc], kh4[0], kh4[1]);
                mma16816(s[2*np+1], qfh[kc], kh4[2], kh4[3]);
                mma16816(s[2*np],   qfl4,    kh4[0], kh4[1]);
                mma16816(s[2*np+1], qfl4,    kh4[2], kh4[3]);
                mma16816(s[2*np],   qfh[kc], kl4[0], kl4[1]);
                mma16816(s[2*np+1], qfh[kc], kl4[2], kl4[3]);
            }
        }

        if (t >= 2 * qtile) {
            #pragma unroll
            for (int j = 0; j < 8; j++) {
                int col = t * 64 + j * 8 + (lane & 3) * 2;
                #pragma unroll
                for (int r = 0; r < 4; r++) {
                    int cc = col + (r & 1);
                    int rw = row_a0 + ((r >= 2) ? 8 : 0);
                    if (cc > rw) s[j][r] = -1e30f;
                }
            }
        }

        float mx0 = -1e30f, mx1 = -1e30f;
        #pragma unroll
        for (int j = 0; j < 8; j++) {
            mx0 = fmaxf(mx0, fmaxf(s[j][0], s[j][1]));
            mx1 = fmaxf(mx1, fmaxf(s[j][2], s[j][3]));
        }
        mx0 = fmaxf(mx0, __shfl_xor_sync(0xffffffffu, mx0, 1));
        mx0 = fmaxf(mx0, __shfl_xor_sync(0xffffffffu, mx0, 2));
        mx1 = fmaxf(mx1, __shfl_xor_sync(0xffffffffu, mx1, 1));
        mx1 = fmaxf(mx1, __shfl_xor_sync(0xffffffffu, mx1, 2));
        float mn0 = fmaxf(m0, mx0), mn1 = fmaxf(m1, mx1);
        float sc0 = ex2f(m0 - mn0), sc1 = ex2f(m1 - mn1);
        m0 = mn0; m1 = mn1;
        l0 *= sc0; l1 *= sc1;
        #pragma unroll
        for (int j = 0; j < 8; j++) {
            o[j][0] *= sc0; o[j][1] *= sc0;
            o[j][2] *= sc1; o[j][3] *= sc1;
        }
        #pragma unroll
        for (int j = 0; j < 8; j++) {
            float p0 = ex2f(s[j][0] - mn0);
            float p1 = ex2f(s[j][1] - mn0);
            float p2 = ex2f(s[j][2] - mn1);
            float p3 = ex2f(s[j][3] - mn1);
            s[j][0] = p0; s[j][1] = p1; s[j][2] = p2; s[j][3] = p3;
            l0 += p0 + p1;
            l1 += p2 + p3;
        }

        #pragma unroll
        for (int kc = 0; kc < 4; kc++) {
            uint32_t aph[4], apl[4];
            #pragma unroll
            for (int t2 = 0; t2 < 2; t2++) {
                int j = 2 * kc + t2;
                __nv_bfloat16 h0 = __float2bfloat16_rn(s[j][0]);
                __nv_bfloat16 h1 = __float2bfloat16_rn(s[j][1]);
                __nv_bfloat16 h2 = __float2bfloat16_rn(s[j][2]);
                __nv_bfloat16 h3 = __float2bfloat16_rn(s[j][3]);
                aph[t2*2 + 0] = pack_bf2(h0, h1);
                aph[t2*2 + 1] = pack_bf2(h2, h3);
                apl[t2*2 + 0] = pack_bf2(
                    __float2bfloat16_rn(s[j][0] - __bfloat162float(h0)),
                    __float2bfloat16_rn(s[j][1] - __bfloat162float(h1)));
                apl[t2*2 + 1] = pack_bf2(
                    __float2bfloat16_rn(s[j][2] - __bfloat162float(h2)),
                    __float2bfloat16_rn(s[j][3] - __bfloat162float(h3)));
            }
            #pragma unroll
            for (int nb = 0; nb < 4; nb++) {
                uint32_t vh4[4], vl4[4];
                ldsm_x4_t(vh4, va_h + kc * (16 * KSTR * 2) + nb * 32);
                ldsm_x4_t(vl4, va_l + kc * (16 * KSTR * 2) + nb * 32);
                mma16816(o[2*nb],   aph, vh4[0], vh4[1]);
                mma16816(o[2*nb+1], aph, vh4[2], vh4[3]);
                mma16816(o[2*nb],   apl, vh4[0], vh4[1]);
                mma16816(o[2*nb+1], apl, vh4[2], vh4[3]);
                mma16816(o[2*nb],   aph, vl4[0], vl4[1]);
                mma16816(o[2*nb+1], aph, vl4[2], vl4[3]);
            }
        }
    }

    l0 += __shfl_xor_sync(0xffffffffu, l0, 1);
    l0 += __shfl_xor_sync(0xffffffffu, l0, 2);
    l1 += __shfl_xor_sync(0xffffffffu, l1, 1);
    l1 += __shfl_xor_sync(0xffffffffu, l1, 2);
    float inv0 = 1.f / l0, inv1 = 1.f / l1;

    size_t tok0 = (size_t)b * SS + row_a0;
    size_t o0 = tok0 * DD + h * HDD + (lane & 3) * 2;
    size_t o1 = o0 + (size_t)8 * DD;
    #pragma unroll
    for (int j = 0; j < 8; j++) {
        float v00 = o[j][0] * inv0, v01 = o[j][1] * inv0;
        float v10 = o[j][2] * inv1, v11 = o[j][3] * inv1;
        __nv_bfloat16 h00 = __float2bfloat16_rn(v00);
        __nv_bfloat16 h01 = __float2bfloat16_rn(v01);
        __nv_bfloat16 h10 = __float2bfloat16_rn(v10);
        __nv_bfloat16 h11 = __float2bfloat16_rn(v11);
        *reinterpret_cast<uint32_t*>(&yh[o0 + j * 8]) = pack_bf2(h00, h01);
        *reinterpret_cast<uint32_t*>(&yl[o0 + j * 8]) = pack_bf2(
            __float2bfloat16_rn(v00 - __bfloat162float(h00)),
            __float2bfloat16_rn(v01 - __bfloat162float(h01)));
        *reinterpret_cast<uint32_t*>(&yh[o1 + j * 8]) = pack_bf2(h10, h11);
        *reinterpret_cast<uint32_t*>(&yl[o1 + j * 8]) = pack_bf2(
            __float2bfloat16_rn(v10 - __bfloat162float(h10)),
            __float2bfloat16_rn(v11 - __bfloat162float(h11)));
    }
}

// ---------------------------------------------------------------------------
// Launch
// ---------------------------------------------------------------------------
extern "C" void kernel_launch(void* const* d_in, const int* in_sizes, int n_in,
                              void* d_out, int out_size)
{
    const float* x      = (const float*)d_in[0];
    const float* W_attn = (const float*)d_in[1];
    const float* b_attn = (const float*)d_in[2];
    const float* W_proj = (const float*)d_in[3];
    const float* b_proj = (const float*)d_in[4];
    float* out = (float*)d_out;

    static __nv_bfloat16 *xh = nullptr, *xl, *yh, *yl;
    static __nv_bfloat16 *wt_hi, *wt_lo, *wpt_hi, *wpt_lo;
    static __nv_bfloat16 *qh, *ql, *kh, *kl, *vh, *vl;
    static int gemm_grid = 0;
    if (!xh) {   // first (non-captured) correctness call
        cudaGetSymbolAddress((void**)&xh, g_xh);
        cudaGetSymbolAddress((void**)&xl, g_xl);
        cudaGetSymbolAddress((void**)&yh, g_yh);
        cudaGetSymbolAddress((void**)&yl, g_yl);
        cudaGetSymbolAddress((void**)&wt_hi,  g_wt_hi);
        cudaGetSymbolAddress((void**)&wt_lo,  g_wt_lo);
        cudaGetSymbolAddress((void**)&wpt_hi, g_wpt_hi);
        cudaGetSymbolAddress((void**)&wpt_lo, g_wpt_lo);
        cudaGetSymbolAddress((void**)&qh, g_qh);
        cudaGetSymbolAddress((void**)&ql, g_ql);
        cudaGetSymbolAddress((void**)&kh, g_kh);
        cudaGetSymbolAddress((void**)&kl, g_kl);
        cudaGetSymbolAddress((void**)&vh, g_vh);
        cudaGetSymbolAddress((void**)&vl, g_vl);
        cudaFuncSetAttribute(flash_attn_tc,
                             cudaFuncAttributeMaxDynamicSharedMemorySize,
                             FS_TOTAL);
        cudaFuncSetAttribute(tc_gemm_kernel<0>,
                             cudaFuncAttributeMaxDynamicSharedMemorySize,
                             GEMM_SMEM);
        cudaFuncSetAttribute(tc_gemm_kernel<1>,
                             cudaFuncAttributeMaxDynamicSharedMemorySize,
                             GEMM_SMEM);
        cudaDeviceProp prop;
        cudaGetDeviceProperties(&prop, 0);
        gemm_grid = prop.multiProcessorCount * 2;   // persistent: 2 CTAs/SM
    }

    // 0a) split x -> bf16 hi/lo
    split_kernel<<<(MTOK * DD) / (256 * 4), 256>>>(x, xh, xl);
    // 0b) transpose + split weights
    {
        dim3 g1(3 * DD / 32, DD / 32);
        transpose_split_kernel<<<g1, 256>>>(W_attn, wt_hi, wt_lo, DD, 3 * DD);
        dim3 g2(DD / 32, DD / 32);
        transpose_split_kernel<<<g2, 256>>>(W_proj, wpt_hi, wpt_lo, DD, DD);
    }

    // 1) QKV GEMM (persistent) + fused split epilogue
    tc_gemm_kernel<1><<<gemm_grid, 256, GEMM_SMEM>>>(
        xh, xl, wt_hi, wt_lo, b_attn, nullptr,
        qh, ql, kh, kl, vh, vl, MTOK, 3 * DD, DD);

    // 2) tensor-core causal flash attention -> split bf16 y
    {
        dim3 grid(SS / 128, HH, BB);
        flash_attn_tc<<<grid, 256, FS_TOTAL>>>(qh, ql, kh, kl, vh, vl, yh, yl);
    }

    // 3) output projection (persistent) -> out
    tc_gemm_kernel<0><<<gemm_grid, 256, GEMM_SMEM>>>(
        yh, yl, wpt_hi, wpt_lo, b_proj, out,
        nullptr, nullptr, nullptr, nullptr, nullptr, nullptr,
        MTOK, DD, DD);
}

// round 10
// speedup vs baseline: 1.1218x; 1.0226x over previous
#include <cuda_runtime.h>
#include <cuda_bf16.h>
#include <cstdint>
#include <cstddef>

// Problem constants
#define BB  4
#define SS  2048
#define DD  1024
#define HH  16
#define HDD 64
#define MTOK (BB*SS)          // 8192 token rows

// q prescale: HD^-0.5 * log2(e)  (softmax done in exp2 domain)
#define QSC 0.18033688011112042f

// Scratch (device globals; no allocations allowed)
__device__ __align__(128) __nv_bfloat16 g_xh[(size_t)MTOK * DD];
__device__ __align__(128) __nv_bfloat16 g_xl[(size_t)MTOK * DD];
__device__ __align__(128) __nv_bfloat16 g_yh[(size_t)MTOK * DD];
__device__ __align__(128) __nv_bfloat16 g_yl[(size_t)MTOK * DD];
__device__ __align__(128) __nv_bfloat16 g_wt_hi [(size_t)3 * DD * DD];
__device__ __align__(128) __nv_bfloat16 g_wt_lo [(size_t)3 * DD * DD];
__device__ __align__(128) __nv_bfloat16 g_wpt_hi[(size_t)DD * DD];
__device__ __align__(128) __nv_bfloat16 g_wpt_lo[(size_t)DD * DD];
#define BHSZ ((size_t)BB * HH * SS * HDD)
__device__ __align__(128) __nv_bfloat16 g_qh[BHSZ], g_ql[BHSZ];
__device__ __align__(128) __nv_bfloat16 g_kh[BHSZ], g_kl[BHSZ];
__device__ __align__(128) __nv_bfloat16 g_vh[BHSZ], g_vl[BHSZ];

// ---------------------------------------------------------------------------
// Warp-MMA + async-copy helpers
// ---------------------------------------------------------------------------
__device__ __forceinline__ uint32_t smem_u32(const void* p) {
    uint32_t a;
    asm("{ .reg .u64 t; cvta.to.shared.u64 t, %1; cvt.u32.u64 %0, t; }"
        : "=r"(a) : "l"(p));
    return a;
}
__device__ __forceinline__ void ldsm_x4(uint32_t* r, uint32_t addr) {
    asm volatile("ldmatrix.sync.aligned.m8n8.x4.shared.b16 {%0,%1,%2,%3}, [%4];"
                 : "=r"(r[0]), "=r"(r[1]), "=r"(r[2]), "=r"(r[3]) : "r"(addr));
}
__device__ __forceinline__ void ldsm_x4_t(uint32_t* r, uint32_t addr) {
    asm volatile("ldmatrix.sync.aligned.m8n8.x4.trans.shared.b16 {%0,%1,%2,%3}, [%4];"
                 : "=r"(r[0]), "=r"(r[1]), "=r"(r[2]), "=r"(r[3]) : "r"(addr));
}
__device__ __forceinline__ void mma16816(float* d, const uint32_t* a,
                                         const uint32_t b0, const uint32_t b1) {
    asm volatile(
        "mma.sync.aligned.m16n8k16.row.col.f32.bf16.bf16.f32 "
        "{%0,%1,%2,%3}, {%4,%5,%6,%7}, {%8,%9}, {%0,%1,%2,%3};"
        : "+f"(d[0]), "+f"(d[1]), "+f"(d[2]), "+f"(d[3])
        : "r"(a[0]), "r"(a[1]), "r"(a[2]), "r"(a[3]), "r"(b0), "r"(b1));
}
__device__ __forceinline__ void cp_async16(uint32_t saddr, const void* g) {
    asm volatile("cp.async.cg.shared.global [%0], [%1], 16;"
                 :: "r"(saddr), "l"(g) : "memory");
}
#define CP_COMMIT() asm volatile("cp.async.commit_group;" ::: "memory")
#define CP_WAIT(n)  asm volatile("cp.async.wait_group %0;" :: "n"(n) : "memory")

__device__ __forceinline__ uint32_t pack_bf2(__nv_bfloat16 a, __nv_bfloat16 b) {
    __nv_bfloat162 t; t.x = a; t.y = b;
    return *reinterpret_cast<uint32_t*>(&t);
}
// packed f32x2 -> bf16x2 (lo = a, hi = b)
__device__ __forceinline__ uint32_t cvt_bf2(float a, float b) {
    uint32_t r;
    asm("cvt.rn.bf16x2.f32 %0, %1, %2;" : "=r"(r) : "f"(b), "f"(a));
    return r;
}
__device__ __forceinline__ float ex2f(float x) {
    float r;
    asm("ex2.approx.f32 %0, %1;" : "=f"(r) : "f"(x));
    return r;
}

#define TS16 24   // GEMM BK=16 row stride (elems): 48B rows, conflict-free ldsm
#define KSTR 72   // attention tile row stride (144B rows, conflict-free)

// ---------------------------------------------------------------------------
// Elementwise fp32 -> bf16 hi/lo split (for x)
// ---------------------------------------------------------------------------
__global__ __launch_bounds__(256)
void split_kernel(const float* __restrict__ in,
                  __nv_bfloat16* __restrict__ hi,
                  __nv_bfloat16* __restrict__ lo)
{
    size_t i = ((size_t)blockIdx.x * 256 + threadIdx.x) * 4;
    float4 v = *reinterpret_cast<const float4*>(in + i);
    uint32_t h01 = cvt_bf2(v.x, v.y);
    uint32_t h23 = cvt_bf2(v.z, v.w);
    float r0 = __uint_as_float(h01 << 16);
    float r1 = __uint_as_float(h01 & 0xffff0000u);
    float r2 = __uint_as_float(h23 << 16);
    float r3 = __uint_as_float(h23 & 0xffff0000u);
    uint2 hv, lv;
    hv.x = h01; hv.y = h23;
    lv.x = cvt_bf2(v.x - r0, v.y - r1);
    lv.y = cvt_bf2(v.z - r2, v.w - r3);
    *reinterpret_cast<uint2*>(hi + i) = hv;
    *reinterpret_cast<uint2*>(lo + i) = lv;
}

// ---------------------------------------------------------------------------
// Transpose + bf16 hi/lo split of weights:  W[K,N] fp32 -> Th/Tl[N,K] bf16
// ---------------------------------------------------------------------------
__global__ __launch_bounds__(256)
void transpose_split_kernel(const float* __restrict__ W,
                            __nv_bfloat16* __restrict__ Th,
                            __nv_bfloat16* __restrict__ Tl,
                            int K, int N)
{
    __shared__ float tile[32][33];
    const int n0 = blockIdx.x * 32;
    const int k0 = blockIdx.y * 32;
    const int tx = threadIdx.x & 31;
    const int ty4 = (threadIdx.x >> 5) * 4;

    #pragma unroll
    for (int j = 0; j < 4; j++)
        tile[ty4 + j][tx] = W[(size_t)(k0 + ty4 + j) * N + n0 + tx];
    __syncthreads();
    #pragma unroll
    for (int j = 0; j < 4; j++) {
        float v = tile[tx][ty4 + j];
        __nv_bfloat16 hi = __float2bfloat16_rn(v);
        __nv_bfloat16 lo = __float2bfloat16_rn(v - __bfloat162float(hi));
        size_t o = (size_t)(n0 + ty4 + j) * K + k0 + tx;
        Th[o] = hi;
        Tl[o] = lo;
    }
}

// ---------------------------------------------------------------------------
// Persistent tensor-core GEMM (bf16 hi/lo, fp32 accum):
// BM=128, BN=128, BK=16, 256 threads (8 warps, 64x32 warp tiles), 2 CTA/SM.
// 4-stage continuous pipeline; __syncthreads every 2 chunks (pair barrier);
// incremental 32-bit global offsets; copies interleaved between MMA passes.
// MODE 0: fp32 C.  MODE 1 (QKV): split bf16 q/k/v per-head buffers.
// ---------------------------------------------------------------------------
#define A16_BYTES (128 * TS16 * 2)       // 6144 per array
#define S16_AH 0
#define S16_AL (1 * A16_BYTES)
#define S16_BH (2 * A16_BYTES)
#define S16_BL (3 * A16_BYTES)
#define S16_STG (4 * A16_BYTES)          // 24576 per stage
#define GEMM_SMEM (4 * S16_STG)          // 98304 (4 stages)

template <int MODE>
__global__ __launch_bounds__(256, 2)
void tc_gemm_kernel(const __nv_bfloat16* __restrict__ Agh,
                    const __nv_bfloat16* __restrict__ Agl,
                    const __nv_bfloat16* __restrict__ Bgh,
                    const __nv_bfloat16* __restrict__ Bgl,
                    const float* __restrict__ bias,
                    float* __restrict__ C,
                    __nv_bfloat16* __restrict__ oqh, __nv_bfloat16* __restrict__ oql,
                    __nv_bfloat16* __restrict__ okh, __nv_bfloat16* __restrict__ okl,
                    __nv_bfloat16* __restrict__ ovh, __nv_bfloat16* __restrict__ ovl,
                    int M, int N, int K)
{
    extern __shared__ __align__(16) char gsm[];
    const uint32_t sb = smem_u32(gsm);

    const int tid  = threadIdx.x;
    const int lane = tid & 31;
    const int wid  = tid >> 5;              // 0..7
    const int bid  = blockIdx.x;
    const int G    = gridDim.x;

    const int NX      = N >> 7;             // tiles along N
    const int ntiles  = (M >> 7) * NX;
    const int nchunks = K >> 4;             // BK=16 (even count)
    const int njobs   = (bid < ntiles) ? ((ntiles - bid + G - 1) / G) : 0;

    const int m_base = (wid >> 2) * 64;
    const int n_base = (wid & 3) * 32;

    // ldsm per-thread relative offsets (within a stage)
    const int a_r  = lane & 15;
    const int a_k  = (lane >> 4) * 8;
    const uint32_t ah_rel = S16_AH + ((m_base + a_r) * TS16 + a_k) * 2;
    const uint32_t al_rel = S16_AL + ((m_base + a_r) * TS16 + a_k) * 2;
    const int b_n  = (lane >> 4) * 8 + (lane & 7);
    const int b_k  = ((lane >> 3) & 1) * 8;
    const uint32_t bh_rel = S16_BH + ((n_base + b_n) * TS16 + b_k) * 2;
    const uint32_t bl_rel = S16_BL + ((n_base + b_n) * TS16 + b_k) * 2;

    // cp.async per-thread mapping: 1 chunk of 16B per array per BK-16 chunk
    const int cp_r  = tid >> 1;             // 0..127
    const int cp_k8 = (tid & 1) << 3;       // 0 / 8
    const uint32_t cp_sdo = (uint32_t)(cp_r * TS16 + cp_k8) * 2;

    // --- load-pointer state: tile lj, chunk lc, stage ls, incremental offs ---
    int lj = 0, lc = 0, ls = 0;
    uint32_t goA = 0, goB = 0;              // 32-bit element offsets
    if (njobs > 0) {
        int t = bid;
        int lby = t / NX, lbx = t - lby * NX;
        goA = (uint32_t)(lby * 128 + cp_r) * (uint32_t)K + cp_k8;
        goB = (uint32_t)(lbx * 128 + cp_r) * (uint32_t)K + cp_k8;
    }

    auto advance_load = [&]() {
        ls = (ls + 1) & 3;
        if (++lc == nchunks) {
            lc = 0; lj++;
            if (lj < njobs) {
                int t = bid + lj * G;
                int lby = t / NX, lbx = t - lby * NX;
                goA = (uint32_t)(lby * 128 + cp_r) * (uint32_t)K + cp_k8;
                goB = (uint32_t)(lbx * 128 + cp_r) * (uint32_t)K + cp_k8;
            }
        } else {
            goA += 16; goB += 16;
        }
    };

    // prologue: issue chunks 0,1 (one commit each; empty if no work)
    #pragma unroll
    for (int i = 0; i < 2; i++) {
        if (lj < njobs) {
            const uint32_t so = sb + (uint32_t)ls * S16_STG;
            cp_async16(so + S16_AH + cp_sdo, Agh + goA);
            cp_async16(so + S16_AL + cp_sdo, Agl + goA);
            cp_async16(so + S16_BH + cp_sdo, Bgh + goB);
            cp_async16(so + S16_BL + cp_sdo, Bgl + goB);
        }
        CP_COMMIT();
        advance_load();
    }

    int cs = 0;   // compute stage
    for (int j = 0; j < njobs; j++) {
        const int tile_id = bid + j * G;
        const int by = tile_id / NX;
        const int bx = tile_id - by * NX;
        const int brow = by * 128;
        const int bcol = bx * 128;

        float acc[4][4][4];
        #pragma unroll
        for (int i = 0; i < 4; i++)
            #pragma unroll
            for (int jj = 0; jj < 4; jj++)
                #pragma unroll
                for (int r = 0; r < 4; r++) acc[i][jj][r] = 0.f;

        for (int cpair = 0; cpair < nchunks; cpair += 2) {
            CP_WAIT(0);
            __syncthreads();      // both chunks of this pair resident

            #pragma unroll
            for (int u = 0; u < 2; u++) {
                // snapshot load coords for chunk +2
                const bool lvalid = (lj < njobs);
                const uint32_t so_l = sb + (uint32_t)ls * S16_STG;
                const uint32_t lga = goA, lgb = goB;

                const uint32_t so = sb + (uint32_t)cs * S16_STG;
                uint32_t ah[4][4], al[4][4], bh[2][4], bl[2][4];

                // pass 1: Ahi x Bhi
                #pragma unroll
                for (int mt = 0; mt < 4; mt++)
                    ldsm_x4(ah[mt], so + ah_rel + mt * (16 * TS16 * 2));
                #pragma unroll
                for (int p = 0; p < 2; p++)
                    ldsm_x4(bh[p], so + bh_rel + p * (16 * TS16 * 2));
                #pragma unroll
                for (int mt = 0; mt < 4; mt++)
                    #pragma unroll
                    for (int nt = 0; nt < 4; nt++) {
                        const int p = nt >> 1, hx = (nt & 1) * 2;
                        mma16816(acc[mt][nt], ah[mt], bh[p][hx], bh[p][hx + 1]);
                    }
                if (lvalid) {
                    cp_async16(so_l + S16_AH + cp_sdo, Agh + lga);
                    cp_async16(so_l + S16_AL + cp_sdo, Agl + lga);
                }

                // pass 2: Ahi x Blo
                #pragma unroll
                for (int p = 0; p < 2; p++)
                    ldsm_x4(bl[p], so + bl_rel + p * (16 * TS16 * 2));
                #pragma unroll
                for (int mt = 0; mt < 4; mt++)
                    #pragma unroll
                    for (int nt = 0; nt < 4; nt++) {
                        const int p = nt >> 1, hx = (nt & 1) * 2;
                        mma16816(acc[mt][nt], ah[mt], bl[p][hx], bl[p][hx + 1]);
                    }
                if (lvalid) {
                    cp_async16(so_l + S16_BH + cp_sdo, Bgh + lgb);
                    cp_async16(so_l + S16_BL + cp_sdo, Bgl + lgb);
                }

                // pass 3: Alo x Bhi
                #pragma unroll
                for (int mt = 0; mt < 4; mt++)
                    ldsm_x4(al[mt], so + al_rel + mt * (16 * TS16 * 2));
                #pragma unroll
                for (int mt = 0; mt < 4; mt++)
                    #pragma unroll
                    for (int nt = 0; nt < 4; nt++) {
                        const int p = nt >> 1, hx = (nt & 1) * 2;
                        mma16816(acc[mt][nt], al[mt], bh[p][hx], bh[p][hx + 1]);
                    }

                CP_COMMIT();       // one group per chunk (may be empty)
                advance_load();
                cs = (cs + 1) & 3;
            }
        }

        // --- epilogue for this tile (registers + global only; no smem) ---
        #pragma unroll
        for (int nt = 0; nt < 4; nt++) {
            const int ncol = bcol + n_base + nt * 8 + (lane & 3) * 2;
            float2 bv = *reinterpret_cast<const float2*>(&bias[ncol]);
            if (MODE == 0) {
                #pragma unroll
                for (int mt = 0; mt < 4; mt++) {
                    int row0 = brow + m_base + mt * 16 + (lane >> 2);
                    float2 v0, v1;
                    v0.x = acc[mt][nt][0] + bv.x;  v0.y = acc[mt][nt][1] + bv.y;
                    v1.x = acc[mt][nt][2] + bv.x;  v1.y = acc[mt][nt][3] + bv.y;
                    *reinterpret_cast<float2*>(&C[(size_t)row0 * N + ncol]) = v0;
                    *reinterpret_cast<float2*>(&C[(size_t)(row0 + 8) * N + ncol]) = v1;
                }
            } else {
                const int region = ncol >> 10;
                const int hh = (ncol >> 6) & (HH - 1);
                const int dd = ncol & (HDD - 1);
                __nv_bfloat16* oh = (region == 0) ? oqh : (region == 1) ? okh : ovh;
                __nv_bfloat16* ol = (region == 0) ? oql : (region == 1) ? okl : ovl;
                const float sc = (region == 0) ? QSC : 1.f;
                const size_t colbase = (size_t)hh * (SS * HDD) + dd;
                #pragma unroll
                for (int mt = 0; mt < 4; mt++) {
                    int row0 = brow + m_base + mt * 16 + (lane >> 2);
                    #pragma unroll
                    for (int rr = 0; rr < 2; rr++) {
                        int row = row0 + rr * 8;
                        float v0 = (acc[mt][nt][rr * 2 + 0] + bv.x) * sc;
                        float v1 = (acc[mt][nt][rr * 2 + 1] + bv.y) * sc;
                        uint32_t hp = cvt_bf2(v0, v1);
                        float r0 = __uint_as_float(hp << 16);
                        float r1 = __uint_as_float(hp & 0xffff0000u);
                        uint32_t lp = cvt_bf2(v0 - r0, v1 - r1);
                        int bb = row >> 11, ss = row & (SS - 1);
                        size_t off = (size_t)bb * HH * SS * HDD + colbase + (size_t)ss * HDD;
                        *reinterpret_cast<uint32_t*>(&oh[off]) = hp;
                        *reinterpret_cast<uint32_t*>(&ol[off]) = lp;
                    }
                }
            }
        }
    }
}

// ---------------------------------------------------------------------------
// Tensor-core causal flash attention: BM=128 (8 warps, 256 threads),
// cp.async 2-stage K/V ring (64 keys/tile), Q-lo in dedicated smem.
// Copies for tile t+1 interleaved inside the S-MMA loop; packed-cvt P split.
// ---------------------------------------------------------------------------
#define FS_KH   0
#define FS_KL   9216
#define FS_VH   18432
#define FS_VL   27648
#define FS_STG  36864
#define FS_QL   (2 * FS_STG)           // 73728
#define FS_TOTAL (FS_QL + 18432)       // 92160

__global__ __launch_bounds__(256, 2)
void flash_attn_tc(const __nv_bfloat16* __restrict__ Qh, const __nv_bfloat16* __restrict__ Ql,
                   const __nv_bfloat16* __restrict__ Kh, const __nv_bfloat16* __restrict__ Kl,
                   const __nv_bfloat16* __restrict__ Vh, const __nv_bfloat16* __restrict__ Vl,
                   __nv_bfloat16* __restrict__ yh, __nv_bfloat16* __restrict__ yl)
{
    extern __shared__ __align__(16) char sm[];
    const uint32_t sbase = smem_u32(sm);

    const int tid  = threadIdx.x;
    const int lane = tid & 31;
    const int w    = tid >> 5;
    const int qtile = (gridDim.x - 1) - blockIdx.x;
    const int h = blockIdx.y;
    const int b = blockIdx.z;
    const size_t base = ((size_t)(b * HH + h)) * SS * HDD;

    {
        const int s0 = qtile * 128;
        #pragma unroll
        for (int i = 0; i < 4; i++) {
            int idx = i * 256 + tid;
            int r  = idx >> 3;
            int c8 = (idx & 7) * 8;
            uint32_t so = (uint32_t)(r * KSTR + c8) * 2;
            size_t g = base + (size_t)(s0 + r) * HDD + c8;
            *reinterpret_cast<uint4*>(sm + so) =
                *reinterpret_cast<const uint4*>(&Qh[g]);
            *reinterpret_cast<uint4*>(sm + FS_QL + so) =
                *reinterpret_cast<const uint4*>(&Ql[g]);
        }
    }
    __syncthreads();

    uint32_t qfh[4][4];
    const uint32_t q_rel = ((w * 16 + (lane & 15)) * KSTR + (lane >> 4) * 8) * 2;
    {
        const uint32_t qa = sbase + q_rel;
        #pragma unroll
        for (int kc = 0; kc < 4; kc++) ldsm_x4(qfh[kc], qa + kc * 32);
    }
    __syncthreads();
    const uint32_t qla = sbase + FS_QL + q_rel;

    const uint32_t ka_rel = (((lane >> 4) * 8 + (lane & 7)) * KSTR +
                             ((lane >> 3) & 1) * 8) * 2;
    const uint32_t va_rel = ((((lane >> 3) & 1) * 8 + (lane & 7)) * KSTR +
                             ((lane >> 4) & 1) * 8) * 2;

    // per-thread copy mapping (2 x 16B per array per tile)
    int cg_r[2], cg_c8[2]; uint32_t cg_so[2];
    #pragma unroll
    for (int ii = 0; ii < 2; ii++) {
        int j  = ii * 256 + tid;
        cg_r[ii]  = j >> 3;
        cg_c8[ii] = (j & 7) * 8;
        cg_so[ii] = (uint32_t)(cg_r[ii] * KSTR + cg_c8[ii]) * 2;
    }

    float o[8][4];
    #pragma unroll
    for (int j = 0; j < 8; j++)
        #pragma unroll
        for (int r = 0; r < 4; r++) o[j][r] = 0.f;
    float m0 = -1e30f, m1 = -1e30f, l0 = 0.f, l1 = 0.f;

    const int row_a0 = qtile * 128 + w * 16 + (lane >> 2);
    const int num_kv = 2 * qtile + 2;

    // prologue: tile 0 into stage 0
    {
        const uint32_t sa = sbase;
        #pragma unroll
        for (int ii = 0; ii < 2; ii++) {
            size_t g = base + (size_t)cg_r[ii] * HDD + cg_c8[ii];
            cp_async16(sa + FS_KH + cg_so[ii], Kh + g);
            cp_async16(sa + FS_KL + cg_so[ii], Kl + g);
            cp_async16(sa + FS_VH + cg_so[ii], Vh + g);
            cp_async16(sa + FS_VL + cg_so[ii], Vl + g);
        }
        CP_COMMIT();
    }

    for (int t = 0; t < num_kv; t++) {
        CP_WAIT(0);
        __syncthreads();

        const bool pre = (t + 1 < num_kv);
        const uint32_t sa_n = sbase + (uint32_t)((t + 1) & 1) * FS_STG;
        const size_t gb_n = base + (size_t)(t + 1) * 64 * HDD;

        const uint32_t sa = sbase + (uint32_t)(t & 1) * FS_STG;
        const uint32_t ka_h = sa + FS_KH + ka_rel;
        const uint32_t ka_l = sa + FS_KL + ka_rel;
        const uint32_t va_h = sa + FS_VH + va_rel;
        const uint32_t va_l = sa + FS_VL + va_rel;

        float s[8][4];
        #pragma unroll
        for (int j = 0; j < 8; j++)
            #pragma unroll
            for (int r = 0; r < 4; r++) s[j][r] = 0.f;

        #pragma unroll
        for (int kc = 0; kc < 4; kc++) {
            uint32_t qfl4[4];
            ldsm_x4(qfl4, qla + kc * 32);
            #pragma unroll
            for (int np = 0; np < 4; np++) {
                uint32_t kh4[4], kl4[4];
                ldsm_x4(kh4, ka_h + np * (16 * KSTR * 2) + kc * 32);
                ldsm_x4(kl4, ka_l + np * (16 * KSTR * 2) + kc * 32);
                mma16816(s[2*np],   qfh[kc], kh4[0], kh4[1]);
                mma16816(s[2*np+1], qfh[kc], kh4[2], kh4[3]);
                mma16816(s[2*np],   qfl4,    kh4[0], kh4[1]);
                mma16816(s[2*np+1], qfl4,    kh4[2], kh4[3]);
                mma16816(s[2*np],   qfh[kc], kl4[0], kl4[1]);
                mma16816(s[2*np+1], qfh[kc], kl4[2], kl4[3]);
            }
            // interleaved prefetch of tile t+1 (K half at kc==0, V at kc==2)
            if (kc == 0 && pre) {
                #pragma unroll
                for (int ii = 0; ii < 2; ii++) {
                    size_t g = gb_n + (size_t)cg_r[ii] * HDD + cg_c8[ii];
                    cp_async16(sa_n + FS_KH + cg_so[ii], Kh + g);
                    cp_async16(sa_n + FS_KL + cg_so[ii], Kl + g);
                }
            }
            if (kc == 2 && pre) {
                #pragma unroll
                for (int ii = 0; ii < 2; ii++) {
                    size_t g = gb_n + (size_t)cg_r[ii] * HDD + cg_c8[ii];
                    cp_async16(sa_n + FS_VH + cg_so[ii], Vh + g);
                    cp_async16(sa_n + FS_VL + cg_so[ii], Vl + g);
                }
            }
        }
        CP_COMMIT();

        if (t >= 2 * qtile) {
            #pragma unroll
            for (int j = 0; j < 8; j++) {
                int col = t * 64 + j * 8 + (lane & 3) * 2;
                #pragma unroll
                for (int r = 0; r < 4; r++) {
                    int cc = col + (r & 1);
                    int rw = row_a0 + ((r >= 2) ? 8 : 0);
                    if (cc > rw) s[j][r] = -1e30f;
                }
            }
        }

        float mx0 = -1e30f, mx1 = -1e30f;
        #pragma unroll
        for (int j = 0; j < 8; j++) {
            mx0 = fmaxf(mx0, fmaxf(s[j][0], s[j][1]));
            mx1 = fmaxf(mx1, fmaxf(s[j][2], s[j][3]));
        }
        mx0 = fmaxf(mx0, __shfl_xor_sync(0xffffffffu, mx0, 1));
        mx0 = fmaxf(mx0, __shfl_xor_sync(0xffffffffu, mx0, 2));
        mx1 = fmaxf(mx1, __shfl_xor_sync(0xffffffffu, mx1, 1));
        mx1 = fmaxf(mx1, __shfl_xor_sync(0xffffffffu, mx1, 2));
        float mn0 = fmaxf(m0, mx0), mn1 = fmaxf(m1, mx1);
        float sc0 = ex2f(m0 - mn0), sc1 = ex2f(m1 - mn1);
        m0 = mn0; m1 = mn1;
        l0 *= sc0; l1 *= sc1;
        #pragma unroll
        for (int j = 0; j < 8; j++) {
            o[j][0] *= sc0; o[j][1] *= sc0;
            o[j][2] *= sc1; o[j][3] *= sc1;
        }
        #pragma unroll
        for (int j = 0; j < 8; j++) {
            float p0 = ex2f(s[j][0] - mn0);
            float p1 = ex2f(s[j][1] - mn0);
            float p2 = ex2f(s[j][2] - mn1);
            float p3 = ex2f(s[j][3] - mn1);
            s[j][0] = p0; s[j][1] = p1; s[j][2] = p2; s[j][3] = p3;
            l0 += p0 + p1;
            l1 += p2 + p3;
        }

        // ---- O += P V (packed-cvt hi/lo split of P) ----
        #pragma unroll
        for (int kc = 0; kc < 4; kc++) {
            uint32_t aph[4], apl[4];
            #pragma unroll
            for (int t2 = 0; t2 < 2; t2++) {
                int j = 2 * kc + t2;
                uint32_t h01 = cvt_bf2(s[j][0], s[j][1]);
                uint32_t h23 = cvt_bf2(s[j][2], s[j][3]);
                aph[t2*2 + 0] = h01;
                aph[t2*2 + 1] = h23;
                float r0 = __uint_as_float(h01 << 16);
                float r1 = __uint_as_float(h01 & 0xffff0000u);
                float r2 = __uint_as_float(h23 << 16);
                float r3 = __uint_as_float(h23 & 0xffff0000u);
                apl[t2*2 + 0] = cvt_bf2(s[j][0] - r0, s[j][1] - r1);
                apl[t2*2 + 1] = cvt_bf2(s[j][2] - r2, s[j][3] - r3);
            }
            #pragma unroll
            for (int nb = 0; nb < 4; nb++) {
                uint32_t vh4[4], vl4[4];
                ldsm_x4_t(vh4, va_h + kc * (16 * KSTR * 2) + nb * 32);
                ldsm_x4_t(vl4, va_l + kc * (16 * KSTR * 2) + nb * 32);
                mma16816(o[2*nb],   aph, vh4[0], vh4[1]);
                mma16816(o[2*nb+1], aph, vh4[2], vh4[3]);
                mma16816(o[2*nb],   apl, vh4[0], vh4[1]);
                mma16816(o[2*nb+1], apl, vh4[2], vh4[3]);
                mma16816(o[2*nb],   aph, vl4[0], vl4[1]);
                mma16816(o[2*nb+1], aph, vl4[2], vl4[3]);
            }
        }
    }

    l0 += __shfl_xor_sync(0xffffffffu, l0, 1);
    l0 += __shfl_xor_sync(0xffffffffu, l0, 2);
    l1 += __shfl_xor_sync(0xffffffffu, l1, 1);
    l1 += __shfl_xor_sync(0xffffffffu, l1, 2);
    float inv0 = 1.f / l0, inv1 = 1.f / l1;

    size_t tok0 = (size_t)b * SS + row_a0;
    size_t o0 = tok0 * DD + h * HDD + (lane & 3) * 2;
    size_t o1 = o0 + (size_t)8 * DD;
    #pragma unroll
    for (int j = 0; j < 8; j++) {
        float v00 = o[j][0] * inv0, v01 = o[j][1] * inv0;
        float v10 = o[j][2] * inv1, v11 = o[j][3] * inv1;
        uint32_t hA = cvt_bf2(v00, v01);
        uint32_t hB = cvt_bf2(v10, v11);
        float rA0 = __uint_as_float(hA << 16);
        float rA1 = __uint_as_float(hA & 0xffff0000u);
        float rB0 = __uint_as_float(hB << 16);
        float rB1 = __uint_as_float(hB & 0xffff0000u);
        *reinterpret_cast<uint32_t*>(&yh[o0 + j * 8]) = hA;
        *reinterpret_cast<uint32_t*>(&yl[o0 + j * 8]) = cvt_bf2(v00 - rA0, v01 - rA1);
        *reinterpret_cast<uint32_t*>(&yh[o1 + j * 8]) = hB;
        *reinterpret_cast<uint32_t*>(&yl[o1 + j * 8]) = cvt_bf2(v10 - rB0, v11 - rB1);
    }
}

// ---------------------------------------------------------------------------
// Launch
// ---------------------------------------------------------------------------
extern "C" void kernel_launch(void* const* d_in, const int* in_sizes, int n_in,
                              void* d_out, int out_size)
{
    const float* x      = (const float*)d_in[0];
    const float* W_attn = (const float*)d_in[1];
    const float* b_attn = (const float*)d_in[2];
    const float* W_proj = (const float*)d_in[3];
    const float* b_proj = (const float*)d_in[4];
    float* out = (float*)d_out;

    static __nv_bfloat16 *xh = nullptr, *xl, *yh, *yl;
    static __nv_bfloat16 *wt_hi, *wt_lo, *wpt_hi, *wpt_lo;
    static __nv_bfloat16 *qh, *ql, *kh, *kl, *vh, *vl;
    static int gemm_grid = 0;
    if (!xh) {   // first (non-captured) correctness call
        cudaGetSymbolAddress((void**)&xh, g_xh);
        cudaGetSymbolAddress((void**)&xl, g_xl);
        cudaGetSymbolAddress((void**)&yh, g_yh);
        cudaGetSymbolAddress((void**)&yl, g_yl);
        cudaGetSymbolAddress((void**)&wt_hi,  g_wt_hi);
        cudaGetSymbolAddress((void**)&wt_lo,  g_wt_lo);
        cudaGetSymbolAddress((void**)&wpt_hi, g_wpt_hi);
        cudaGetSymbolAddress((void**)&wpt_lo, g_wpt_lo);
        cudaGetSymbolAddress((void**)&qh, g_qh);
        cudaGetSymbolAddress((void**)&ql, g_ql);
        cudaGetSymbolAddress((void**)&kh, g_kh);
        cudaGetSymbolAddress((void**)&kl, g_kl);
        cudaGetSymbolAddress((void**)&vh, g_vh);
        cudaGetSymbolAddress((void**)&vl, g_vl);
        cudaFuncSetAttribute(flash_attn_tc,
                             cudaFuncAttributeMaxDynamicSharedMemorySize,
                             FS_TOTAL);
        cudaFuncSetAttribute(tc_gemm_kernel<0>,
                             cudaFuncAttributeMaxDynamicSharedMemorySize,
                             GEMM_SMEM);
        cudaFuncSetAttribute(tc_gemm_kernel<1>,
                             cudaFuncAttributeMaxDynamicSharedMemorySize,
                             GEMM_SMEM);
        cudaDeviceProp prop;
        cudaGetDeviceProperties(&prop, 0);
        gemm_grid = prop.multiProcessorCount * 2;   // persistent: 2 CTAs/SM
    }

    // 0a) split x -> bf16 hi/lo
    split_kernel<<<(MTOK * DD) / (256 * 4), 256>>>(x, xh, xl);
    // 0b) transpose + split weights
    {
        dim3 g1(3 * DD / 32, DD / 32);
        transpose_split_kernel<<<g1, 256>>>(W_attn, wt_hi, wt_lo, DD, 3 * DD);
        dim3 g2(DD / 32, DD / 32);
        transpose_split_kernel<<<g2, 256>>>(W_proj, wpt_hi, wpt_lo, DD, DD);
    }

    // 1) QKV GEMM (persistent) + fused split epilogue
    tc_gemm_kernel<1><<<gemm_grid, 256, GEMM_SMEM>>>(
        xh, xl, wt_hi, wt_lo, b_attn, nullptr,
        qh, ql, kh, kl, vh, vl, MTOK, 3 * DD, DD);

    // 2) tensor-core causal flash attention -> split bf16 y
    {
        dim3 grid(SS / 128, HH, BB);
        flash_attn_tc<<<grid, 256, FS_TOTAL>>>(qh, ql, kh, kl, vh, vl, yh, yl);
    }

    // 3) output projection (persistent) -> out
    tc_gemm_kernel<0><<<gemm_grid, 256, GEMM_SMEM>>>(
        yh, yl, wpt_hi, wpt_lo, b_proj, out,
        nullptr, nullptr, nullptr, nullptr, nullptr, nullptr,
        MTOK, DD, DD);
}

// round 11
// speedup vs baseline: 1.3514x; 1.2047x over previous
#include <cuda_runtime.h>
#include <cuda_bf16.h>
#include <cuda_fp16.h>
#include <cstdint>
#include <cstddef>

// Problem constants
#define BB  4
#define SS  2048
#define DD  1024
#define HH  16
#define HDD 64
#define MTOK (BB*SS)          // 8192 token rows

// q prescale: HD^-0.5 * log2(e)  (softmax done in exp2 domain)
#define QSC 0.18033688011112042f

// Scratch (device globals; no allocations allowed)
__device__ __align__(128) __half g_xf[(size_t)MTOK * DD];            // x fp16
__device__ __align__(128) __half g_yf[(size_t)MTOK * DD];            // attn out fp16
__device__ __align__(128) __half g_wt_hi [(size_t)3 * DD * DD];      // W_attn^T fp16 hi
__device__ __align__(128) __half g_wt_lo [(size_t)3 * DD * DD];      // W_attn^T fp16 lo
__device__ __align__(128) __half g_wpt_hi[(size_t)DD * DD];
__device__ __align__(128) __half g_wpt_lo[(size_t)DD * DD];
#define BHSZ ((size_t)BB * HH * SS * HDD)
__device__ __align__(128) __nv_bfloat16 g_qh[BHSZ], g_ql[BHSZ];
__device__ __align__(128) __nv_bfloat16 g_kh[BHSZ], g_kl[BHSZ];
__device__ __align__(128) __nv_bfloat16 g_vh[BHSZ], g_vl[BHSZ];

// ---------------------------------------------------------------------------
// Warp-MMA + async-copy helpers
// ---------------------------------------------------------------------------
__device__ __forceinline__ uint32_t smem_u32(const void* p) {
    uint32_t a;
    asm("{ .reg .u64 t; cvta.to.shared.u64 t, %1; cvt.u32.u64 %0, t; }"
        : "=r"(a) : "l"(p));
    return a;
}
__device__ __forceinline__ void ldsm_x4(uint32_t* r, uint32_t addr) {
    asm volatile("ldmatrix.sync.aligned.m8n8.x4.shared.b16 {%0,%1,%2,%3}, [%4];"
                 : "=r"(r[0]), "=r"(r[1]), "=r"(r[2]), "=r"(r[3]) : "r"(addr));
}
__device__ __forceinline__ void ldsm_x4_t(uint32_t* r, uint32_t addr) {
    asm volatile("ldmatrix.sync.aligned.m8n8.x4.trans.shared.b16 {%0,%1,%2,%3}, [%4];"
                 : "=r"(r[0]), "=r"(r[1]), "=r"(r[2]), "=r"(r[3]) : "r"(addr));
}
// bf16 mma (attention)
__device__ __forceinline__ void mma16816(float* d, const uint32_t* a,
                                         const uint32_t b0, const uint32_t b1) {
    asm volatile(
        "mma.sync.aligned.m16n8k16.row.col.f32.bf16.bf16.f32 "
        "{%0,%1,%2,%3}, {%4,%5,%6,%7}, {%8,%9}, {%0,%1,%2,%3};"
        : "+f"(d[0]), "+f"(d[1]), "+f"(d[2]), "+f"(d[3])
        : "r"(a[0]), "r"(a[1]), "r"(a[2]), "r"(a[3]), "r"(b0), "r"(b1));
}
// fp16 mma (GEMMs)
__device__ __forceinline__ void mma16816h(float* d, const uint32_t* a,
                                          const uint32_t b0, const uint32_t b1) {
    asm volatile(
        "mma.sync.aligned.m16n8k16.row.col.f32.f16.f16.f32 "
        "{%0,%1,%2,%3}, {%4,%5,%6,%7}, {%8,%9}, {%0,%1,%2,%3};"
        : "+f"(d[0]), "+f"(d[1]), "+f"(d[2]), "+f"(d[3])
        : "r"(a[0]), "r"(a[1]), "r"(a[2]), "r"(a[3]), "r"(b0), "r"(b1));
}
__device__ __forceinline__ void cp_async16(uint32_t saddr, const void* g) {
    asm volatile("cp.async.cg.shared.global [%0], [%1], 16;"
                 :: "r"(saddr), "l"(g) : "memory");
}
#define CP_COMMIT() asm volatile("cp.async.commit_group;" ::: "memory")
#define CP_WAIT(n)  asm volatile("cp.async.wait_group %0;" :: "n"(n) : "memory")

// packed f32x2 -> bf16x2 (lo = a, hi = b)
__device__ __forceinline__ uint32_t cvt_bf2(float a, float b) {
    uint32_t r;
    asm("cvt.rn.bf16x2.f32 %0, %1, %2;" : "=r"(r) : "f"(b), "f"(a));
    return r;
}
// packed f32x2 -> f16x2 (lo = a, hi = b)
__device__ __forceinline__ uint32_t cvt_h2(float a, float b) {
    uint32_t r;
    asm("cvt.rn.f16x2.f32 %0, %1, %2;" : "=r"(r) : "f"(b), "f"(a));
    return r;
}
__device__ __forceinline__ float ex2f(float x) {
    float r;
    asm("ex2.approx.f32 %0, %1;" : "=f"(r) : "f"(x));
    return r;
}

#define TS16 24   // GEMM BK=16 row stride (elems): 48B rows, conflict-free ldsm
#define KSTR 72   // attention tile row stride (144B rows, conflict-free)

// ---------------------------------------------------------------------------
// Elementwise fp32 -> fp16 convert (for x)
// ---------------------------------------------------------------------------
__global__ __launch_bounds__(256)
void convert_f16_kernel(const float* __restrict__ in, __half* __restrict__ of)
{
    size_t i = ((size_t)blockIdx.x * 256 + threadIdx.x) * 4;
    float4 v = *reinterpret_cast<const float4*>(in + i);
    uint2 hv;
    hv.x = cvt_h2(v.x, v.y);
    hv.y = cvt_h2(v.z, v.w);
    *reinterpret_cast<uint2*>(of + i) = hv;
}

// ---------------------------------------------------------------------------
// Transpose + fp16 hi/lo split of weights:  W[K,N] fp32 -> Th/Tl[N,K] fp16
// ---------------------------------------------------------------------------
__global__ __launch_bounds__(256)
void transpose_split_kernel(const float* __restrict__ W,
                            __half* __restrict__ Th,
                            __half* __restrict__ Tl,
                            int K, int N)
{
    __shared__ float tile[32][33];
    const int n0 = blockIdx.x * 32;
    const int k0 = blockIdx.y * 32;
    const int tx = threadIdx.x & 31;
    const int ty4 = (threadIdx.x >> 5) * 4;

    #pragma unroll
    for (int j = 0; j < 4; j++)
        tile[ty4 + j][tx] = W[(size_t)(k0 + ty4 + j) * N + n0 + tx];
    __syncthreads();
    #pragma unroll
    for (int j = 0; j < 4; j++) {
        float v = tile[tx][ty4 + j];
        __half hi = __float2half_rn(v);
        __half lo = __float2half_rn(v - __half2float(hi));
        size_t o = (size_t)(n0 + ty4 + j) * K + k0 + tx;
        Th[o] = hi;
        Tl[o] = lo;
    }
}

// ---------------------------------------------------------------------------
// Persistent tensor-core GEMM, fp16 2-pass (A single fp16, B = Bh+Bl fp16):
// BM=128, BN=128, BK=16, 256 threads (8 warps, 64x32 warp tiles), 2 CTA/SM.
// 4-stage continuous pipeline; pair barrier; incremental 32-bit offsets.
// MODE 0: fp32 C.  MODE 1 (QKV): split bf16 q/k/v per-head buffers.
// ---------------------------------------------------------------------------
#define A16_BYTES (128 * TS16 * 2)       // 6144 per array
#define S16_AF 0
#define S16_BH (1 * A16_BYTES)
#define S16_BL (2 * A16_BYTES)
#define S16_STG (3 * A16_BYTES)          // 18432 per stage
#define GEMM_SMEM (4 * S16_STG)          // 73728 (4 stages)

template <int MODE>
__global__ __launch_bounds__(256, 2)
void tc_gemm_kernel(const __half* __restrict__ Agf,
                    const __half* __restrict__ Bgh,
                    const __half* __restrict__ Bgl,
                    const float* __restrict__ bias,
                    float* __restrict__ C,
                    __nv_bfloat16* __restrict__ oqh, __nv_bfloat16* __restrict__ oql,
                    __nv_bfloat16* __restrict__ okh, __nv_bfloat16* __restrict__ okl,
                    __nv_bfloat16* __restrict__ ovh, __nv_bfloat16* __restrict__ ovl,
                    int M, int N, int K)
{
    extern __shared__ __align__(16) char gsm[];
    const uint32_t sb = smem_u32(gsm);

    const int tid  = threadIdx.x;
    const int lane = tid & 31;
    const int wid  = tid >> 5;              // 0..7
    const int bid  = blockIdx.x;
    const int G    = gridDim.x;

    const int NX      = N >> 7;
    const int ntiles  = (M >> 7) * NX;
    const int nchunks = K >> 4;             // BK=16 (even)
    const int njobs   = (bid < ntiles) ? ((ntiles - bid + G - 1) / G) : 0;

    const int m_base = (wid >> 2) * 64;
    const int n_base = (wid & 3) * 32;

    const int a_r  = lane & 15;
    const int a_k  = (lane >> 4) * 8;
    const uint32_t af_rel = S16_AF + ((m_base + a_r) * TS16 + a_k) * 2;
    const int b_n  = (lane >> 4) * 8 + (lane & 7);
    const int b_k  = ((lane >> 3) & 1) * 8;
    const uint32_t bh_rel = S16_BH + ((n_base + b_n) * TS16 + b_k) * 2;
    const uint32_t bl_rel = S16_BL + ((n_base + b_n) * TS16 + b_k) * 2;

    // cp.async per-thread mapping: 1 x 16B per array per BK-16 chunk
    const int cp_r  = tid >> 1;             // 0..127
    const int cp_k8 = (tid & 1) << 3;       // 0 / 8
    const uint32_t cp_sdo = (uint32_t)(cp_r * TS16 + cp_k8) * 2;

    int lj = 0, lc = 0, ls = 0;
    uint32_t goA = 0, goB = 0;
    if (njobs > 0) {
        int t = bid;
        int lby = t / NX, lbx = t - lby * NX;
        goA = (uint32_t)(lby * 128 + cp_r) * (uint32_t)K + cp_k8;
        goB = (uint32_t)(lbx * 128 + cp_r) * (uint32_t)K + cp_k8;
    }

    auto advance_load = [&]() {
        ls = (ls + 1) & 3;
        if (++lc == nchunks) {
            lc = 0; lj++;
            if (lj < njobs) {
                int t = bid + lj * G;
                int lby = t / NX, lbx = t - lby * NX;
                goA = (uint32_t)(lby * 128 + cp_r) * (uint32_t)K + cp_k8;
                goB = (uint32_t)(lbx * 128 + cp_r) * (uint32_t)K + cp_k8;
            }
        } else {
            goA += 16; goB += 16;
        }
    };

    // prologue: chunks 0,1
    #pragma unroll
    for (int i = 0; i < 2; i++) {
        if (lj < njobs) {
            const uint32_t so = sb + (uint32_t)ls * S16_STG;
            cp_async16(so + S16_AF + cp_sdo, Agf + goA);
            cp_async16(so + S16_BH + cp_sdo, Bgh + goB);
            cp_async16(so + S16_BL + cp_sdo, Bgl + goB);
        }
        CP_COMMIT();
        advance_load();
    }

    int cs = 0;
    for (int j = 0; j < njobs; j++) {
        const int tile_id = bid + j * G;
        const int by = tile_id / NX;
        const int bx = tile_id - by * NX;
        const int brow = by * 128;
        const int bcol = bx * 128;

        float acc[4][4][4];
        #pragma unroll
        for (int i = 0; i < 4; i++)
            #pragma unroll
            for (int jj = 0; jj < 4; jj++)
                #pragma unroll
                for (int r = 0; r < 4; r++) acc[i][jj][r] = 0.f;

        for (int cpair = 0; cpair < nchunks; cpair += 2) {
            CP_WAIT(0);
            __syncthreads();

            #pragma unroll
            for (int u = 0; u < 2; u++) {
                const bool lvalid = (lj < njobs);
                const uint32_t so_l = sb + (uint32_t)ls * S16_STG;
                const uint32_t lga = goA, lgb = goB;

                const uint32_t so = sb + (uint32_t)cs * S16_STG;
                uint32_t af[4][4], bh[2][4], bl[2][4];

                // pass 1: A x Bhi
                #pragma unroll
                for (int mt = 0; mt < 4; mt++)
                    ldsm_x4(af[mt], so + af_rel + mt * (16 * TS16 * 2));
                #pragma unroll
                for (int p = 0; p < 2; p++)
                    ldsm_x4(bh[p], so + bh_rel + p * (16 * TS16 * 2));
                #pragma unroll
                for (int mt = 0; mt < 4; mt++)
                    #pragma unroll
                    for (int nt = 0; nt < 4; nt++) {
                        const int p = nt >> 1, hx = (nt & 1) * 2;
                        mma16816h(acc[mt][nt], af[mt], bh[p][hx], bh[p][hx + 1]);
                    }
                if (lvalid)
                    cp_async16(so_l + S16_AF + cp_sdo, Agf + lga);

                // pass 2: A x Blo
                #pragma unroll
                for (int p = 0; p < 2; p++)
                    ldsm_x4(bl[p], so + bl_rel + p * (16 * TS16 * 2));
                #pragma unroll
                for (int mt = 0; mt < 4; mt++)
                    #pragma unroll
                    for (int nt = 0; nt < 4; nt++) {
                        const int p = nt >> 1, hx = (nt & 1) * 2;
                        mma16816h(acc[mt][nt], af[mt], bl[p][hx], bl[p][hx + 1]);
                    }
                if (lvalid) {
                    cp_async16(so_l + S16_BH + cp_sdo, Bgh + lgb);
                    cp_async16(so_l + S16_BL + cp_sdo, Bgl + lgb);
                }

                CP_COMMIT();
                advance_load();
                cs = (cs + 1) & 3;
            }
        }

        // --- epilogue ---
        #pragma unroll
        for (int nt = 0; nt < 4; nt++) {
            const int ncol = bcol + n_base + nt * 8 + (lane & 3) * 2;
            float2 bv = *reinterpret_cast<const float2*>(&bias[ncol]);
            if (MODE == 0) {
                #pragma unroll
                for (int mt = 0; mt < 4; mt++) {
                    int row0 = brow + m_base + mt * 16 + (lane >> 2);
                    float2 v0, v1;
                    v0.x = acc[mt][nt][0] + bv.x;  v0.y = acc[mt][nt][1] + bv.y;
                    v1.x = acc[mt][nt][2] + bv.x;  v1.y = acc[mt][nt][3] + bv.y;
                    *reinterpret_cast<float2*>(&C[(size_t)row0 * N + ncol]) = v0;
                    *reinterpret_cast<float2*>(&C[(size_t)(row0 + 8) * N + ncol]) = v1;
                }
            } else {
                const int region = ncol >> 10;
                const int hh = (ncol >> 6) & (HH - 1);
                const int dd = ncol & (HDD - 1);
                __nv_bfloat16* oh = (region == 0) ? oqh : (region == 1) ? okh : ovh;
                __nv_bfloat16* ol = (region == 0) ? oql : (region == 1) ? okl : ovl;
                const float sc = (region == 0) ? QSC : 1.f;
                const size_t colbase = (size_t)hh * (SS * HDD) + dd;
                #pragma unroll
                for (int mt = 0; mt < 4; mt++) {
                    int row0 = brow + m_base + mt * 16 + (lane >> 2);
                    #pragma unroll
                    for (int rr = 0; rr < 2; rr++) {
                        int row = row0 + rr * 8;
                        float v0 = (acc[mt][nt][rr * 2 + 0] + bv.x) * sc;
                        float v1 = (acc[mt][nt][rr * 2 + 1] + bv.y) * sc;
                        uint32_t hp = cvt_bf2(v0, v1);
                        float r0 = __uint_as_float(hp << 16);
                        float r1 = __uint_as_float(hp & 0xffff0000u);
                        uint32_t lp = cvt_bf2(v0 - r0, v1 - r1);
                        int bb = row >> 11, ss = row & (SS - 1);
                        size_t off = (size_t)bb * HH * SS * HDD + colbase + (size_t)ss * HDD;
                        *reinterpret_cast<uint32_t*>(&oh[off]) = hp;
                        *reinterpret_cast<uint32_t*>(&ol[off]) = lp;
                    }
                }
            }
        }
    }
}

// ---------------------------------------------------------------------------
// Tensor-core causal flash attention (bf16 3-pass, as R10);
// epilogue writes single fp16 y.
// ---------------------------------------------------------------------------
#define FS_KH   0
#define FS_KL   9216
#define FS_VH   18432
#define FS_VL   27648
#define FS_STG  36864
#define FS_QL   (2 * FS_STG)           // 73728
#define FS_TOTAL (FS_QL + 18432)       // 92160

__global__ __launch_bounds__(256, 2)
void flash_attn_tc(const __nv_bfloat16* __restrict__ Qh, const __nv_bfloat16* __restrict__ Ql,
                   const __nv_bfloat16* __restrict__ Kh, const __nv_bfloat16* __restrict__ Kl,
                   const __nv_bfloat16* __restrict__ Vh, const __nv_bfloat16* __restrict__ Vl,
                   __half* __restrict__ yf)
{
    extern __shared__ __align__(16) char sm[];
    const uint32_t sbase = smem_u32(sm);

    const int tid  = threadIdx.x;
    const int lane = tid & 31;
    const int w    = tid >> 5;
    const int qtile = (gridDim.x - 1) - blockIdx.x;
    const int h = blockIdx.y;
    const int b = blockIdx.z;
    const size_t base = ((size_t)(b * HH + h)) * SS * HDD;

    {
        const int s0 = qtile * 128;
        #pragma unroll
        for (int i = 0; i < 4; i++) {
            int idx = i * 256 + tid;
            int r  = idx >> 3;
            int c8 = (idx & 7) * 8;
            uint32_t so = (uint32_t)(r * KSTR + c8) * 2;
            size_t g = base + (size_t)(s0 + r) * HDD + c8;
            *reinterpret_cast<uint4*>(sm + so) =
                *reinterpret_cast<const uint4*>(&Qh[g]);
            *reinterpret_cast<uint4*>(sm + FS_QL + so) =
                *reinterpret_cast<const uint4*>(&Ql[g]);
        }
    }
    __syncthreads();

    uint32_t qfh[4][4];
    const uint32_t q_rel = ((w * 16 + (lane & 15)) * KSTR + (lane >> 4) * 8) * 2;
    {
        const uint32_t qa = sbase + q_rel;
        #pragma unroll
        for (int kc = 0; kc < 4; kc++) ldsm_x4(qfh[kc], qa + kc * 32);
    }
    __syncthreads();
    const uint32_t qla = sbase + FS_QL + q_rel;

    const uint32_t ka_rel = (((lane >> 4) * 8 + (lane & 7)) * KSTR +
                             ((lane >> 3) & 1) * 8) * 2;
    const uint32_t va_rel = ((((lane >> 3) & 1) * 8 + (lane & 7)) * KSTR +
                             ((lane >> 4) & 1) * 8) * 2;

    int cg_r[2], cg_c8[2]; uint32_t cg_so[2];
    #pragma unroll
    for (int ii = 0; ii < 2; ii++) {
        int j  = ii * 256 + tid;
        cg_r[ii]  = j >> 3;
        cg_c8[ii] = (j & 7) * 8;
        cg_so[ii] = (uint32_t)(cg_r[ii] * KSTR + cg_c8[ii]) * 2;
    }

    float o[8][4];
    #pragma unroll
    for (int j = 0; j < 8; j++)
        #pragma unroll
        for (int r = 0; r < 4; r++) o[j][r] = 0.f;
    float m0 = -1e30f, m1 = -1e30f, l0 = 0.f, l1 = 0.f;

    const int row_a0 = qtile * 128 + w * 16 + (lane >> 2);
    const int num_kv = 2 * qtile + 2;

    {
        const uint32_t sa = sbase;
        #pragma unroll
        for (int ii = 0; ii < 2; ii++) {
            size_t g = base + (size_t)cg_r[ii] * HDD + cg_c8[ii];
            cp_async16(sa + FS_KH + cg_so[ii], Kh + g);
            cp_async16(sa + FS_KL + cg_so[ii], Kl + g);
            cp_async16(sa + FS_VH + cg_so[ii], Vh + g);
            cp_async16(sa + FS_VL + cg_so[ii], Vl + g);
        }
        CP_COMMIT();
    }

    for (int t = 0; t < num_kv; t++) {
        CP_WAIT(0);
        __syncthreads();

        const bool pre = (t + 1 < num_kv);
        const uint32_t sa_n = sbase + (uint32_t)((t + 1) & 1) * FS_STG;
        const size_t gb_n = base + (size_t)(t + 1) * 64 * HDD;

        const uint32_t sa = sbase + (uint32_t)(t & 1) * FS_STG;
        const uint32_t ka_h = sa + FS_KH + ka_rel;
        const uint32_t ka_l = sa + FS_KL + ka_rel;
        const uint32_t va_h = sa + FS_VH + va_rel;
        const uint32_t va_l = sa + FS_VL + va_rel;

        float s[8][4];
        #pragma unroll
        for (int j = 0; j < 8; j++)
            #pragma unroll
            for (int r = 0; r < 4; r++) s[j][r] = 0.f;

        #pragma unroll
        for (int kc = 0; kc < 4; kc++) {
            uint32_t qfl4[4];
            ldsm_x4(qfl4, qla + kc * 32);
            #pragma unroll
            for (int np = 0; np < 4; np++) {
                uint32_t kh4[4], kl4[4];
                ldsm_x4(kh4, ka_h + np * (16 * KSTR * 2) + kc * 32);
                ldsm_x4(kl4, ka_l + np * (16 * KSTR * 2) + kc * 32);
                mma16816(s[2*np],   qfh[kc], kh4[0], kh4[1]);
                mma16816(s[2*np+1], qfh[kc], kh4[2], kh4[3]);
                mma16816(s[2*np],   qfl4,    kh4[0], kh4[1]);
                mma16816(s[2*np+1], qfl4,    kh4[2], kh4[3]);
                mma16816(s[2*np],   qfh[kc], kl4[0], kl4[1]);
                mma16816(s[2*np+1], qfh[kc], kl4[2], kl4[3]);
            }
            if (kc == 0 && pre) {
                #pragma unroll
                for (int ii = 0; ii < 2; ii++) {
                    size_t g = gb_n + (size_t)cg_r[ii] * HDD + cg_c8[ii];
                    cp_async16(sa_n + FS_KH + cg_so[ii], Kh + g);
                    cp_async16(sa_n + FS_KL + cg_so[ii], Kl + g);
                }
            }
            if (kc == 2 && pre) {
                #pragma unroll
                for (int ii = 0; ii < 2; ii++) {
                    size_t g = gb_n + (size_t)cg_r[ii] * HDD + cg_c8[ii];
                    cp_async16(sa_n + FS_VH + cg_so[ii], Vh + g);
                    cp_async16(sa_n + FS_VL + cg_so[ii], Vl + g);
                }
            }
        }
        CP_COMMIT();

        if (t >= 2 * qtile) {
            #pragma unroll
            for (int j = 0; j < 8; j++) {
                int col = t * 64 + j * 8 + (lane & 3) * 2;
                #pragma unroll
                for (int r = 0; r < 4; r++) {
                    int cc = col + (r & 1);
                    int rw = row_a0 + ((r >= 2) ? 8 : 0);
                    if (cc > rw) s[j][r] = -1e30f;
                }
            }
        }

        float mx0 = -1e30f, mx1 = -1e30f;
        #pragma unroll
        for (int j = 0; j < 8; j++) {
            mx0 = fmaxf(mx0, fmaxf(s[j][0], s[j][1]));
            mx1 = fmaxf(mx1, fmaxf(s[j][2], s[j][3]));
        }
        mx0 = fmaxf(mx0, __shfl_xor_sync(0xffffffffu, mx0, 1));
        mx0 = fmaxf(mx0, __shfl_xor_sync(0xffffffffu, mx0, 2));
        mx1 = fmaxf(mx1, __shfl_xor_sync(0xffffffffu, mx1, 1));
        mx1 = fmaxf(mx1, __shfl_xor_sync(0xffffffffu, mx1, 2));
        float mn0 = fmaxf(m0, mx0), mn1 = fmaxf(m1, mx1);
        float sc0 = ex2f(m0 - mn0), sc1 = ex2f(m1 - mn1);
        m0 = mn0; m1 = mn1;
        l0 *= sc0; l1 *= sc1;
        #pragma unroll
        for (int j = 0; j < 8; j++) {
            o[j][0] *= sc0; o[j][1] *= sc0;
            o[j][2] *= sc1; o[j][3] *= sc1;
        }
        #pragma unroll
        for (int j = 0; j < 8; j++) {
            float p0 = ex2f(s[j][0] - mn0);
            float p1 = ex2f(s[j][1] - mn0);
            float p2 = ex2f(s[j][2] - mn1);
            float p3 = ex2f(s[j][3] - mn1);
            s[j][0] = p0; s[j][1] = p1; s[j][2] = p2; s[j][3] = p3;
            l0 += p0 + p1;
            l1 += p2 + p3;
        }

        #pragma unroll
        for (int kc = 0; kc < 4; kc++) {
            uint32_t aph[4], apl[4];
            #pragma unroll
            for (int t2 = 0; t2 < 2; t2++) {
                int j = 2 * kc + t2;
                uint32_t h01 = cvt_bf2(s[j][0], s[j][1]);
                uint32_t h23 = cvt_bf2(s[j][2], s[j][3]);
                aph[t2*2 + 0] = h01;
                aph[t2*2 + 1] = h23;
                float r0 = __uint_as_float(h01 << 16);
                float r1 = __uint_as_float(h01 & 0xffff0000u);
                float r2 = __uint_as_float(h23 << 16);
                float r3 = __uint_as_float(h23 & 0xffff0000u);
                apl[t2*2 + 0] = cvt_bf2(s[j][0] - r0, s[j][1] - r1);
                apl[t2*2 + 1] = cvt_bf2(s[j][2] - r2, s[j][3] - r3);
            }
            #pragma unroll
            for (int nb = 0; nb < 4; nb++) {
                uint32_t vh4[4], vl4[4];
                ldsm_x4_t(vh4, va_h + kc * (16 * KSTR * 2) + nb * 32);
                ldsm_x4_t(vl4, va_l + kc * (16 * KSTR * 2) + nb * 32);
                mma16816(o[2*nb],   aph, vh4[0], vh4[1]);
                mma16816(o[2*nb+1], aph, vh4[2], vh4[3]);
                mma16816(o[2*nb],   apl, vh4[0], vh4[1]);
                mma16816(o[2*nb+1], apl, vh4[2], vh4[3]);
                mma16816(o[2*nb],   aph, vl4[0], vl4[1]);
                mma16816(o[2*nb+1], aph, vl4[2], vl4[3]);
            }
        }
    }

    l0 += __shfl_xor_sync(0xffffffffu, l0, 1);
    l0 += __shfl_xor_sync(0xffffffffu, l0, 2);
    l1 += __shfl_xor_sync(0xffffffffu, l1, 1);
    l1 += __shfl_xor_sync(0xffffffffu, l1, 2);
    float inv0 = 1.f / l0, inv1 = 1.f / l1;

    // epilogue: write single fp16 y (row-major [8192, 1024])
    size_t tok0 = (size_t)b * SS + row_a0;
    size_t o0 = tok0 * DD + h * HDD + (lane & 3) * 2;
    size_t o1 = o0 + (size_t)8 * DD;
    #pragma unroll
    for (int j = 0; j < 8; j++) {
        *reinterpret_cast<uint32_t*>(&yf[o0 + j * 8]) =
            cvt_h2(o[j][0] * inv0, o[j][1] * inv0);
        *reinterpret_cast<uint32_t*>(&yf[o1 + j * 8]) =
            cvt_h2(o[j][2] * inv1, o[j][3] * inv1);
    }
}

// ---------------------------------------------------------------------------
// Launch
// ---------------------------------------------------------------------------
extern "C" void kernel_launch(void* const* d_in, const int* in_sizes, int n_in,
                              void* d_out, int out_size)
{
    const float* x      = (const float*)d_in[0];
    const float* W_attn = (const float*)d_in[1];
    const float* b_attn = (const float*)d_in[2];
    const float* W_proj = (const float*)d_in[3];
    const float* b_proj = (const float*)d_in[4];
    float* out = (float*)d_out;

    static __half *xf = nullptr, *yf;
    static __half *wt_hi, *wt_lo, *wpt_hi, *wpt_lo;
    static __nv_bfloat16 *qh, *ql, *kh, *kl, *vh, *vl;
    static int gemm_grid = 0;
    if (!xf) {   // first (non-captured) correctness call
        cudaGetSymbolAddress((void**)&xf, g_xf);
        cudaGetSymbolAddress((void**)&yf, g_yf);
        cudaGetSymbolAddress((void**)&wt_hi,  g_wt_hi);
        cudaGetSymbolAddress((void**)&wt_lo,  g_wt_lo);
        cudaGetSymbolAddress((void**)&wpt_hi, g_wpt_hi);
        cudaGetSymbolAddress((void**)&wpt_lo, g_wpt_lo);
        cudaGetSymbolAddress((void**)&qh, g_qh);
        cudaGetSymbolAddress((void**)&ql, g_ql);
        cudaGetSymbolAddress((void**)&kh, g_kh);
        cudaGetSymbolAddress((void**)&kl, g_kl);
        cudaGetSymbolAddress((void**)&vh, g_vh);
        cudaGetSymbolAddress((void**)&vl, g_vl);
        cudaFuncSetAttribute(flash_attn_tc,
                             cudaFuncAttributeMaxDynamicSharedMemorySize,
                             FS_TOTAL);
        cudaFuncSetAttribute(tc_gemm_kernel<0>,
                             cudaFuncAttributeMaxDynamicSharedMemorySize,
                             GEMM_SMEM);
        cudaFuncSetAttribute(tc_gemm_kernel<1>,
                             cudaFuncAttributeMaxDynamicSharedMemorySize,
                             GEMM_SMEM);
        cudaDeviceProp prop;
        cudaGetDeviceProperties(&prop, 0);
        gemm_grid = prop.multiProcessorCount * 2;   // persistent: 2 CTAs/SM
    }

    // 0a) convert x -> fp16
    convert_f16_kernel<<<(MTOK * DD) / (256 * 4), 256>>>(x, xf);
    // 0b) transpose + fp16 hi/lo split weights
    {
        dim3 g1(3 * DD / 32, DD / 32);
        transpose_split_kernel<<<g1, 256>>>(W_attn, wt_hi, wt_lo, DD, 3 * DD);
        dim3 g2(DD / 32, DD / 32);
        transpose_split_kernel<<<g2, 256>>>(W_proj, wpt_hi, wpt_lo, DD, DD);
    }

    // 1) QKV GEMM (persistent, fp16 2-pass) + fused split epilogue
    tc_gemm_kernel<1><<<gemm_grid, 256, GEMM_SMEM>>>(
        xf, wt_hi, wt_lo, b_attn, nullptr,
        qh, ql, kh, kl, vh, vl, MTOK, 3 * DD, DD);

    // 2) tensor-core causal flash attention -> fp16 y
    {
        dim3 grid(SS / 128, HH, BB);
        flash_attn_tc<<<grid, 256, FS_TOTAL>>>(qh, ql, kh, kl, vh, vl, yf);
    }

    // 3) output projection (persistent, fp16 2-pass) -> out
    tc_gemm_kernel<0><<<gemm_grid, 256, GEMM_SMEM>>>(
        yf, wpt_hi, wpt_lo, b_proj, out,
        nullptr, nullptr, nullptr, nullptr, nullptr, nullptr,
        MTOK, DD, DD);
}

// round 12
// speedup vs baseline: 1.5202x; 1.1249x over previous
#include <cuda_runtime.h>
#include <cuda_bf16.h>
#include <cuda_fp16.h>
#include <cstdint>
#include <cstddef>

// Problem constants
#define BB  4
#define SS  2048
#define DD  1024
#define HH  16
#define HDD 64
#define MTOK (BB*SS)          // 8192 token rows

// q prescale: HD^-0.5 * log2(e)  (softmax done in exp2 domain)
#define QSC 0.18033688011112042f

// Scratch (device globals; no allocations allowed)
__device__ __align__(128) __half g_xf[(size_t)MTOK * DD];            // x fp16
__device__ __align__(128) __half g_yf[(size_t)MTOK * DD];            // attn out fp16
__device__ __align__(128) __half g_wt_hi [(size_t)3 * DD * DD];      // W_attn^T fp16 hi
__device__ __align__(128) __half g_wt_lo [(size_t)3 * DD * DD];
__device__ __align__(128) __half g_wpt_hi[(size_t)DD * DD];
__device__ __align__(128) __half g_wpt_lo[(size_t)DD * DD];
#define BHSZ ((size_t)BB * HH * SS * HDD)
__device__ __align__(128) __half g_qf[BHSZ];                          // Q single fp16
__device__ __align__(128) __half g_kh[BHSZ], g_kl[BHSZ];              // K fp16 hi/lo
__device__ __align__(128) __half g_vh[BHSZ], g_vl[BHSZ];              // V fp16 hi/lo

// ---------------------------------------------------------------------------
// Warp-MMA + async-copy helpers
// ---------------------------------------------------------------------------
__device__ __forceinline__ uint32_t smem_u32(const void* p) {
    uint32_t a;
    asm("{ .reg .u64 t; cvta.to.shared.u64 t, %1; cvt.u32.u64 %0, t; }"
        : "=r"(a) : "l"(p));
    return a;
}
__device__ __forceinline__ void ldsm_x4(uint32_t* r, uint32_t addr) {
    asm volatile("ldmatrix.sync.aligned.m8n8.x4.shared.b16 {%0,%1,%2,%3}, [%4];"
                 : "=r"(r[0]), "=r"(r[1]), "=r"(r[2]), "=r"(r[3]) : "r"(addr));
}
__device__ __forceinline__ void ldsm_x4_t(uint32_t* r, uint32_t addr) {
    asm volatile("ldmatrix.sync.aligned.m8n8.x4.trans.shared.b16 {%0,%1,%2,%3}, [%4];"
                 : "=r"(r[0]), "=r"(r[1]), "=r"(r[2]), "=r"(r[3]) : "r"(addr));
}
// fp16 mma (all stages)
__device__ __forceinline__ void mma16816h(float* d, const uint32_t* a,
                                          const uint32_t b0, const uint32_t b1) {
    asm volatile(
        "mma.sync.aligned.m16n8k16.row.col.f32.f16.f16.f32 "
        "{%0,%1,%2,%3}, {%4,%5,%6,%7}, {%8,%9}, {%0,%1,%2,%3};"
        : "+f"(d[0]), "+f"(d[1]), "+f"(d[2]), "+f"(d[3])
        : "r"(a[0]), "r"(a[1]), "r"(a[2]), "r"(a[3]), "r"(b0), "r"(b1));
}
__device__ __forceinline__ void cp_async16(uint32_t saddr, const void* g) {
    asm volatile("cp.async.cg.shared.global [%0], [%1], 16;"
                 :: "r"(saddr), "l"(g) : "memory");
}
#define CP_COMMIT() asm volatile("cp.async.commit_group;" ::: "memory")
#define CP_WAIT(n)  asm volatile("cp.async.wait_group %0;" :: "n"(n) : "memory")

// packed f32x2 -> f16x2 (lo = a, hi = b)
__device__ __forceinline__ uint32_t cvt_h2(float a, float b) {
    uint32_t r;
    asm("cvt.rn.f16x2.f32 %0, %1, %2;" : "=r"(r) : "f"(b), "f"(a));
    return r;
}
__device__ __forceinline__ float ex2f(float x) {
    float r;
    asm("ex2.approx.f32 %0, %1;" : "=f"(r) : "f"(x));
    return r;
}

#define TS16 24   // GEMM BK=16 row stride (elems): 48B rows, conflict-free ldsm
#define KSTR 72   // attention tile row stride (144B rows, conflict-free)

// ---------------------------------------------------------------------------
// Elementwise fp32 -> fp16 convert (for x)
// ---------------------------------------------------------------------------
__global__ __launch_bounds__(256)
void convert_f16_kernel(const float* __restrict__ in, __half* __restrict__ of)
{
    size_t i = ((size_t)blockIdx.x * 256 + threadIdx.x) * 4;
    float4 v = *reinterpret_cast<const float4*>(in + i);
    uint2 hv;
    hv.x = cvt_h2(v.x, v.y);
    hv.y = cvt_h2(v.z, v.w);
    *reinterpret_cast<uint2*>(of + i) = hv;
}

// ---------------------------------------------------------------------------
// Transpose + fp16 hi/lo split of weights:  W[K,N] fp32 -> Th/Tl[N,K] fp16
// ---------------------------------------------------------------------------
__global__ __launch_bounds__(256)
void transpose_split_kernel(const float* __restrict__ W,
                            __half* __restrict__ Th,
                            __half* __restrict__ Tl,
                            int K, int N)
{
    __shared__ float tile[32][33];
    const int n0 = blockIdx.x * 32;
    const int k0 = blockIdx.y * 32;
    const int tx = threadIdx.x & 31;
    const int ty4 = (threadIdx.x >> 5) * 4;

    #pragma unroll
    for (int j = 0; j < 4; j++)
        tile[ty4 + j][tx] = W[(size_t)(k0 + ty4 + j) * N + n0 + tx];
    __syncthreads();
    #pragma unroll
    for (int j = 0; j < 4; j++) {
        float v = tile[tx][ty4 + j];
        __half hi = __float2half_rn(v);
        __half lo = __float2half_rn(v - __half2float(hi));
        size_t o = (size_t)(n0 + ty4 + j) * K + k0 + tx;
        Th[o] = hi;
        Tl[o] = lo;
    }
}

// ---------------------------------------------------------------------------
// Persistent tensor-core GEMM, fp16 2-pass (A single fp16, B = Bh+Bl fp16):
// BM=128, BN=128, BK=16, 256 threads, 2 CTA/SM, 4-stage continuous pipeline.
// MODE 0: fp32 C.  MODE 1 (QKV): q single fp16 + k,v fp16 hi/lo buffers.
// ---------------------------------------------------------------------------
#define A16_BYTES (128 * TS16 * 2)       // 6144 per array
#define S16_AF 0
#define S16_BH (1 * A16_BYTES)
#define S16_BL (2 * A16_BYTES)
#define S16_STG (3 * A16_BYTES)          // 18432 per stage
#define GEMM_SMEM (4 * S16_STG)          // 73728 (4 stages)

template <int MODE>
__global__ __launch_bounds__(256, 2)
void tc_gemm_kernel(const __half* __restrict__ Agf,
                    const __half* __restrict__ Bgh,
                    const __half* __restrict__ Bgl,
                    const float* __restrict__ bias,
                    float* __restrict__ C,
                    __half* __restrict__ oqf,
                    __half* __restrict__ okh, __half* __restrict__ okl,
                    __half* __restrict__ ovh, __half* __restrict__ ovl,
                    int M, int N, int K)
{
    extern __shared__ __align__(16) char gsm[];
    const uint32_t sb = smem_u32(gsm);

    const int tid  = threadIdx.x;
    const int lane = tid & 31;
    const int wid  = tid >> 5;              // 0..7
    const int bid  = blockIdx.x;
    const int G    = gridDim.x;

    const int NX      = N >> 7;
    const int ntiles  = (M >> 7) * NX;
    const int nchunks = K >> 4;             // BK=16 (even)
    const int njobs   = (bid < ntiles) ? ((ntiles - bid + G - 1) / G) : 0;

    const int m_base = (wid >> 2) * 64;
    const int n_base = (wid & 3) * 32;

    const int a_r  = lane & 15;
    const int a_k  = (lane >> 4) * 8;
    const uint32_t af_rel = S16_AF + ((m_base + a_r) * TS16 + a_k) * 2;
    const int b_n  = (lane >> 4) * 8 + (lane & 7);
    const int b_k  = ((lane >> 3) & 1) * 8;
    const uint32_t bh_rel = S16_BH + ((n_base + b_n) * TS16 + b_k) * 2;
    const uint32_t bl_rel = S16_BL + ((n_base + b_n) * TS16 + b_k) * 2;

    const int cp_r  = tid >> 1;
    const int cp_k8 = (tid & 1) << 3;
    const uint32_t cp_sdo = (uint32_t)(cp_r * TS16 + cp_k8) * 2;

    int lj = 0, lc = 0, ls = 0;
    uint32_t goA = 0, goB = 0;
    if (njobs > 0) {
        int t = bid;
        int lby = t / NX, lbx = t - lby * NX;
        goA = (uint32_t)(lby * 128 + cp_r) * (uint32_t)K + cp_k8;
        goB = (uint32_t)(lbx * 128 + cp_r) * (uint32_t)K + cp_k8;
    }

    auto advance_load = [&]() {
        ls = (ls + 1) & 3;
        if (++lc == nchunks) {
            lc = 0; lj++;
            if (lj < njobs) {
                int t = bid + lj * G;
                int lby = t / NX, lbx = t - lby * NX;
                goA = (uint32_t)(lby * 128 + cp_r) * (uint32_t)K + cp_k8;
                goB = (uint32_t)(lbx * 128 + cp_r) * (uint32_t)K + cp_k8;
            }
        } else {
            goA += 16; goB += 16;
        }
    };

    #pragma unroll
    for (int i = 0; i < 2; i++) {
        if (lj < njobs) {
            const uint32_t so = sb + (uint32_t)ls * S16_STG;
            cp_async16(so + S16_AF + cp_sdo, Agf + goA);
            cp_async16(so + S16_BH + cp_sdo, Bgh + goB);
            cp_async16(so + S16_BL + cp_sdo, Bgl + goB);
        }
        CP_COMMIT();
        advance_load();
    }

    int cs = 0;
    for (int j = 0; j < njobs; j++) {
        const int tile_id = bid + j * G;
        const int by = tile_id / NX;
        const int bx = tile_id - by * NX;
        const int brow = by * 128;
        const int bcol = bx * 128;

        float acc[4][4][4];
        #pragma unroll
        for (int i = 0; i < 4; i++)
            #pragma unroll
            for (int jj = 0; jj < 4; jj++)
                #pragma unroll
                for (int r = 0; r < 4; r++) acc[i][jj][r] = 0.f;

        for (int cpair = 0; cpair < nchunks; cpair += 2) {
            CP_WAIT(0);
            __syncthreads();

            #pragma unroll
            for (int u = 0; u < 2; u++) {
                const bool lvalid = (lj < njobs);
                const uint32_t so_l = sb + (uint32_t)ls * S16_STG;
                const uint32_t lga = goA, lgb = goB;

                const uint32_t so = sb + (uint32_t)cs * S16_STG;
                uint32_t af[4][4], bh[2][4], bl[2][4];

                // pass 1: A x Bhi
                #pragma unroll
                for (int mt = 0; mt < 4; mt++)
                    ldsm_x4(af[mt], so + af_rel + mt * (16 * TS16 * 2));
                #pragma unroll
                for (int p = 0; p < 2; p++)
                    ldsm_x4(bh[p], so + bh_rel + p * (16 * TS16 * 2));
                #pragma unroll
                for (int mt = 0; mt < 4; mt++)
                    #pragma unroll
                    for (int nt = 0; nt < 4; nt++) {
                        const int p = nt >> 1, hx = (nt & 1) * 2;
                        mma16816h(acc[mt][nt], af[mt], bh[p][hx], bh[p][hx + 1]);
                    }
                if (lvalid)
                    cp_async16(so_l + S16_AF + cp_sdo, Agf + lga);

                // pass 2: A x Blo
                #pragma unroll
                for (int p = 0; p < 2; p++)
                    ldsm_x4(bl[p], so + bl_rel + p * (16 * TS16 * 2));
                #pragma unroll
                for (int mt = 0; mt < 4; mt++)
                    #pragma unroll
                    for (int nt = 0; nt < 4; nt++) {
                        const int p = nt >> 1, hx = (nt & 1) * 2;
                        mma16816h(acc[mt][nt], af[mt], bl[p][hx], bl[p][hx + 1]);
                    }
                if (lvalid) {
                    cp_async16(so_l + S16_BH + cp_sdo, Bgh + lgb);
                    cp_async16(so_l + S16_BL + cp_sdo, Bgl + lgb);
                }

                CP_COMMIT();
                advance_load();
                cs = (cs + 1) & 3;
            }
        }

        // --- epilogue ---
        #pragma unroll
        for (int nt = 0; nt < 4; nt++) {
            const int ncol = bcol + n_base + nt * 8 + (lane & 3) * 2;
            float2 bv = *reinterpret_cast<const float2*>(&bias[ncol]);
            if (MODE == 0) {
                #pragma unroll
                for (int mt = 0; mt < 4; mt++) {
                    int row0 = brow + m_base + mt * 16 + (lane >> 2);
                    float2 v0, v1;
                    v0.x = acc[mt][nt][0] + bv.x;  v0.y = acc[mt][nt][1] + bv.y;
                    v1.x = acc[mt][nt][2] + bv.x;  v1.y = acc[mt][nt][3] + bv.y;
                    *reinterpret_cast<float2*>(&C[(size_t)row0 * N + ncol]) = v0;
                    *reinterpret_cast<float2*>(&C[(size_t)(row0 + 8) * N + ncol]) = v1;
                }
            } else {
                const int region = ncol >> 10;          // 0:q 1:k 2:v
                const int hh = (ncol >> 6) & (HH - 1);
                const int dd = ncol & (HDD - 1);
                const size_t colbase = (size_t)hh * (SS * HDD) + dd;
                #pragma unroll
                for (int mt = 0; mt < 4; mt++) {
                    int row0 = brow + m_base + mt * 16 + (lane >> 2);
                    #pragma unroll
                    for (int rr = 0; rr < 2; rr++) {
                        int row = row0 + rr * 8;
                        float v0 = acc[mt][nt][rr * 2 + 0] + bv.x;
                        float v1 = acc[mt][nt][rr * 2 + 1] + bv.y;
                        int bb = row >> 11, ss = row & (SS - 1);
                        size_t off = (size_t)bb * HH * SS * HDD + colbase + (size_t)ss * HDD;
                        if (region == 0) {
                            *reinterpret_cast<uint32_t*>(&oqf[off]) =
                                cvt_h2(v0 * QSC, v1 * QSC);
                        } else {
                            __half h0 = __float2half_rn(v0);
                            __half h1 = __float2half_rn(v1);
                            __half l0 = __float2half_rn(v0 - __half2float(h0));
                            __half l1 = __float2half_rn(v1 - __half2float(h1));
                            __half2 hp; hp.x = h0; hp.y = h1;
                            __half2 lp; lp.x = l0; lp.y = l1;
                            __half* oh = (region == 1) ? okh : ovh;
                            __half* ol = (region == 1) ? okl : ovl;
                            *reinterpret_cast<__half2*>(&oh[off]) = hp;
                            *reinterpret_cast<__half2*>(&ol[off]) = lp;
                        }
                    }
                }
            }
        }
    }
}

// ---------------------------------------------------------------------------
// Tensor-core causal flash attention, fp16 2-pass:
// S = Qf (single) x (Kh+Kl);  O += Pf (single) x (Vh+Vl).
// BM=128 (8 warps, 256 threads), cp.async 2-stage K/V ring (64 keys/tile).
// ---------------------------------------------------------------------------
#define FS_KH   0
#define FS_KL   9216
#define FS_VH   18432
#define FS_VL   27648
#define FS_STG  36864
#define FS_TOTAL (2 * FS_STG)          // 73728

__global__ __launch_bounds__(256, 2)
void flash_attn_tc(const __half* __restrict__ Qf,
                   const __half* __restrict__ Kh, const __half* __restrict__ Kl,
                   const __half* __restrict__ Vh, const __half* __restrict__ Vl,
                   __half* __restrict__ yf)
{
    extern __shared__ __align__(16) char sm[];
    const uint32_t sbase = smem_u32(sm);

    const int tid  = threadIdx.x;
    const int lane = tid & 31;
    const int w    = tid >> 5;
    const int qtile = (gridDim.x - 1) - blockIdx.x;
    const int h = blockIdx.y;
    const int b = blockIdx.z;
    const size_t base = ((size_t)(b * HH + h)) * SS * HDD;

    // ---- stage Q (single fp16) through ring stage 0, build frags ----
    {
        const int s0 = qtile * 128;
        #pragma unroll
        for (int i = 0; i < 4; i++) {
            int idx = i * 256 + tid;
            int r  = idx >> 3;
            int c8 = (idx & 7) * 8;
            *reinterpret_cast<uint4*>(sm + (uint32_t)(r * KSTR + c8) * 2) =
                *reinterpret_cast<const uint4*>(&Qf[base + (size_t)(s0 + r) * HDD + c8]);
        }
    }
    __syncthreads();

    uint32_t qf[4][4];
    {
        const uint32_t qa = sbase +
            ((w * 16 + (lane & 15)) * KSTR + (lane >> 4) * 8) * 2;
        #pragma unroll
        for (int kc = 0; kc < 4; kc++) ldsm_x4(qf[kc], qa + kc * 32);
    }
    __syncthreads();   // Q staging dead; ring stage 0 reusable

    const uint32_t ka_rel = (((lane >> 4) * 8 + (lane & 7)) * KSTR +
                             ((lane >> 3) & 1) * 8) * 2;
    const uint32_t va_rel = ((((lane >> 3) & 1) * 8 + (lane & 7)) * KSTR +
                             ((lane >> 4) & 1) * 8) * 2;

    int cg_r[2], cg_c8[2]; uint32_t cg_so[2];
    #pragma unroll
    for (int ii = 0; ii < 2; ii++) {
        int j  = ii * 256 + tid;
        cg_r[ii]  = j >> 3;
        cg_c8[ii] = (j & 7) * 8;
        cg_so[ii] = (uint32_t)(cg_r[ii] * KSTR + cg_c8[ii]) * 2;
    }

    float o[8][4];
    #pragma unroll
    for (int j = 0; j < 8; j++)
        #pragma unroll
        for (int r = 0; r < 4; r++) o[j][r] = 0.f;
    float m0 = -1e30f, m1 = -1e30f, l0 = 0.f, l1 = 0.f;

    const int row_a0 = qtile * 128 + w * 16 + (lane >> 2);
    const int num_kv = 2 * qtile + 2;

    // prologue: tile 0 into stage 0
    {
        const uint32_t sa = sbase;
        #pragma unroll
        for (int ii = 0; ii < 2; ii++) {
            size_t g = base + (size_t)cg_r[ii] * HDD + cg_c8[ii];
            cp_async16(sa + FS_KH + cg_so[ii], Kh + g);
            cp_async16(sa + FS_KL + cg_so[ii], Kl + g);
            cp_async16(sa + FS_VH + cg_so[ii], Vh + g);
            cp_async16(sa + FS_VL + cg_so[ii], Vl + g);
        }
        CP_COMMIT();
    }

    for (int t = 0; t < num_kv; t++) {
        CP_WAIT(0);
        __syncthreads();

        const bool pre = (t + 1 < num_kv);
        const uint32_t sa_n = sbase + (uint32_t)((t + 1) & 1) * FS_STG;
        const size_t gb_n = base + (size_t)(t + 1) * 64 * HDD;

        const uint32_t sa = sbase + (uint32_t)(t & 1) * FS_STG;
        const uint32_t ka_h = sa + FS_KH + ka_rel;
        const uint32_t ka_l = sa + FS_KL + ka_rel;
        const uint32_t va_h = sa + FS_VH + va_rel;
        const uint32_t va_l = sa + FS_VL + va_rel;

        // ---- S = Qf (Kh + Kl)^T ----
        float s[8][4];
        #pragma unroll
        for (int j = 0; j < 8; j++)
            #pragma unroll
            for (int r = 0; r < 4; r++) s[j][r] = 0.f;

        #pragma unroll
        for (int kc = 0; kc < 4; kc++) {
            #pragma unroll
            for (int np = 0; np < 4; np++) {
                uint32_t kh4[4], kl4[4];
                ldsm_x4(kh4, ka_h + np * (16 * KSTR * 2) + kc * 32);
                ldsm_x4(kl4, ka_l + np * (16 * KSTR * 2) + kc * 32);
                mma16816h(s[2*np],   qf[kc], kh4[0], kh4[1]);
                mma16816h(s[2*np+1], qf[kc], kh4[2], kh4[3]);
                mma16816h(s[2*np],   qf[kc], kl4[0], kl4[1]);
                mma16816h(s[2*np+1], qf[kc], kl4[2], kl4[3]);
            }
            if (kc == 0 && pre) {
                #pragma unroll
                for (int ii = 0; ii < 2; ii++) {
                    size_t g = gb_n + (size_t)cg_r[ii] * HDD + cg_c8[ii];
                    cp_async16(sa_n + FS_KH + cg_so[ii], Kh + g);
                    cp_async16(sa_n + FS_KL + cg_so[ii], Kl + g);
                }
            }
            if (kc == 2 && pre) {
                #pragma unroll
                for (int ii = 0; ii < 2; ii++) {
                    size_t g = gb_n + (size_t)cg_r[ii] * HDD + cg_c8[ii];
                    cp_async16(sa_n + FS_VH + cg_so[ii], Vh + g);
                    cp_async16(sa_n + FS_VL + cg_so[ii], Vl + g);
                }
            }
        }
        CP_COMMIT();

        if (t >= 2 * qtile) {
            #pragma unroll
            for (int j = 0; j < 8; j++) {
                int col = t * 64 + j * 8 + (lane & 3) * 2;
                #pragma unroll
                for (int r = 0; r < 4; r++) {
                    int cc = col + (r & 1);
                    int rw = row_a0 + ((r >= 2) ? 8 : 0);
                    if (cc > rw) s[j][r] = -1e30f;
                }
            }
        }

        float mx0 = -1e30f, mx1 = -1e30f;
        #pragma unroll
        for (int j = 0; j < 8; j++) {
            mx0 = fmaxf(mx0, fmaxf(s[j][0], s[j][1]));
            mx1 = fmaxf(mx1, fmaxf(s[j][2], s[j][3]));
        }
        mx0 = fmaxf(mx0, __shfl_xor_sync(0xffffffffu, mx0, 1));
        mx0 = fmaxf(mx0, __shfl_xor_sync(0xffffffffu, mx0, 2));
        mx1 = fmaxf(mx1, __shfl_xor_sync(0xffffffffu, mx1, 1));
        mx1 = fmaxf(mx1, __shfl_xor_sync(0xffffffffu, mx1, 2));
        float mn0 = fmaxf(m0, mx0), mn1 = fmaxf(m1, mx1);
        float sc0 = ex2f(m0 - mn0), sc1 = ex2f(m1 - mn1);
        m0 = mn0; m1 = mn1;
        l0 *= sc0; l1 *= sc1;
        #pragma unroll
        for (int j = 0; j < 8; j++) {
            o[j][0] *= sc0; o[j][1] *= sc0;
            o[j][2] *= sc1; o[j][3] *= sc1;
        }
        #pragma unroll
        for (int j = 0; j < 8; j++) {
            float p0 = ex2f(s[j][0] - mn0);
            float p1 = ex2f(s[j][1] - mn0);
            float p2 = ex2f(s[j][2] - mn1);
            float p3 = ex2f(s[j][3] - mn1);
            s[j][0] = p0; s[j][1] = p1; s[j][2] = p2; s[j][3] = p3;
            l0 += p0 + p1;
            l1 += p2 + p3;
        }

        // ---- O += Pf (Vh + Vl) ----
        #pragma unroll
        for (int kc = 0; kc < 4; kc++) {
            uint32_t pf[4];
            #pragma unroll
            for (int t2 = 0; t2 < 2; t2++) {
                int j = 2 * kc + t2;
                pf[t2*2 + 0] = cvt_h2(s[j][0], s[j][1]);
                pf[t2*2 + 1] = cvt_h2(s[j][2], s[j][3]);
            }
            #pragma unroll
            for (int nb = 0; nb < 4; nb++) {
                uint32_t vh4[4], vl4[4];
                ldsm_x4_t(vh4, va_h + kc * (16 * KSTR * 2) + nb * 32);
                ldsm_x4_t(vl4, va_l + kc * (16 * KSTR * 2) + nb * 32);
                mma16816h(o[2*nb],   pf, vh4[0], vh4[1]);
                mma16816h(o[2*nb+1], pf, vh4[2], vh4[3]);
                mma16816h(o[2*nb],   pf, vl4[0], vl4[1]);
                mma16816h(o[2*nb+1], pf, vl4[2], vl4[3]);
            }
        }
    }

    l0 += __shfl_xor_sync(0xffffffffu, l0, 1);
    l0 += __shfl_xor_sync(0xffffffffu, l0, 2);
    l1 += __shfl_xor_sync(0xffffffffu, l1, 1);
    l1 += __shfl_xor_sync(0xffffffffu, l1, 2);
    float inv0 = 1.f / l0, inv1 = 1.f / l1;

    // epilogue: write single fp16 y (row-major [8192, 1024])
    size_t tok0 = (size_t)b * SS + row_a0;
    size_t o0 = tok0 * DD + h * HDD + (lane & 3) * 2;
    size_t o1 = o0 + (size_t)8 * DD;
    #pragma unroll
    for (int j = 0; j < 8; j++) {
        *reinterpret_cast<uint32_t*>(&yf[o0 + j * 8]) =
            cvt_h2(o[j][0] * inv0, o[j][1] * inv0);
        *reinterpret_cast<uint32_t*>(&yf[o1 + j * 8]) =
            cvt_h2(o[j][2] * inv1, o[j][3] * inv1);
    }
}

// ---------------------------------------------------------------------------
// Launch
// ---------------------------------------------------------------------------
extern "C" void kernel_launch(void* const* d_in, const int* in_sizes, int n_in,
                              void* d_out, int out_size)
{
    const float* x      = (const float*)d_in[0];
    const float* W_attn = (const float*)d_in[1];
    const float* b_attn = (const float*)d_in[2];
    const float* W_proj = (const float*)d_in[3];
    const float* b_proj = (const float*)d_in[4];
    float* out = (float*)d_out;

    static __half *xf = nullptr, *yf;
    static __half *wt_hi, *wt_lo, *wpt_hi, *wpt_lo;
    static __half *qf, *kh, *kl, *vh, *vl;
    static int gemm_grid = 0;
    if (!xf) {   // first (non-captured) correctness call
        cudaGetSymbolAddress((void**)&xf, g_xf);
        cudaGetSymbolAddress((void**)&yf, g_yf);
        cudaGetSymbolAddress((void**)&wt_hi,  g_wt_hi);
        cudaGetSymbolAddress((void**)&wt_lo,  g_wt_lo);
        cudaGetSymbolAddress((void**)&wpt_hi, g_wpt_hi);
        cudaGetSymbolAddress((void**)&wpt_lo, g_wpt_lo);
        cudaGetSymbolAddress((void**)&qf, g_qf);
        cudaGetSymbolAddress((void**)&kh, g_kh);
        cudaGetSymbolAddress((void**)&kl, g_kl);
        cudaGetSymbolAddress((void**)&vh, g_vh);
        cudaGetSymbolAddress((void**)&vl, g_vl);
        cudaFuncSetAttribute(flash_attn_tc,
                             cudaFuncAttributeMaxDynamicSharedMemorySize,
                             FS_TOTAL);
        cudaFuncSetAttribute(tc_gemm_kernel<0>,
                             cudaFuncAttributeMaxDynamicSharedMemorySize,
                             GEMM_SMEM);
        cudaFuncSetAttribute(tc_gemm_kernel<1>,
                             cudaFuncAttributeMaxDynamicSharedMemorySize,
                             GEMM_SMEM);
        cudaDeviceProp prop;
        cudaGetDeviceProperties(&prop, 0);
        gemm_grid = prop.multiProcessorCount * 2;   // persistent: 2 CTAs/SM
    }

    // 0a) convert x -> fp16
    convert_f16_kernel<<<(MTOK * DD) / (256 * 4), 256>>>(x, xf);
    // 0b) transpose + fp16 hi/lo split weights
    {
        dim3 g1(3 * DD / 32, DD / 32);
        transpose_split_kernel<<<g1, 256>>>(W_attn, wt_hi, wt_lo, DD, 3 * DD);
        dim3 g2(DD / 32, DD / 32);
        transpose_split_kernel<<<g2, 256>>>(W_proj, wpt_hi, wpt_lo, DD, DD);
    }

    // 1) QKV GEMM (persistent, fp16 2-pass) + fused epilogue -> qf,kh,kl,vh,vl
    tc_gemm_kernel<1><<<gemm_grid, 256, GEMM_SMEM>>>(
        xf, wt_hi, wt_lo, b_attn, nullptr,
        qf, kh, kl, vh, vl, MTOK, 3 * DD, DD);

    // 2) fp16 tensor-core causal flash attention -> fp16 y
    {
        dim3 grid(SS / 128, HH, BB);
        flash_attn_tc<<<grid, 256, FS_TOTAL>>>(qf, kh, kl, vh, vl, yf);
    }

    // 3) output projection (persistent, fp16 2-pass) -> out
    tc_gemm_kernel<0><<<gemm_grid, 256, GEMM_SMEM>>>(
        yf, wpt_hi, wpt_lo, b_proj, out,
        nullptr, nullptr, nullptr, nullptr, nullptr,
        MTOK, DD, DD);
}

// round 13
// speedup vs baseline: 1.7979x; 1.1826x over previous
#include <cuda_runtime.h>
#include <cuda_bf16.h>
#include <cuda_fp16.h>
#include <cstdint>
#include <cstddef>

// Problem constants
#define BB  4
#define SS  2048
#define DD  1024
#define HH  16
#define HDD 64
#define MTOK (BB*SS)          // 8192 token rows

// q prescale: HD^-0.5 * log2(e)  (softmax done in exp2 domain)
#define QSC 0.18033688011112042f

// Scratch (device globals; no allocations allowed)
__device__ __align__(128) __half g_xf[(size_t)MTOK * DD];            // x fp16
__device__ __align__(128) __half g_yf[(size_t)MTOK * DD];            // attn out fp16
__device__ __align__(128) __half g_wt_hi [(size_t)3 * DD * DD];      // W_attn^T fp16 hi
__device__ __align__(128) __half g_wt_lo [(size_t)3 * DD * DD];
__device__ __align__(128) __half g_wpt_hi[(size_t)DD * DD];
__device__ __align__(128) __half g_wpt_lo[(size_t)DD * DD];
#define BHSZ ((size_t)BB * HH * SS * HDD)
__device__ __align__(128) __half g_qf[BHSZ];                          // Q fp16
__device__ __align__(128) __half g_kf[BHSZ];                          // K fp16
__device__ __align__(128) __half g_vf[BHSZ];                          // V fp16

// ---------------------------------------------------------------------------
// Warp-MMA + async-copy helpers
// ---------------------------------------------------------------------------
__device__ __forceinline__ uint32_t smem_u32(const void* p) {
    uint32_t a;
    asm("{ .reg .u64 t; cvta.to.shared.u64 t, %1; cvt.u32.u64 %0, t; }"
        : "=r"(a) : "l"(p));
    return a;
}
__device__ __forceinline__ void ldsm_x4(uint32_t* r, uint32_t addr) {
    asm volatile("ldmatrix.sync.aligned.m8n8.x4.shared.b16 {%0,%1,%2,%3}, [%4];"
                 : "=r"(r[0]), "=r"(r[1]), "=r"(r[2]), "=r"(r[3]) : "r"(addr));
}
__device__ __forceinline__ void ldsm_x4_t(uint32_t* r, uint32_t addr) {
    asm volatile("ldmatrix.sync.aligned.m8n8.x4.trans.shared.b16 {%0,%1,%2,%3}, [%4];"
                 : "=r"(r[0]), "=r"(r[1]), "=r"(r[2]), "=r"(r[3]) : "r"(addr));
}
// fp16 mma
__device__ __forceinline__ void mma16816h(float* d, const uint32_t* a,
                                          const uint32_t b0, const uint32_t b1) {
    asm volatile(
        "mma.sync.aligned.m16n8k16.row.col.f32.f16.f16.f32 "
        "{%0,%1,%2,%3}, {%4,%5,%6,%7}, {%8,%9}, {%0,%1,%2,%3};"
        : "+f"(d[0]), "+f"(d[1]), "+f"(d[2]), "+f"(d[3])
        : "r"(a[0]), "r"(a[1]), "r"(a[2]), "r"(a[3]), "r"(b0), "r"(b1));
}
__device__ __forceinline__ void cp_async16(uint32_t saddr, const void* g) {
    asm volatile("cp.async.cg.shared.global [%0], [%1], 16;"
                 :: "r"(saddr), "l"(g) : "memory");
}
#define CP_COMMIT() asm volatile("cp.async.commit_group;" ::: "memory")
#define CP_WAIT(n)  asm volatile("cp.async.wait_group %0;" :: "n"(n) : "memory")

// packed f32x2 -> f16x2 (lo = a, hi = b)
__device__ __forceinline__ uint32_t cvt_h2(float a, float b) {
    uint32_t r;
    asm("cvt.rn.f16x2.f32 %0, %1, %2;" : "=r"(r) : "f"(b), "f"(a));
    return r;
}
__device__ __forceinline__ float ex2f(float x) {
    float r;
    asm("ex2.approx.f32 %0, %1;" : "=f"(r) : "f"(x));
    return r;
}

#define TS16 24   // GEMM BK=16 row stride (elems): 48B rows, conflict-free ldsm
#define KSTR 72   // attention tile row stride (144B rows, conflict-free)

// ---------------------------------------------------------------------------
// Elementwise fp32 -> fp16 convert (for x)
// ---------------------------------------------------------------------------
__global__ __launch_bounds__(256)
void convert_f16_kernel(const float* __restrict__ in, __half* __restrict__ of)
{
    size_t i = ((size_t)blockIdx.x * 256 + threadIdx.x) * 4;
    float4 v = *reinterpret_cast<const float4*>(in + i);
    uint2 hv;
    hv.x = cvt_h2(v.x, v.y);
    hv.y = cvt_h2(v.z, v.w);
    *reinterpret_cast<uint2*>(of + i) = hv;
}

// ---------------------------------------------------------------------------
// Transpose + fp16 hi/lo split of weights:  W[K,N] fp32 -> Th/Tl[N,K] fp16
// ---------------------------------------------------------------------------
__global__ __launch_bounds__(256)
void transpose_split_kernel(const float* __restrict__ W,
                            __half* __restrict__ Th,
                            __half* __restrict__ Tl,
                            int K, int N)
{
    __shared__ float tile[32][33];
    const int n0 = blockIdx.x * 32;
    const int k0 = blockIdx.y * 32;
    const int tx = threadIdx.x & 31;
    const int ty4 = (threadIdx.x >> 5) * 4;

    #pragma unroll
    for (int j = 0; j < 4; j++)
        tile[ty4 + j][tx] = W[(size_t)(k0 + ty4 + j) * N + n0 + tx];
    __syncthreads();
    #pragma unroll
    for (int j = 0; j < 4; j++) {
        float v = tile[tx][ty4 + j];
        __half hi = __float2half_rn(v);
        __half lo = __float2half_rn(v - __half2float(hi));
        size_t o = (size_t)(n0 + ty4 + j) * K + k0 + tx;
        Th[o] = hi;
        Tl[o] = lo;
    }
}

// ---------------------------------------------------------------------------
// Persistent tensor-core GEMM, fp16 2-pass (A single fp16, B = Bh+Bl fp16):
// BM=128, BN=128, BK=16, 256 threads, 2 CTA/SM, 4-stage continuous pipeline.
// MODE 0: fp32 C.  MODE 1 (QKV): q/k/v single fp16 per-head buffers.
// ---------------------------------------------------------------------------
#define A16_BYTES (128 * TS16 * 2)       // 6144 per array
#define S16_AF 0
#define S16_BH (1 * A16_BYTES)
#define S16_BL (2 * A16_BYTES)
#define S16_STG (3 * A16_BYTES)          // 18432 per stage
#define GEMM_SMEM (4 * S16_STG)          // 73728 (4 stages)

template <int MODE>
__global__ __launch_bounds__(256, 2)
void tc_gemm_kernel(const __half* __restrict__ Agf,
                    const __half* __restrict__ Bgh,
                    const __half* __restrict__ Bgl,
                    const float* __restrict__ bias,
                    float* __restrict__ C,
                    __half* __restrict__ oqf,
                    __half* __restrict__ okf,
                    __half* __restrict__ ovf,
                    int M, int N, int K)
{
    extern __shared__ __align__(16) char gsm[];
    const uint32_t sb = smem_u32(gsm);

    const int tid  = threadIdx.x;
    const int lane = tid & 31;
    const int wid  = tid >> 5;              // 0..7
    const int bid  = blockIdx.x;
    const int G    = gridDim.x;

    const int NX      = N >> 7;
    const int ntiles  = (M >> 7) * NX;
    const int nchunks = K >> 4;             // BK=16 (even)
    const int njobs   = (bid < ntiles) ? ((ntiles - bid + G - 1) / G) : 0;

    const int m_base = (wid >> 2) * 64;
    const int n_base = (wid & 3) * 32;

    const int a_r  = lane & 15;
    const int a_k  = (lane >> 4) * 8;
    const uint32_t af_rel = S16_AF + ((m_base + a_r) * TS16 + a_k) * 2;
    const int b_n  = (lane >> 4) * 8 + (lane & 7);
    const int b_k  = ((lane >> 3) & 1) * 8;
    const uint32_t bh_rel = S16_BH + ((n_base + b_n) * TS16 + b_k) * 2;
    const uint32_t bl_rel = S16_BL + ((n_base + b_n) * TS16 + b_k) * 2;

    const int cp_r  = tid >> 1;
    const int cp_k8 = (tid & 1) << 3;
    const uint32_t cp_sdo = (uint32_t)(cp_r * TS16 + cp_k8) * 2;

    int lj = 0, lc = 0, ls = 0;
    uint32_t goA = 0, goB = 0;
    if (njobs > 0) {
        int t = bid;
        int lby = t / NX, lbx = t - lby * NX;
        goA = (uint32_t)(lby * 128 + cp_r) * (uint32_t)K + cp_k8;
        goB = (uint32_t)(lbx * 128 + cp_r) * (uint32_t)K + cp_k8;
    }

    auto advance_load = [&]() {
        ls = (ls + 1) & 3;
        if (++lc == nchunks) {
            lc = 0; lj++;
            if (lj < njobs) {
                int t = bid + lj * G;
                int lby = t / NX, lbx = t - lby * NX;
                goA = (uint32_t)(lby * 128 + cp_r) * (uint32_t)K + cp_k8;
                goB = (uint32_t)(lbx * 128 + cp_r) * (uint32_t)K + cp_k8;
            }
        } else {
            goA += 16; goB += 16;
        }
    };

    #pragma unroll
    for (int i = 0; i < 2; i++) {
        if (lj < njobs) {
            const uint32_t so = sb + (uint32_t)ls * S16_STG;
            cp_async16(so + S16_AF + cp_sdo, Agf + goA);
            cp_async16(so + S16_BH + cp_sdo, Bgh + goB);
            cp_async16(so + S16_BL + cp_sdo, Bgl + goB);
        }
        CP_COMMIT();
        advance_load();
    }

    int cs = 0;
    for (int j = 0; j < njobs; j++) {
        const int tile_id = bid + j * G;
        const int by = tile_id / NX;
        const int bx = tile_id - by * NX;
        const int brow = by * 128;
        const int bcol = bx * 128;

        float acc[4][4][4];
        #pragma unroll
        for (int i = 0; i < 4; i++)
            #pragma unroll
            for (int jj = 0; jj < 4; jj++)
                #pragma unroll
                for (int r = 0; r < 4; r++) acc[i][jj][r] = 0.f;

        for (int cpair = 0; cpair < nchunks; cpair += 2) {
            CP_WAIT(0);
            __syncthreads();

            #pragma unroll
            for (int u = 0; u < 2; u++) {
                const bool lvalid = (lj < njobs);
                const uint32_t so_l = sb + (uint32_t)ls * S16_STG;
                const uint32_t lga = goA, lgb = goB;

                const uint32_t so = sb + (uint32_t)cs * S16_STG;
                uint32_t af[4][4], bh[2][4], bl[2][4];

                // pass 1: A x Bhi
                #pragma unroll
                for (int mt = 0; mt < 4; mt++)
                    ldsm_x4(af[mt], so + af_rel + mt * (16 * TS16 * 2));
                #pragma unroll
                for (int p = 0; p < 2; p++)
                    ldsm_x4(bh[p], so + bh_rel + p * (16 * TS16 * 2));
                #pragma unroll
                for (int mt = 0; mt < 4; mt++)
                    #pragma unroll
                    for (int nt = 0; nt < 4; nt++) {
                        const int p = nt >> 1, hx = (nt & 1) * 2;
                        mma16816h(acc[mt][nt], af[mt], bh[p][hx], bh[p][hx + 1]);
                    }
                if (lvalid)
                    cp_async16(so_l + S16_AF + cp_sdo, Agf + lga);

                // pass 2: A x Blo
                #pragma unroll
                for (int p = 0; p < 2; p++)
                    ldsm_x4(bl[p], so + bl_rel + p * (16 * TS16 * 2));
                #pragma unroll
                for (int mt = 0; mt < 4; mt++)
                    #pragma unroll
                    for (int nt = 0; nt < 4; nt++) {
                        const int p = nt >> 1, hx = (nt & 1) * 2;
                        mma16816h(acc[mt][nt], af[mt], bl[p][hx], bl[p][hx + 1]);
                    }
                if (lvalid) {
                    cp_async16(so_l + S16_BH + cp_sdo, Bgh + lgb);
                    cp_async16(so_l + S16_BL + cp_sdo, Bgl + lgb);
                }

                CP_COMMIT();
                advance_load();
                cs = (cs + 1) & 3;
            }
        }

        // --- epilogue ---
        #pragma unroll
        for (int nt = 0; nt < 4; nt++) {
            const int ncol = bcol + n_base + nt * 8 + (lane & 3) * 2;
            float2 bv = *reinterpret_cast<const float2*>(&bias[ncol]);
            if (MODE == 0) {
                #pragma unroll
                for (int mt = 0; mt < 4; mt++) {
                    int row0 = brow + m_base + mt * 16 + (lane >> 2);
                    float2 v0, v1;
                    v0.x = acc[mt][nt][0] + bv.x;  v0.y = acc[mt][nt][1] + bv.y;
                    v1.x = acc[mt][nt][2] + bv.x;  v1.y = acc[mt][nt][3] + bv.y;
                    *reinterpret_cast<float2*>(&C[(size_t)row0 * N + ncol]) = v0;
                    *reinterpret_cast<float2*>(&C[(size_t)(row0 + 8) * N + ncol]) = v1;
                }
            } else {
                const int region = ncol >> 10;          // 0:q 1:k 2:v
                const int hh = (ncol >> 6) & (HH - 1);
                const int dd = ncol & (HDD - 1);
                const float sc = (region == 0) ? QSC : 1.f;
                __half* dst = (region == 0) ? oqf : (region == 1) ? okf : ovf;
                const size_t colbase = (size_t)hh * (SS * HDD) + dd;
                #pragma unroll
                for (int mt = 0; mt < 4; mt++) {
                    int row0 = brow + m_base + mt * 16 + (lane >> 2);
                    #pragma unroll
                    for (int rr = 0; rr < 2; rr++) {
                        int row = row0 + rr * 8;
                        float v0 = (acc[mt][nt][rr * 2 + 0] + bv.x) * sc;
                        float v1 = (acc[mt][nt][rr * 2 + 1] + bv.y) * sc;
                        int bb = row >> 11, ss = row & (SS - 1);
                        size_t off = (size_t)bb * HH * SS * HDD + colbase + (size_t)ss * HDD;
                        *reinterpret_cast<uint32_t*>(&dst[off]) = cvt_h2(v0, v1);
                    }
                }
            }
        }
    }
}

// ---------------------------------------------------------------------------
// Tensor-core causal flash attention, all-fp16 (Q,K,V,P single):
// S = Qf x Kf^T (1 pass);  O += Pf x Vf (1 pass).
// BM=128 (8 warps, 256 threads), cp.async 2-stage K/V ring (64 keys/tile).
// ---------------------------------------------------------------------------
#define FS_KF   0
#define FS_VF   9216
#define FS_STG  18432
#define FS_TOTAL (2 * FS_STG)          // 36864

__global__ __launch_bounds__(256, 2)
void flash_attn_tc(const __half* __restrict__ Qf,
                   const __half* __restrict__ Kf,
                   const __half* __restrict__ Vf,
                   __half* __restrict__ yf)
{
    extern __shared__ __align__(16) char sm[];
    const uint32_t sbase = smem_u32(sm);

    const int tid  = threadIdx.x;
    const int lane = tid & 31;
    const int w    = tid >> 5;
    const int qtile = (gridDim.x - 1) - blockIdx.x;
    const int h = blockIdx.y;
    const int b = blockIdx.z;
    const size_t base = ((size_t)(b * HH + h)) * SS * HDD;

    // ---- stage Q (fp16) through both ring stages, build frags ----
    {
        const int s0 = qtile * 128;
        #pragma unroll
        for (int i = 0; i < 4; i++) {
            int idx = i * 256 + tid;
            int r  = idx >> 3;
            int c8 = (idx & 7) * 8;
            *reinterpret_cast<uint4*>(sm + (uint32_t)(r * KSTR + c8) * 2) =
                *reinterpret_cast<const uint4*>(&Qf[base + (size_t)(s0 + r) * HDD + c8]);
        }
    }
    __syncthreads();

    uint32_t qf[4][4];
    {
        const uint32_t qa = sbase +
            ((w * 16 + (lane & 15)) * KSTR + (lane >> 4) * 8) * 2;
        #pragma unroll
        for (int kc = 0; kc < 4; kc++) ldsm_x4(qf[kc], qa + kc * 32);
    }
    __syncthreads();   // Q staging dead; ring reusable

    const uint32_t ka_rel = (((lane >> 4) * 8 + (lane & 7)) * KSTR +
                             ((lane >> 3) & 1) * 8) * 2;
    const uint32_t va_rel = ((((lane >> 3) & 1) * 8 + (lane & 7)) * KSTR +
                             ((lane >> 4) & 1) * 8) * 2;

    // per-thread copy mapping (2 x 16B per array per tile)
    int cg_r[2], cg_c8[2]; uint32_t cg_so[2];
    #pragma unroll
    for (int ii = 0; ii < 2; ii++) {
        int j  = ii * 256 + tid;
        cg_r[ii]  = j >> 3;
        cg_c8[ii] = (j & 7) * 8;
        cg_so[ii] = (uint32_t)(cg_r[ii] * KSTR + cg_c8[ii]) * 2;
    }

    float o[8][4];
    #pragma unroll
    for (int j = 0; j < 8; j++)
        #pragma unroll
        for (int r = 0; r < 4; r++) o[j][r] = 0.f;
    float m0 = -1e30f, m1 = -1e30f, l0 = 0.f, l1 = 0.f;

    const int row_a0 = qtile * 128 + w * 16 + (lane >> 2);
    const int num_kv = 2 * qtile + 2;

    // prologue: tile 0 into stage 0
    {
        const uint32_t sa = sbase;
        #pragma unroll
        for (int ii = 0; ii < 2; ii++) {
            size_t g = base + (size_t)cg_r[ii] * HDD + cg_c8[ii];
            cp_async16(sa + FS_KF + cg_so[ii], Kf + g);
            cp_async16(sa + FS_VF + cg_so[ii], Vf + g);
        }
        CP_COMMIT();
    }

    for (int t = 0; t < num_kv; t++) {
        CP_WAIT(0);
        __syncthreads();

        const bool pre = (t + 1 < num_kv);
        const uint32_t sa_n = sbase + (uint32_t)((t + 1) & 1) * FS_STG;
        const size_t gb_n = base + (size_t)(t + 1) * 64 * HDD;

        const uint32_t sa = sbase + (uint32_t)(t & 1) * FS_STG;
        const uint32_t ka = sa + FS_KF + ka_rel;
        const uint32_t va = sa + FS_VF + va_rel;

        // ---- S = Qf Kf^T ----
        float s[8][4];
        #pragma unroll
        for (int j = 0; j < 8; j++)
            #pragma unroll
            for (int r = 0; r < 4; r++) s[j][r] = 0.f;

        #pragma unroll
        for (int kc = 0; kc < 4; kc++) {
            #pragma unroll
            for (int np = 0; np < 4; np++) {
                uint32_t kf4[4];
                ldsm_x4(kf4, ka + np * (16 * KSTR * 2) + kc * 32);
                mma16816h(s[2*np],   qf[kc], kf4[0], kf4[1]);
                mma16816h(s[2*np+1], qf[kc], kf4[2], kf4[3]);
            }
            // interleaved prefetch of tile t+1 (K at kc==0, V at kc==2)
            if (kc == 0 && pre) {
                #pragma unroll
                for (int ii = 0; ii < 2; ii++) {
                    size_t g = gb_n + (size_t)cg_r[ii] * HDD + cg_c8[ii];
                    cp_async16(sa_n + FS_KF + cg_so[ii], Kf + g);
                }
            }
            if (kc == 2 && pre) {
                #pragma unroll
                for (int ii = 0; ii < 2; ii++) {
                    size_t g = gb_n + (size_t)cg_r[ii] * HDD + cg_c8[ii];
                    cp_async16(sa_n + FS_VF + cg_so[ii], Vf + g);
                }
            }
        }
        CP_COMMIT();

        if (t >= 2 * qtile) {
            #pragma unroll
            for (int j = 0; j < 8; j++) {
                int col = t * 64 + j * 8 + (lane & 3) * 2;
                #pragma unroll
                for (int r = 0; r < 4; r++) {
                    int cc = col + (r & 1);
                    int rw = row_a0 + ((r >= 2) ? 8 : 0);
                    if (cc > rw) s[j][r] = -1e30f;
                }
            }
        }

        float mx0 = -1e30f, mx1 = -1e30f;
        #pragma unroll
        for (int j = 0; j < 8; j++) {
            mx0 = fmaxf(mx0, fmaxf(s[j][0], s[j][1]));
            mx1 = fmaxf(mx1, fmaxf(s[j][2], s[j][3]));
        }
        mx0 = fmaxf(mx0, __shfl_xor_sync(0xffffffffu, mx0, 1));
        mx0 = fmaxf(mx0, __shfl_xor_sync(0xffffffffu, mx0, 2));
        mx1 = fmaxf(mx1, __shfl_xor_sync(0xffffffffu, mx1, 1));
        mx1 = fmaxf(mx1, __shfl_xor_sync(0xffffffffu, mx1, 2));
        float mn0 = fmaxf(m0, mx0), mn1 = fmaxf(m1, mx1);
        float sc0 = ex2f(m0 - mn0), sc1 = ex2f(m1 - mn1);
        m0 = mn0; m1 = mn1;
        l0 *= sc0; l1 *= sc1;
        #pragma unroll
        for (int j = 0; j < 8; j++) {
            o[j][0] *= sc0; o[j][1] *= sc0;
            o[j][2] *= sc1; o[j][3] *= sc1;
        }
        #pragma unroll
        for (int j = 0; j < 8; j++) {
            float p0 = ex2f(s[j][0] - mn0);
            float p1 = ex2f(s[j][1] - mn0);
            float p2 = ex2f(s[j][2] - mn1);
            float p3 = ex2f(s[j][3] - mn1);
            s[j][0] = p0; s[j][1] = p1; s[j][2] = p2; s[j][3] = p3;
            l0 += p0 + p1;
            l1 += p2 + p3;
        }

        // ---- O += Pf Vf ----
        #pragma unroll
        for (int kc = 0; kc < 4; kc++) {
            uint32_t pf[4];
            #pragma unroll
            for (int t2 = 0; t2 < 2; t2++) {
                int j = 2 * kc + t2;
                pf[t2*2 + 0] = cvt_h2(s[j][0], s[j][1]);
                pf[t2*2 + 1] = cvt_h2(s[j][2], s[j][3]);
            }
            #pragma unroll
            for (int nb = 0; nb < 4; nb++) {
                uint32_t vf4[4];
                ldsm_x4_t(vf4, va + kc * (16 * KSTR * 2) + nb * 32);
                mma16816h(o[2*nb],   pf, vf4[0], vf4[1]);
                mma16816h(o[2*nb+1], pf, vf4[2], vf4[3]);
            }
        }
    }

    l0 += __shfl_xor_sync(0xffffffffu, l0, 1);
    l0 += __shfl_xor_sync(0xffffffffu, l0, 2);
    l1 += __shfl_xor_sync(0xffffffffu, l1, 1);
    l1 += __shfl_xor_sync(0xffffffffu, l1, 2);
    float inv0 = 1.f / l0, inv1 = 1.f / l1;

    // epilogue: write single fp16 y (row-major [8192, 1024])
    size_t tok0 = (size_t)b * SS + row_a0;
    size_t o0 = tok0 * DD + h * HDD + (lane & 3) * 2;
    size_t o1 = o0 + (size_t)8 * DD;
    #pragma unroll
    for (int j = 0; j < 8; j++) {
        *reinterpret_cast<uint32_t*>(&yf[o0 + j * 8]) =
            cvt_h2(o[j][0] * inv0, o[j][1] * inv0);
        *reinterpret_cast<uint32_t*>(&yf[o1 + j * 8]) =
            cvt_h2(o[j][2] * inv1, o[j][3] * inv1);
    }
}

// ---------------------------------------------------------------------------
// Launch
// ---------------------------------------------------------------------------
extern "C" void kernel_launch(void* const* d_in, const int* in_sizes, int n_in,
                              void* d_out, int out_size)
{
    const float* x      = (const float*)d_in[0];
    const float* W_attn = (const float*)d_in[1];
    const float* b_attn = (const float*)d_in[2];
    const float* W_proj = (const float*)d_in[3];
    const float* b_proj = (const float*)d_in[4];
    float* out = (float*)d_out;

    static __half *xf = nullptr, *yf;
    static __half *wt_hi, *wt_lo, *wpt_hi, *wpt_lo;
    static __half *qf, *kf, *vf;
    static int gemm_grid = 0;
    if (!xf) {   // first (non-captured) correctness call
        cudaGetSymbolAddress((void**)&xf, g_xf);
        cudaGetSymbolAddress((void**)&yf, g_yf);
        cudaGetSymbolAddress((void**)&wt_hi,  g_wt_hi);
        cudaGetSymbolAddress((void**)&wt_lo,  g_wt_lo);
        cudaGetSymbolAddress((void**)&wpt_hi, g_wpt_hi);
        cudaGetSymbolAddress((void**)&wpt_lo, g_wpt_lo);
        cudaGetSymbolAddress((void**)&qf, g_qf);
        cudaGetSymbolAddress((void**)&kf, g_kf);
        cudaGetSymbolAddress((void**)&vf, g_vf);
        cudaFuncSetAttribute(flash_attn_tc,
                             cudaFuncAttributeMaxDynamicSharedMemorySize,
                             FS_TOTAL);
        cudaFuncSetAttribute(tc_gemm_kernel<0>,
                             cudaFuncAttributeMaxDynamicSharedMemorySize,
                             GEMM_SMEM);
        cudaFuncSetAttribute(tc_gemm_kernel<1>,
                             cudaFuncAttributeMaxDynamicSharedMemorySize,
                             GEMM_SMEM);
        cudaDeviceProp prop;
        cudaGetDeviceProperties(&prop, 0);
        gemm_grid = prop.multiProcessorCount * 2;   // persistent: 2 CTAs/SM
    }

    // 0a) convert x -> fp16
    convert_f16_kernel<<<(MTOK * DD) / (256 * 4), 256>>>(x, xf);
    // 0b) transpose + fp16 hi/lo split weights
    {
        dim3 g1(3 * DD / 32, DD / 32);
        transpose_split_kernel<<<g1, 256>>>(W_attn, wt_hi, wt_lo, DD, 3 * DD);
        dim3 g2(DD / 32, DD / 32);
        transpose_split_kernel<<<g2, 256>>>(W_proj, wpt_hi, wpt_lo, DD, DD);
    }

    // 1) QKV GEMM (persistent, fp16 2-pass) + fused epilogue -> qf,kf,vf
    tc_gemm_kernel<1><<<gemm_grid, 256, GEMM_SMEM>>>(
        xf, wt_hi, wt_lo, b_attn, nullptr,
        qf, kf, vf, MTOK, 3 * DD, DD);

    // 2) all-fp16 tensor-core causal flash attention -> fp16 y
    {
        dim3 grid(SS / 128, HH, BB);
        flash_attn_tc<<<grid, 256, FS_TOTAL>>>(qf, kf, vf, yf);
    }

    // 3) output projection (persistent, fp16 2-pass) -> out
    tc_gemm_kernel<0><<<gemm_grid, 256, GEMM_SMEM>>>(
        yf, wpt_hi, wpt_lo, b_proj, out,
        nullptr, nullptr, nullptr,
        MTOK, DD, DD);
}

// round 14
// speedup vs baseline: 2.2284x; 1.2395x over previous
#include <cuda_runtime.h>
#include <cuda_bf16.h>
#include <cuda_fp16.h>
#include <cstdint>
#include <cstddef>

// Problem constants
#define BB  4
#define SS  2048
#define DD  1024
#define HH  16
#define HDD 64
#define MTOK (BB*SS)          // 8192 token rows

// q prescale: HD^-0.5 * log2(e)  (softmax done in exp2 domain)
#define QSC 0.18033688011112042f

// Scratch (device globals; no allocations allowed)
__device__ __align__(128) __half g_xf[(size_t)MTOK * DD];            // x fp16
__device__ __align__(128) __half g_yf[(size_t)MTOK * DD];            // attn out fp16
__device__ __align__(128) __half g_wt [(size_t)3 * DD * DD];         // W_attn^T fp16
__device__ __align__(128) __half g_wpt[(size_t)DD * DD];             // W_proj^T fp16
#define BHSZ ((size_t)BB * HH * SS * HDD)
__device__ __align__(128) __half g_qf[BHSZ];                          // Q fp16
__device__ __align__(128) __half g_kf[BHSZ];                          // K fp16
__device__ __align__(128) __half g_vf[BHSZ];                          // V fp16

// ---------------------------------------------------------------------------
// Warp-MMA + async-copy helpers
// ---------------------------------------------------------------------------
__device__ __forceinline__ uint32_t smem_u32(const void* p) {
    uint32_t a;
    asm("{ .reg .u64 t; cvta.to.shared.u64 t, %1; cvt.u32.u64 %0, t; }"
        : "=r"(a) : "l"(p));
    return a;
}
__device__ __forceinline__ void ldsm_x4(uint32_t* r, uint32_t addr) {
    asm volatile("ldmatrix.sync.aligned.m8n8.x4.shared.b16 {%0,%1,%2,%3}, [%4];"
                 : "=r"(r[0]), "=r"(r[1]), "=r"(r[2]), "=r"(r[3]) : "r"(addr));
}
__device__ __forceinline__ void ldsm_x4_t(uint32_t* r, uint32_t addr) {
    asm volatile("ldmatrix.sync.aligned.m8n8.x4.trans.shared.b16 {%0,%1,%2,%3}, [%4];"
                 : "=r"(r[0]), "=r"(r[1]), "=r"(r[2]), "=r"(r[3]) : "r"(addr));
}
// fp16 mma
__device__ __forceinline__ void mma16816h(float* d, const uint32_t* a,
                                          const uint32_t b0, const uint32_t b1) {
    asm volatile(
        "mma.sync.aligned.m16n8k16.row.col.f32.f16.f16.f32 "
        "{%0,%1,%2,%3}, {%4,%5,%6,%7}, {%8,%9}, {%0,%1,%2,%3};"
        : "+f"(d[0]), "+f"(d[1]), "+f"(d[2]), "+f"(d[3])
        : "r"(a[0]), "r"(a[1]), "r"(a[2]), "r"(a[3]), "r"(b0), "r"(b1));
}
__device__ __forceinline__ void cp_async16(uint32_t saddr, const void* g) {
    asm volatile("cp.async.cg.shared.global [%0], [%1], 16;"
                 :: "r"(saddr), "l"(g) : "memory");
}
#define CP_COMMIT() asm volatile("cp.async.commit_group;" ::: "memory")
#define CP_WAIT(n)  asm volatile("cp.async.wait_group %0;" :: "n"(n) : "memory")

// packed f32x2 -> f16x2 (lo = a, hi = b)
__device__ __forceinline__ uint32_t cvt_h2(float a, float b) {
    uint32_t r;
    asm("cvt.rn.f16x2.f32 %0, %1, %2;" : "=r"(r) : "f"(b), "f"(a));
    return r;
}
__device__ __forceinline__ float ex2f(float x) {
    float r;
    asm("ex2.approx.f32 %0, %1;" : "=f"(r) : "f"(x));
    return r;
}

#define TS16 24   // GEMM BK=16 row stride (elems): 48B rows, conflict-free ldsm
#define KSTR 72   // attention tile row stride (144B rows, conflict-free)

// ---------------------------------------------------------------------------
// Elementwise fp32 -> fp16 convert (for x)
// ---------------------------------------------------------------------------
__global__ __launch_bounds__(256)
void convert_f16_kernel(const float* __restrict__ in, __half* __restrict__ of)
{
    size_t i = ((size_t)blockIdx.x * 256 + threadIdx.x) * 4;
    float4 v = *reinterpret_cast<const float4*>(in + i);
    uint2 hv;
    hv.x = cvt_h2(v.x, v.y);
    hv.y = cvt_h2(v.z, v.w);
    *reinterpret_cast<uint2*>(of + i) = hv;
}

// ---------------------------------------------------------------------------
// Transpose + fp16 convert of weights:  W[K,N] fp32 -> T[N,K] fp16
// ---------------------------------------------------------------------------
__global__ __launch_bounds__(256)
void transpose_f16_kernel(const float* __restrict__ W,
                          __half* __restrict__ T,
                          int K, int N)
{
    __shared__ float tile[32][33];
    const int n0 = blockIdx.x * 32;
    const int k0 = blockIdx.y * 32;
    const int tx = threadIdx.x & 31;
    const int ty4 = (threadIdx.x >> 5) * 4;

    #pragma unroll
    for (int j = 0; j < 4; j++)
        tile[ty4 + j][tx] = W[(size_t)(k0 + ty4 + j) * N + n0 + tx];
    __syncthreads();
    #pragma unroll
    for (int j = 0; j < 4; j++) {
        float v = tile[tx][ty4 + j];
        T[(size_t)(n0 + ty4 + j) * K + k0 + tx] = __float2half_rn(v);
    }
}

// ---------------------------------------------------------------------------
// Persistent tensor-core GEMM, plain fp16 1-pass (A fp16, B fp16):
// BM=128, BN=128, BK=16, 256 threads, 2 CTA/SM, 4-stage continuous pipeline.
// MODE 0: fp32 C.  MODE 1 (QKV): q/k/v single fp16 per-head buffers.
// ---------------------------------------------------------------------------
#define A16_BYTES (128 * TS16 * 2)       // 6144 per array
#define S16_AF 0
#define S16_BF (1 * A16_BYTES)
#define S16_STG (2 * A16_BYTES)          // 12288 per stage
#define GEMM_SMEM (4 * S16_STG)          // 49152 (4 stages)

template <int MODE>
__global__ __launch_bounds__(256, 2)
void tc_gemm_kernel(const __half* __restrict__ Agf,
                    const __half* __restrict__ Bgf,
                    const float* __restrict__ bias,
                    float* __restrict__ C,
                    __half* __restrict__ oqf,
                    __half* __restrict__ okf,
                    __half* __restrict__ ovf,
                    int M, int N, int K)
{
    extern __shared__ __align__(16) char gsm[];
    const uint32_t sb = smem_u32(gsm);

    const int tid  = threadIdx.x;
    const int lane = tid & 31;
    const int wid  = tid >> 5;              // 0..7
    const int bid  = blockIdx.x;
    const int G    = gridDim.x;

    const int NX      = N >> 7;
    const int ntiles  = (M >> 7) * NX;
    const int nchunks = K >> 4;             // BK=16 (even)
    const int njobs   = (bid < ntiles) ? ((ntiles - bid + G - 1) / G) : 0;

    const int m_base = (wid >> 2) * 64;
    const int n_base = (wid & 3) * 32;

    const int a_r  = lane & 15;
    const int a_k  = (lane >> 4) * 8;
    const uint32_t af_rel = S16_AF + ((m_base + a_r) * TS16 + a_k) * 2;
    const int b_n  = (lane >> 4) * 8 + (lane & 7);
    const int b_k  = ((lane >> 3) & 1) * 8;
    const uint32_t bf_rel = S16_BF + ((n_base + b_n) * TS16 + b_k) * 2;

    const int cp_r  = tid >> 1;
    const int cp_k8 = (tid & 1) << 3;
    const uint32_t cp_sdo = (uint32_t)(cp_r * TS16 + cp_k8) * 2;

    int lj = 0, lc = 0, ls = 0;
    uint32_t goA = 0, goB = 0;
    if (njobs > 0) {
        int t = bid;
        int lby = t / NX, lbx = t - lby * NX;
        goA = (uint32_t)(lby * 128 + cp_r) * (uint32_t)K + cp_k8;
        goB = (uint32_t)(lbx * 128 + cp_r) * (uint32_t)K + cp_k8;
    }

    auto advance_load = [&]() {
        ls = (ls + 1) & 3;
        if (++lc == nchunks) {
            lc = 0; lj++;
            if (lj < njobs) {
                int t = bid + lj * G;
                int lby = t / NX, lbx = t - lby * NX;
                goA = (uint32_t)(lby * 128 + cp_r) * (uint32_t)K + cp_k8;
                goB = (uint32_t)(lbx * 128 + cp_r) * (uint32_t)K + cp_k8;
            }
        } else {
            goA += 16; goB += 16;
        }
    };

    #pragma unroll
    for (int i = 0; i < 2; i++) {
        if (lj < njobs) {
            const uint32_t so = sb + (uint32_t)ls * S16_STG;
            cp_async16(so + S16_AF + cp_sdo, Agf + goA);
            cp_async16(so + S16_BF + cp_sdo, Bgf + goB);
        }
        CP_COMMIT();
        advance_load();
    }

    int cs = 0;
    for (int j = 0; j < njobs; j++) {
        const int tile_id = bid + j * G;
        const int by = tile_id / NX;
        const int bx = tile_id - by * NX;
        const int brow = by * 128;
        const int bcol = bx * 128;

        float acc[4][4][4];
        #pragma unroll
        for (int i = 0; i < 4; i++)
            #pragma unroll
            for (int jj = 0; jj < 4; jj++)
                #pragma unroll
                for (int r = 0; r < 4; r++) acc[i][jj][r] = 0.f;

        for (int cpair = 0; cpair < nchunks; cpair += 2) {
            CP_WAIT(0);
            __syncthreads();

            #pragma unroll
            for (int u = 0; u < 2; u++) {
                const bool lvalid = (lj < njobs);
                const uint32_t so_l = sb + (uint32_t)ls * S16_STG;
                const uint32_t lga = goA, lgb = goB;

                const uint32_t so = sb + (uint32_t)cs * S16_STG;
                uint32_t af[4][4], bf[2][4];

                #pragma unroll
                for (int mt = 0; mt < 4; mt++)
                    ldsm_x4(af[mt], so + af_rel + mt * (16 * TS16 * 2));
                #pragma unroll
                for (int p = 0; p < 2; p++)
                    ldsm_x4(bf[p], so + bf_rel + p * (16 * TS16 * 2));
                // single pass: A x B  (16 MMAs)
                #pragma unroll
                for (int mt = 0; mt < 4; mt++)
                    #pragma unroll
                    for (int nt = 0; nt < 4; nt++) {
                        const int p = nt >> 1, hx = (nt & 1) * 2;
                        mma16816h(acc[mt][nt], af[mt], bf[p][hx], bf[p][hx + 1]);
                    }
                if (lvalid) {
                    cp_async16(so_l + S16_AF + cp_sdo, Agf + lga);
                    cp_async16(so_l + S16_BF + cp_sdo, Bgf + lgb);
                }

                CP_COMMIT();
                advance_load();
                cs = (cs + 1) & 3;
            }
        }

        // --- epilogue ---
        #pragma unroll
        for (int nt = 0; nt < 4; nt++) {
            const int ncol = bcol + n_base + nt * 8 + (lane & 3) * 2;
            float2 bv = *reinterpret_cast<const float2*>(&bias[ncol]);
            if (MODE == 0) {
                #pragma unroll
                for (int mt = 0; mt < 4; mt++) {
                    int row0 = brow + m_base + mt * 16 + (lane >> 2);
                    float2 v0, v1;
                    v0.x = acc[mt][nt][0] + bv.x;  v0.y = acc[mt][nt][1] + bv.y;
                    v1.x = acc[mt][nt][2] + bv.x;  v1.y = acc[mt][nt][3] + bv.y;
                    *reinterpret_cast<float2*>(&C[(size_t)row0 * N + ncol]) = v0;
                    *reinterpret_cast<float2*>(&C[(size_t)(row0 + 8) * N + ncol]) = v1;
                }
            } else {
                const int region = ncol >> 10;          // 0:q 1:k 2:v
                const int hh = (ncol >> 6) & (HH - 1);
                const int dd = ncol & (HDD - 1);
                const float sc = (region == 0) ? QSC : 1.f;
                __half* dst = (region == 0) ? oqf : (region == 1) ? okf : ovf;
                const size_t colbase = (size_t)hh * (SS * HDD) + dd;
                #pragma unroll
                for (int mt = 0; mt < 4; mt++) {
                    int row0 = brow + m_base + mt * 16 + (lane >> 2);
                    #pragma unroll
                    for (int rr = 0; rr < 2; rr++) {
                        int row = row0 + rr * 8;
                        float v0 = (acc[mt][nt][rr * 2 + 0] + bv.x) * sc;
                        float v1 = (acc[mt][nt][rr * 2 + 1] + bv.y) * sc;
                        int bb = row >> 11, ss = row & (SS - 1);
                        size_t off = (size_t)bb * HH * SS * HDD + colbase + (size_t)ss * HDD;
                        *reinterpret_cast<uint32_t*>(&dst[off]) = cvt_h2(v0, v1);
                    }
                }
            }
        }
    }
}

// ---------------------------------------------------------------------------
// Tensor-core causal flash attention, all-fp16 (as R13):
// S = Qf x Kf^T (1 pass);  O += Pf x Vf (1 pass).
// BM=128 (8 warps, 256 threads), cp.async 2-stage K/V ring (64 keys/tile).
// ---------------------------------------------------------------------------
#define FS_KF   0
#define FS_VF   9216
#define FS_STG  18432
#define FS_TOTAL (2 * FS_STG)          // 36864

__global__ __launch_bounds__(256, 2)
void flash_attn_tc(const __half* __restrict__ Qf,
                   const __half* __restrict__ Kf,
                   const __half* __restrict__ Vf,
                   __half* __restrict__ yf)
{
    extern __shared__ __align__(16) char sm[];
    const uint32_t sbase = smem_u32(sm);

    const int tid  = threadIdx.x;
    const int lane = tid & 31;
    const int w    = tid >> 5;
    const int qtile = (gridDim.x - 1) - blockIdx.x;
    const int h = blockIdx.y;
    const int b = blockIdx.z;
    const size_t base = ((size_t)(b * HH + h)) * SS * HDD;

    // ---- stage Q (fp16) through ring stage 0, build frags ----
    {
        const int s0 = qtile * 128;
        #pragma unroll
        for (int i = 0; i < 4; i++) {
            int idx = i * 256 + tid;
            int r  = idx >> 3;
            int c8 = (idx & 7) * 8;
            *reinterpret_cast<uint4*>(sm + (uint32_t)(r * KSTR + c8) * 2) =
                *reinterpret_cast<const uint4*>(&Qf[base + (size_t)(s0 + r) * HDD + c8]);
        }
    }
    __syncthreads();

    uint32_t qf[4][4];
    {
        const uint32_t qa = sbase +
            ((w * 16 + (lane & 15)) * KSTR + (lane >> 4) * 8) * 2;
        #pragma unroll
        for (int kc = 0; kc < 4; kc++) ldsm_x4(qf[kc], qa + kc * 32);
    }
    __syncthreads();   // Q staging dead; ring reusable

    const uint32_t ka_rel = (((lane >> 4) * 8 + (lane & 7)) * KSTR +
                             ((lane >> 3) & 1) * 8) * 2;
    const uint32_t va_rel = ((((lane >> 3) & 1) * 8 + (lane & 7)) * KSTR +
                             ((lane >> 4) & 1) * 8) * 2;

    int cg_r[2], cg_c8[2]; uint32_t cg_so[2];
    #pragma unroll
    for (int ii = 0; ii < 2; ii++) {
        int j  = ii * 256 + tid;
        cg_r[ii]  = j >> 3;
        cg_c8[ii] = (j & 7) * 8;
        cg_so[ii] = (uint32_t)(cg_r[ii] * KSTR + cg_c8[ii]) * 2;
    }

    float o[8][4];
    #pragma unroll
    for (int j = 0; j < 8; j++)
        #pragma unroll
        for (int r = 0; r < 4; r++) o[j][r] = 0.f;
    float m0 = -1e30f, m1 = -1e30f, l0 = 0.f, l1 = 0.f;

    const int row_a0 = qtile * 128 + w * 16 + (lane >> 2);
    const int num_kv = 2 * qtile + 2;

    {
        const uint32_t sa = sbase;
        #pragma unroll
        for (int ii = 0; ii < 2; ii++) {
            size_t g = base + (size_t)cg_r[ii] * HDD + cg_c8[ii];
            cp_async16(sa + FS_KF + cg_so[ii], Kf + g);
            cp_async16(sa + FS_VF + cg_so[ii], Vf + g);
        }
        CP_COMMIT();
    }

    for (int t = 0; t < num_kv; t++) {
        CP_WAIT(0);
        __syncthreads();

        const bool pre = (t + 1 < num_kv);
        const uint32_t sa_n = sbase + (uint32_t)((t + 1) & 1) * FS_STG;
        const size_t gb_n = base + (size_t)(t + 1) * 64 * HDD;

        const uint32_t sa = sbase + (uint32_t)(t & 1) * FS_STG;
        const uint32_t ka = sa + FS_KF + ka_rel;
        const uint32_t va = sa + FS_VF + va_rel;

        float s[8][4];
        #pragma unroll
        for (int j = 0; j < 8; j++)
            #pragma unroll
            for (int r = 0; r < 4; r++) s[j][r] = 0.f;

        #pragma unroll
        for (int kc = 0; kc < 4; kc++) {
            #pragma unroll
            for (int np = 0; np < 4; np++) {
                uint32_t kf4[4];
                ldsm_x4(kf4, ka + np * (16 * KSTR * 2) + kc * 32);
                mma16816h(s[2*np],   qf[kc], kf4[0], kf4[1]);
                mma16816h(s[2*np+1], qf[kc], kf4[2], kf4[3]);
            }
            if (kc == 0 && pre) {
                #pragma unroll
                for (int ii = 0; ii < 2; ii++) {
                    size_t g = gb_n + (size_t)cg_r[ii] * HDD + cg_c8[ii];
                    cp_async16(sa_n + FS_KF + cg_so[ii], Kf + g);
                }
            }
            if (kc == 2 && pre) {
                #pragma unroll
                for (int ii = 0; ii < 2; ii++) {
                    size_t g = gb_n + (size_t)cg_r[ii] * HDD + cg_c8[ii];
                    cp_async16(sa_n + FS_VF + cg_so[ii], Vf + g);
                }
            }
        }
        CP_COMMIT();

        if (t >= 2 * qtile) {
            #pragma unroll
            for (int j = 0; j < 8; j++) {
                int col = t * 64 + j * 8 + (lane & 3) * 2;
                #pragma unroll
                for (int r = 0; r < 4; r++) {
                    int cc = col + (r & 1);
                    int rw = row_a0 + ((r >= 2) ? 8 : 0);
                    if (cc > rw) s[j][r] = -1e30f;
                }
            }
        }

        float mx0 = -1e30f, mx1 = -1e30f;
        #pragma unroll
        for (int j = 0; j < 8; j++) {
            mx0 = fmaxf(mx0, fmaxf(s[j][0], s[j][1]));
            mx1 = fmaxf(mx1, fmaxf(s[j][2], s[j][3]));
        }
        mx0 = fmaxf(mx0, __shfl_xor_sync(0xffffffffu, mx0, 1));
        mx0 = fmaxf(mx0, __shfl_xor_sync(0xffffffffu, mx0, 2));
        mx1 = fmaxf(mx1, __shfl_xor_sync(0xffffffffu, mx1, 1));
        mx1 = fmaxf(mx1, __shfl_xor_sync(0xffffffffu, mx1, 2));
        float mn0 = fmaxf(m0, mx0), mn1 = fmaxf(m1, mx1);
        float sc0 = ex2f(m0 - mn0), sc1 = ex2f(m1 - mn1);
        m0 = mn0; m1 = mn1;
        l0 *= sc0; l1 *= sc1;
        #pragma unroll
        for (int j = 0; j < 8; j++) {
            o[j][0] *= sc0; o[j][1] *= sc0;
            o[j][2] *= sc1; o[j][3] *= sc1;
        }
        #pragma unroll
        for (int j = 0; j < 8; j++) {
            float p0 = ex2f(s[j][0] - mn0);
            float p1 = ex2f(s[j][1] - mn0);
            float p2 = ex2f(s[j][2] - mn1);
            float p3 = ex2f(s[j][3] - mn1);
            s[j][0] = p0; s[j][1] = p1; s[j][2] = p2; s[j][3] = p3;
            l0 += p0 + p1;
            l1 += p2 + p3;
        }

        #pragma unroll
        for (int kc = 0; kc < 4; kc++) {
            uint32_t pf[4];
            #pragma unroll
            for (int t2 = 0; t2 < 2; t2++) {
                int j = 2 * kc + t2;
                pf[t2*2 + 0] = cvt_h2(s[j][0], s[j][1]);
                pf[t2*2 + 1] = cvt_h2(s[j][2], s[j][3]);
            }
            #pragma unroll
            for (int nb = 0; nb < 4; nb++) {
                uint32_t vf4[4];
                ldsm_x4_t(vf4, va + kc * (16 * KSTR * 2) + nb * 32);
                mma16816h(o[2*nb],   pf, vf4[0], vf4[1]);
                mma16816h(o[2*nb+1], pf, vf4[2], vf4[3]);
            }
        }
    }

    l0 += __shfl_xor_sync(0xffffffffu, l0, 1);
    l0 += __shfl_xor_sync(0xffffffffu, l0, 2);
    l1 += __shfl_xor_sync(0xffffffffu, l1, 1);
    l1 += __shfl_xor_sync(0xffffffffu, l1, 2);
    float inv0 = 1.f / l0, inv1 = 1.f / l1;

    size_t tok0 = (size_t)b * SS + row_a0;
    size_t o0 = tok0 * DD + h * HDD + (lane & 3) * 2;
    size_t o1 = o0 + (size_t)8 * DD;
    #pragma unroll
    for (int j = 0; j < 8; j++) {
        *reinterpret_cast<uint32_t*>(&yf[o0 + j * 8]) =
            cvt_h2(o[j][0] * inv0, o[j][1] * inv0);
        *reinterpret_cast<uint32_t*>(&yf[o1 + j * 8]) =
            cvt_h2(o[j][2] * inv1, o[j][3] * inv1);
    }
}

// ---------------------------------------------------------------------------
// Launch
// ---------------------------------------------------------------------------
extern "C" void kernel_launch(void* const* d_in, const int* in_sizes, int n_in,
                              void* d_out, int out_size)
{
    const float* x      = (const float*)d_in[0];
    const float* W_attn = (const float*)d_in[1];
    const float* b_attn = (const float*)d_in[2];
    const float* W_proj = (const float*)d_in[3];
    const float* b_proj = (const float*)d_in[4];
    float* out = (float*)d_out;

    static __half *xf = nullptr, *yf;
    static __half *wt, *wpt;
    static __half *qf, *kf, *vf;
    static int gemm_grid = 0;
    if (!xf) {   // first (non-captured) correctness call
        cudaGetSymbolAddress((void**)&xf, g_xf);
        cudaGetSymbolAddress((void**)&yf, g_yf);
        cudaGetSymbolAddress((void**)&wt,  g_wt);
        cudaGetSymbolAddress((void**)&wpt, g_wpt);
        cudaGetSymbolAddress((void**)&qf, g_qf);
        cudaGetSymbolAddress((void**)&kf, g_kf);
        cudaGetSymbolAddress((void**)&vf, g_vf);
        cudaFuncSetAttribute(flash_attn_tc,
                             cudaFuncAttributeMaxDynamicSharedMemorySize,
                             FS_TOTAL);
        cudaFuncSetAttribute(tc_gemm_kernel<0>,
                             cudaFuncAttributeMaxDynamicSharedMemorySize,
                             GEMM_SMEM);
        cudaFuncSetAttribute(tc_gemm_kernel<1>,
                             cudaFuncAttributeMaxDynamicSharedMemorySize,
                             GEMM_SMEM);
        cudaDeviceProp prop;
        cudaGetDeviceProperties(&prop, 0);
        gemm_grid = prop.multiProcessorCount * 2;   // persistent: 2 CTAs/SM
    }

    // 0a) convert x -> fp16
    convert_f16_kernel<<<(MTOK * DD) / (256 * 4), 256>>>(x, xf);
    // 0b) transpose + fp16 convert weights
    {
        dim3 g1(3 * DD / 32, DD / 32);
        transpose_f16_kernel<<<g1, 256>>>(W_attn, wt, DD, 3 * DD);
        dim3 g2(DD / 32, DD / 32);
        transpose_f16_kernel<<<g2, 256>>>(W_proj, wpt, DD, DD);
    }

    // 1) QKV GEMM (persistent, fp16 1-pass) + fused epilogue -> qf,kf,vf
    tc_gemm_kernel<1><<<gemm_grid, 256, GEMM_SMEM>>>(
        xf, wt, b_attn, nullptr,
        qf, kf, vf, MTOK, 3 * DD, DD);

    // 2) all-fp16 tensor-core causal flash attention -> fp16 y
    {
        dim3 grid(SS / 128, HH, BB);
        flash_attn_tc<<<grid, 256, FS_TOTAL>>>(qf, kf, vf, yf);
    }

    // 3) output projection (persistent, fp16 1-pass) -> out
    tc_gemm_kernel<0><<<gemm_grid, 256, GEMM_SMEM>>>(
        yf, wpt, b_proj, out,
        nullptr, nullptr, nullptr,
        MTOK, DD, DD);
}

// round 16
// speedup vs baseline: 2.6061x; 1.1695x over previous
#include <cuda_runtime.h>
#include <cuda_bf16.h>
#include <cuda_fp16.h>
#include <cstdint>
#include <cstddef>

// Problem constants
#define BB  4
#define SS  2048
#define DD  1024
#define HH  16
#define HDD 64
#define MTOK (BB*SS)          // 8192 token rows

// q prescale: HD^-0.5 * log2(e)  (softmax done in exp2 domain)
#define QSC 0.18033688011112042f

// Scratch (device globals; no allocations allowed)
__device__ __align__(128) __half g_xf[(size_t)MTOK * DD];            // x fp16
__device__ __align__(128) __half g_yf[(size_t)MTOK * DD];            // attn out fp16
__device__ __align__(128) __half g_wt [(size_t)3 * DD * DD];         // W_attn^T fp16
__device__ __align__(128) __half g_wpt[(size_t)DD * DD];             // W_proj^T fp16
#define BHSZ ((size_t)BB * HH * SS * HDD)
__device__ __align__(128) __half g_qf[BHSZ];                          // Q fp16
__device__ __align__(128) __half g_kf[BHSZ];                          // K fp16
__device__ __align__(128) __half g_vf[BHSZ];                          // V fp16

// ---------------------------------------------------------------------------
// Warp-MMA + async-copy helpers
// ---------------------------------------------------------------------------
__device__ __forceinline__ uint32_t smem_u32(const void* p) {
    uint32_t a;
    asm("{ .reg .u64 t; cvta.to.shared.u64 t, %1; cvt.u32.u64 %0, t; }"
        : "=r"(a) : "l"(p));
    return a;
}
__device__ __forceinline__ void ldsm_x4(uint32_t* r, uint32_t addr) {
    asm volatile("ldmatrix.sync.aligned.m8n8.x4.shared.b16 {%0,%1,%2,%3}, [%4];"
                 : "=r"(r[0]), "=r"(r[1]), "=r"(r[2]), "=r"(r[3]) : "r"(addr));
}
__device__ __forceinline__ void ldsm_x4_t(uint32_t* r, uint32_t addr) {
    asm volatile("ldmatrix.sync.aligned.m8n8.x4.trans.shared.b16 {%0,%1,%2,%3}, [%4];"
                 : "=r"(r[0]), "=r"(r[1]), "=r"(r[2]), "=r"(r[3]) : "r"(addr));
}
// fp16 mma
__device__ __forceinline__ void mma16816h(float* d, const uint32_t* a,
                                          const uint32_t b0, const uint32_t b1) {
    asm volatile(
        "mma.sync.aligned.m16n8k16.row.col.f32.f16.f16.f32 "
        "{%0,%1,%2,%3}, {%4,%5,%6,%7}, {%8,%9}, {%0,%1,%2,%3};"
        : "+f"(d[0]), "+f"(d[1]), "+f"(d[2]), "+f"(d[3])
        : "r"(a[0]), "r"(a[1]), "r"(a[2]), "r"(a[3]), "r"(b0), "r"(b1));
}
__device__ __forceinline__ void cp_async16(uint32_t saddr, const void* g) {
    asm volatile("cp.async.cg.shared.global [%0], [%1], 16;"
                 :: "r"(saddr), "l"(g) : "memory");
}
#define CP_COMMIT() asm volatile("cp.async.commit_group;" ::: "memory")
#define CP_WAIT(n)  asm volatile("cp.async.wait_group %0;" :: "n"(n) : "memory")

// packed f32x2 -> f16x2 (lo = a, hi = b)
__device__ __forceinline__ uint32_t cvt_h2(float a, float b) {
    uint32_t r;
    asm("cvt.rn.f16x2.f32 %0, %1, %2;" : "=r"(r) : "f"(b), "f"(a));
    return r;
}
__device__ __forceinline__ float ex2f(float x) {
    float r;
    asm("ex2.approx.f32 %0, %1;" : "=f"(r) : "f"(x));
    return r;
}

#define TS32 40   // GEMM BK=32 row stride (elems): 80B rows, conflict-free ldsm
#define KSTR 72   // attention tile row stride (144B rows, conflict-free)

// ---------------------------------------------------------------------------
// Elementwise fp32 -> fp16 convert (for x)
// ---------------------------------------------------------------------------
__global__ __launch_bounds__(256)
void convert_f16_kernel(const float* __restrict__ in, __half* __restrict__ of)
{
    size_t i = ((size_t)blockIdx.x * 256 + threadIdx.x) * 4;
    float4 v = *reinterpret_cast<const float4*>(in + i);
    uint2 hv;
    hv.x = cvt_h2(v.x, v.y);
    hv.y = cvt_h2(v.z, v.w);
    *reinterpret_cast<uint2*>(of + i) = hv;
}

// ---------------------------------------------------------------------------
// Transpose + fp16 convert of weights:  W[K,N] fp32 -> T[N,K] fp16
// ---------------------------------------------------------------------------
__global__ __launch_bounds__(256)
void transpose_f16_kernel(const float* __restrict__ W,
                          __half* __restrict__ T,
                          int K, int N)
{
    __shared__ float tile[32][33];
    const int n0 = blockIdx.x * 32;
    const int k0 = blockIdx.y * 32;
    const int tx = threadIdx.x & 31;
    const int ty4 = (threadIdx.x >> 5) * 4;

    #pragma unroll
    for (int j = 0; j < 4; j++)
        tile[ty4 + j][tx] = W[(size_t)(k0 + ty4 + j) * N + n0 + tx];
    __syncthreads();
    #pragma unroll
    for (int j = 0; j < 4; j++) {
        float v = tile[tx][ty4 + j];
        T[(size_t)(n0 + ty4 + j) * K + k0 + tx] = __float2half_rn(v);
    }
}

// ---------------------------------------------------------------------------
// Persistent tensor-core GEMM, plain fp16 1-pass, BK=32:
// BM=128, BN=128, 256 threads (8 warps, 64x32 warp tiles), 2 CTA/SM.
// 4-stage continuous pipeline; pair barrier covers 64 K (64 MMAs/warp).
// MODE 0: fp32 C.  MODE 1 (QKV): q/k/v single fp16 per-head buffers.
// ---------------------------------------------------------------------------
#define A32_BYTES (128 * TS32 * 2)       // 10240 per array
#define S32_AF 0
#define S32_BF (1 * A32_BYTES)
#define S32_STG (2 * A32_BYTES)          // 20480 per stage
#define GEMM_SMEM (4 * S32_STG)          // 81920 (4 stages)

template <int MODE>
__global__ __launch_bounds__(256, 2)
void tc_gemm_kernel(const __half* __restrict__ Agf,
                    const __half* __restrict__ Bgf,
                    const float* __restrict__ bias,
                    float* __restrict__ C,
                    __half* __restrict__ oqf,
                    __half* __restrict__ okf,
                    __half* __restrict__ ovf,
                    int M, int N, int K)
{
    extern __shared__ __align__(16) char gsm[];
    const uint32_t sb = smem_u32(gsm);

    const int tid  = threadIdx.x;
    const int lane = tid & 31;
    const int wid  = tid >> 5;              // 0..7
    const int bid  = blockIdx.x;
    const int G    = gridDim.x;

    const int NX      = N >> 7;
    const int ntiles  = (M >> 7) * NX;
    const int nchunks = K >> 5;             // BK=32 (even)
    const int njobs   = (bid < ntiles) ? ((ntiles - bid + G - 1) / G) : 0;

    const int m_base = (wid >> 2) * 64;
    const int n_base = (wid & 3) * 32;

    const int a_r  = lane & 15;
    const int a_k  = (lane >> 4) * 8;
    const uint32_t af_rel = S32_AF + ((m_base + a_r) * TS32 + a_k) * 2;
    const int b_n  = (lane >> 4) * 8 + (lane & 7);
    const int b_k  = ((lane >> 3) & 1) * 8;
    const uint32_t bf_rel = S32_BF + ((n_base + b_n) * TS32 + b_k) * 2;

    // cp.async per-thread mapping: 2 x 16B per array per BK-32 chunk
    // idx = i*256+tid (i=0,1); r = idx>>2; k8 = (idx&3)*8
    uint32_t cp_sdo[2]; int cp_r[2], cp_k8[2];
    #pragma unroll
    for (int i = 0; i < 2; i++) {
        int idx = i * 256 + tid;
        cp_r[i]  = idx >> 2;
        cp_k8[i] = (idx & 3) << 3;
        cp_sdo[i] = (uint32_t)(cp_r[i] * TS32 + cp_k8[i]) * 2;
    }

    int lj = 0, lc = 0, ls = 0;
    uint32_t goA = 0, goB = 0;   // element offset of row 0, col 0 of chunk
    if (njobs > 0) {
        int t = bid;
        int lby = t / NX, lbx = t - lby * NX;
        goA = (uint32_t)(lby * 128) * (uint32_t)K;
        goB = (uint32_t)(lbx * 128) * (uint32_t)K;
    }

    auto advance_load = [&]() {
        ls = (ls + 1) & 3;
        if (++lc == nchunks) {
            lc = 0; lj++;
            if (lj < njobs) {
                int t = bid + lj * G;
                int lby = t / NX, lbx = t - lby * NX;
                goA = (uint32_t)(lby * 128) * (uint32_t)K;
                goB = (uint32_t)(lbx * 128) * (uint32_t)K;
            }
        } else {
            goA += 32; goB += 32;
        }
    };

    auto issue_chunk = [&]() {
        if (lj < njobs) {
            const uint32_t so = sb + (uint32_t)ls * S32_STG;
            #pragma unroll
            for (int i = 0; i < 2; i++) {
                uint32_t ga = goA + (uint32_t)cp_r[i] * (uint32_t)K + cp_k8[i];
                uint32_t gb = goB + (uint32_t)cp_r[i] * (uint32_t)K + cp_k8[i];
                cp_async16(so + S32_AF + cp_sdo[i], Agf + ga);
                cp_async16(so + S32_BF + cp_sdo[i], Bgf + gb);
            }
        }
        CP_COMMIT();
        advance_load();
    };

    // prologue: chunks 0,1
    issue_chunk();
    issue_chunk();

    int cs = 0;
    for (int j = 0; j < njobs; j++) {
        const int tile_id = bid + j * G;
        const int by = tile_id / NX;
        const int bx = tile_id - by * NX;
        const int brow = by * 128;
        const int bcol = bx * 128;

        float acc[4][4][4];
        #pragma unroll
        for (int i = 0; i < 4; i++)
            #pragma unroll
            for (int jj = 0; jj < 4; jj++)
                #pragma unroll
                for (int r = 0; r < 4; r++) acc[i][jj][r] = 0.f;

        for (int cpair = 0; cpair < nchunks; cpair += 2) {
            CP_WAIT(0);
            __syncthreads();      // both chunks of this pair resident

            #pragma unroll
            for (int u = 0; u < 2; u++) {
                const uint32_t so = sb + (uint32_t)cs * S32_STG;

                #pragma unroll
                for (int ks = 0; ks < 32; ks += 16) {
                    uint32_t af[4][4], bf[2][4];
                    #pragma unroll
                    for (int mt = 0; mt < 4; mt++)
                        ldsm_x4(af[mt], so + af_rel + (mt * 16 * TS32 + ks) * 2);
                    #pragma unroll
                    for (int p = 0; p < 2; p++)
                        ldsm_x4(bf[p], so + bf_rel + (p * 16 * TS32 + ks) * 2);
                    #pragma unroll
                    for (int mt = 0; mt < 4; mt++)
                        #pragma unroll
                        for (int nt = 0; nt < 4; nt++) {
                            const int p = nt >> 1, hx = (nt & 1) * 2;
                            mma16816h(acc[mt][nt], af[mt], bf[p][hx], bf[p][hx + 1]);
                        }
                    // interleave next-chunk copies between the two k-steps
                    if (ks == 0) issue_chunk();
                }
                cs = (cs + 1) & 3;
            }
        }

        // --- epilogue ---
        #pragma unroll
        for (int nt = 0; nt < 4; nt++) {
            const int ncol = bcol + n_base + nt * 8 + (lane & 3) * 2;
            float2 bv = *reinterpret_cast<const float2*>(&bias[ncol]);
            if (MODE == 0) {
                #pragma unroll
                for (int mt = 0; mt < 4; mt++) {
                    int row0 = brow + m_base + mt * 16 + (lane >> 2);
                    float2 v0, v1;
                    v0.x = acc[mt][nt][0] + bv.x;  v0.y = acc[mt][nt][1] + bv.y;
                    v1.x = acc[mt][nt][2] + bv.x;  v1.y = acc[mt][nt][3] + bv.y;
                    *reinterpret_cast<float2*>(&C[(size_t)row0 * N + ncol]) = v0;
                    *reinterpret_cast<float2*>(&C[(size_t)(row0 + 8) * N + ncol]) = v1;
                }
            } else {
                const int region = ncol >> 10;          // 0:q 1:k 2:v
                const int hh = (ncol >> 6) & (HH - 1);
                const int dd = ncol & (HDD - 1);
                const float sc = (region == 0) ? QSC : 1.f;
                __half* dst = (region == 0) ? oqf : (region == 1) ? okf : ovf;
                const size_t colbase = (size_t)hh * (SS * HDD) + dd;
                #pragma unroll
                for (int mt = 0; mt < 4; mt++) {
                    int row0 = brow + m_base + mt * 16 + (lane >> 2);
                    #pragma unroll
                    for (int rr = 0; rr < 2; rr++) {
                        int row = row0 + rr * 8;
                        float v0 = (acc[mt][nt][rr * 2 + 0] + bv.x) * sc;
                        float v1 = (acc[mt][nt][rr * 2 + 1] + bv.y) * sc;
                        int bb = row >> 11, ss = row & (SS - 1);
                        size_t off = (size_t)bb * HH * SS * HDD + colbase + (size_t)ss * HDD;
                        *reinterpret_cast<uint32_t*>(&dst[off]) = cvt_h2(v0, v1);
                    }
                }
            }
        }
    }
}

// ---------------------------------------------------------------------------
// Tensor-core causal flash attention, all-fp16 (as R14):
// S = Qf x Kf^T (1 pass);  O += Pf x Vf (1 pass).
// BM=128 (8 warps, 256 threads), cp.async 2-stage K/V ring (64 keys/tile).
// ---------------------------------------------------------------------------
#define FS_KF   0
#define FS_VF   9216
#define FS_STG  18432
#define FS_TOTAL (2 * FS_STG)          // 36864

__global__ __launch_bounds__(256, 2)
void flash_attn_tc(const __half* __restrict__ Qf,
                   const __half* __restrict__ Kf,
                   const __half* __restrict__ Vf,
                   __half* __restrict__ yf)
{
    extern __shared__ __align__(16) char sm[];
    const uint32_t sbase = smem_u32(sm);

    const int tid  = threadIdx.x;
    const int lane = tid & 31;
    const int w    = tid >> 5;
    const int qtile = (gridDim.x - 1) - blockIdx.x;
    const int h = blockIdx.y;
    const int b = blockIdx.z;
    const size_t base = ((size_t)(b * HH + h)) * SS * HDD;

    // ---- stage Q (fp16) through ring stage 0, build frags ----
    {
        const int s0 = qtile * 128;
        #pragma unroll
        for (int i = 0; i < 4; i++) {
            int idx = i * 256 + tid;
            int r  = idx >> 3;
            int c8 = (idx & 7) * 8;
            *reinterpret_cast<uint4*>(sm + (uint32_t)(r * KSTR + c8) * 2) =
                *reinterpret_cast<const uint4*>(&Qf[base + (size_t)(s0 + r) * HDD + c8]);
        }
    }
    __syncthreads();

    uint32_t qf[4][4];
    {
        const uint32_t qa = sbase +
            ((w * 16 + (lane & 15)) * KSTR + (lane >> 4) * 8) * 2;
        #pragma unroll
        for (int kc = 0; kc < 4; kc++) ldsm_x4(qf[kc], qa + kc * 32);
    }
    __syncthreads();   // Q staging dead; ring reusable

    const uint32_t ka_rel = (((lane >> 4) * 8 + (lane & 7)) * KSTR +
                             ((lane >> 3) & 1) * 8) * 2;
    const uint32_t va_rel = ((((lane >> 3) & 1) * 8 + (lane & 7)) * KSTR +
                             ((lane >> 4) & 1) * 8) * 2;

    int cg_r[2], cg_c8[2]; uint32_t cg_so[2];
    #pragma unroll
    for (int ii = 0; ii < 2; ii++) {
        int j  = ii * 256 + tid;
        cg_r[ii]  = j >> 3;
        cg_c8[ii] = (j & 7) * 8;
        cg_so[ii] = (uint32_t)(cg_r[ii] * KSTR + cg_c8[ii]) * 2;
    }

    float o[8][4];
    #pragma unroll
    for (int j = 0; j < 8; j++)
        #pragma unroll
        for (int r = 0; r < 4; r++) o[j][r] = 0.f;
    float m0 = -1e30f, m1 = -1e30f, l0 = 0.f, l1 = 0.f;

    const int row_a0 = qtile * 128 + w * 16 + (lane >> 2);
    const int num_kv = 2 * qtile + 2;

    {
        const uint32_t sa = sbase;
        #pragma unroll
        for (int ii = 0; ii < 2; ii++) {
            size_t g = base + (size_t)cg_r[ii] * HDD + cg_c8[ii];
            cp_async16(sa + FS_KF + cg_so[ii], Kf + g);
            cp_async16(sa + FS_VF + cg_so[ii], Vf + g);
        }
        CP_COMMIT();
    }

    for (int t = 0; t < num_kv; t++) {
        CP_WAIT(0);
        __syncthreads();

        const bool pre = (t + 1 < num_kv);
        const uint32_t sa_n = sbase + (uint32_t)((t + 1) & 1) * FS_STG;
        const size_t gb_n = base + (size_t)(t + 1) * 64 * HDD;

        const uint32_t sa = sbase + (uint32_t)(t & 1) * FS_STG;
        const uint32_t ka = sa + FS_KF + ka_rel;
        const uint32_t va = sa + FS_VF + va_rel;

        float s[8][4];
        #pragma unroll
        for (int j = 0; j < 8; j++)
            #pragma unroll
            for (int r = 0; r < 4; r++) s[j][r] = 0.f;

        #pragma unroll
        for (int kc = 0; kc < 4; kc++) {
            #pragma unroll
            for (int np = 0; np < 4; np++) {
                uint32_t kf4[4];
                ldsm_x4(kf4, ka + np * (16 * KSTR * 2) + kc * 32);
                mma16816h(s[2*np],   qf[kc], kf4[0], kf4[1]);
                mma16816h(s[2*np+1], qf[kc], kf4[2], kf4[3]);
            }
            if (kc == 0 && pre) {
                #pragma unroll
                for (int ii = 0; ii < 2; ii++) {
                    size_t g = gb_n + (size_t)cg_r[ii] * HDD + cg_c8[ii];
                    cp_async16(sa_n + FS_KF + cg_so[ii], Kf + g);
                }
            }
            if (kc == 2 && pre) {
                #pragma unroll
                for (int ii = 0; ii < 2; ii++) {
                    size_t g = gb_n + (size_t)cg_r[ii] * HDD + cg_c8[ii];
                    cp_async16(sa_n + FS_VF + cg_so[ii], Vf + g);
                }
            }
        }
        CP_COMMIT();

        if (t >= 2 * qtile) {
            #pragma unroll
            for (int j = 0; j < 8; j++) {
                int col = t * 64 + j * 8 + (lane & 3) * 2;
                #pragma unroll
                for (int r = 0; r < 4; r++) {
                    int cc = col + (r & 1);
                    int rw = row_a0 + ((r >= 2) ? 8 : 0);
                    if (cc > rw) s[j][r] = -1e30f;
                }
            }
        }

        float mx0 = -1e30f, mx1 = -1e30f;
        #pragma unroll
        for (int j = 0; j < 8; j++) {
            mx0 = fmaxf(mx0, fmaxf(s[j][0], s[j][1]));
            mx1 = fmaxf(mx1, fmaxf(s[j][2], s[j][3]));
        }
        mx0 = fmaxf(mx0, __shfl_xor_sync(0xffffffffu, mx0, 1));
        mx0 = fmaxf(mx0, __shfl_xor_sync(0xffffffffu, mx0, 2));
        mx1 = fmaxf(mx1, __shfl_xor_sync(0xffffffffu, mx1, 1));
        mx1 = fmaxf(mx1, __shfl_xor_sync(0xffffffffu, mx1, 2));
        float mn0 = fmaxf(m0, mx0), mn1 = fmaxf(m1, mx1);
        float sc0 = ex2f(m0 - mn0), sc1 = ex2f(m1 - mn1);
        m0 = mn0; m1 = mn1;
        l0 *= sc0; l1 *= sc1;
        #pragma unroll
        for (int j = 0; j < 8; j++) {
            o[j][0] *= sc0; o[j][1] *= sc0;
            o[j][2] *= sc1; o[j][3] *= sc1;
        }
        #pragma unroll
        for (int j = 0; j < 8; j++) {
            float p0 = ex2f(s[j][0] - mn0);
            float p1 = ex2f(s[j][1] - mn0);
            float p2 = ex2f(s[j][2] - mn1);
            float p3 = ex2f(s[j][3] - mn1);
            s[j][0] = p0; s[j][1] = p1; s[j][2] = p2; s[j][3] = p3;
            l0 += p0 + p1;
            l1 += p2 + p3;
        }

        #pragma unroll
        for (int kc = 0; kc < 4; kc++) {
            uint32_t pf[4];
            #pragma unroll
            for (int t2 = 0; t2 < 2; t2++) {
                int j = 2 * kc + t2;
                pf[t2*2 + 0] = cvt_h2(s[j][0], s[j][1]);
                pf[t2*2 + 1] = cvt_h2(s[j][2], s[j][3]);
            }
            #pragma unroll
            for (int nb = 0; nb < 4; nb++) {
                uint32_t vf4[4];
                ldsm_x4_t(vf4, va + kc * (16 * KSTR * 2) + nb * 32);
                mma16816h(o[2*nb],   pf, vf4[0], vf4[1]);
                mma16816h(o[2*nb+1], pf, vf4[2], vf4[3]);
            }
        }
    }

    l0 += __shfl_xor_sync(0xffffffffu, l0, 1);
    l0 += __shfl_xor_sync(0xffffffffu, l0, 2);
    l1 += __shfl_xor_sync(0xffffffffu, l1, 1);
    l1 += __shfl_xor_sync(0xffffffffu, l1, 2);
    float inv0 = 1.f / l0, inv1 = 1.f / l1;

    size_t tok0 = (size_t)b * SS + row_a0;
    size_t o0 = tok0 * DD + h * HDD + (lane & 3) * 2;
    size_t o1 = o0 + (size_t)8 * DD;
    #pragma unroll
    for (int j = 0; j < 8; j++) {
        *reinterpret_cast<uint32_t*>(&yf[o0 + j * 8]) =
            cvt_h2(o[j][0] * inv0, o[j][1] * inv0);
        *reinterpret_cast<uint32_t*>(&yf[o1 + j * 8]) =
            cvt_h2(o[j][2] * inv1, o[j][3] * inv1);
    }
}

// ---------------------------------------------------------------------------
// Launch
// ---------------------------------------------------------------------------
extern "C" void kernel_launch(void* const* d_in, const int* in_sizes, int n_in,
                              void* d_out, int out_size)
{
    const float* x      = (const float*)d_in[0];
    const float* W_attn = (const float*)d_in[1];
    const float* b_attn = (const float*)d_in[2];
    const float* W_proj = (const float*)d_in[3];
    const float* b_proj = (const float*)d_in[4];
    float* out = (float*)d_out;

    static __half *xf = nullptr, *yf;
    static __half *wt, *wpt;
    static __half *qf, *kf, *vf;
    static int gemm_grid = 0;
    if (!xf) {   // first (non-captured) correctness call
        cudaGetSymbolAddress((void**)&xf, g_xf);
        cudaGetSymbolAddress((void**)&yf, g_yf);
        cudaGetSymbolAddress((void**)&wt,  g_wt);
        cudaGetSymbolAddress((void**)&wpt, g_wpt);
        cudaGetSymbolAddress((void**)&qf, g_qf);
        cudaGetSymbolAddress((void**)&kf, g_kf);
        cudaGetSymbolAddress((void**)&vf, g_vf);
        cudaFuncSetAttribute(flash_attn_tc,
                             cudaFuncAttributeMaxDynamicSharedMemorySize,
                             FS_TOTAL);
        cudaFuncSetAttribute(tc_gemm_kernel<0>,
                             cudaFuncAttributeMaxDynamicSharedMemorySize,
                             GEMM_SMEM);
        cudaFuncSetAttribute(tc_gemm_kernel<1>,
                             cudaFuncAttributeMaxDynamicSharedMemorySize,
                             GEMM_SMEM);
        cudaDeviceProp prop;
        cudaGetDeviceProperties(&prop, 0);
        gemm_grid = prop.multiProcessorCount * 2;   // persistent: 2 CTAs/SM
    }

    // 0a) convert x -> fp16
    convert_f16_kernel<<<(MTOK * DD) / (256 * 4), 256>>>(x, xf);
    // 0b) transpose + fp16 convert weights
    {
        dim3 g1(3 * DD / 32, DD / 32);
        transpose_f16_kernel<<<g1, 256>>>(W_attn, wt, DD, 3 * DD);
        dim3 g2(DD / 32, DD / 32);
        transpose_f16_kernel<<<g2, 256>>>(W_proj, wpt, DD, DD);
    }

    // 1) QKV GEMM (persistent, fp16 1-pass, BK=32) + fused epilogue
    tc_gemm_kernel<1><<<gemm_grid, 256, GEMM_SMEM>>>(
        xf, wt, b_attn, nullptr,
        qf, kf, vf, MTOK, 3 * DD, DD);

    // 2) all-fp16 tensor-core causal flash attention -> fp16 y
    {
        dim3 grid(SS / 128, HH, BB);
        flash_attn_tc<<<grid, 256, FS_TOTAL>>>(qf, kf, vf, yf);
    }

    // 3) output projection (persistent, fp16 1-pass, BK=32) -> out
    tc_gemm_kernel<0><<<gemm_grid, 256, GEMM_SMEM>>>(
        yf, wpt, b_proj, out,
        nullptr, nullptr, nullptr,
        MTOK, DD, DD);
}